// round 9
// baseline (speedup 1.0000x reference)
#include <cuda_runtime.h>
#include <cuda_bf16.h>
#include <math.h>

#define Bsz 4
#define Lsz 1024
#define Dsz 512
#define Hsz 8
#define DKsz 64

// ---------------- scratch (static device globals; no allocation) ----------------
__device__ float g_Q[Bsz*Lsz*Dsz];      // tf32-prerounded
__device__ float g_K[Bsz*Lsz*Dsz];      // tf32-prerounded
__device__ float g_V[Bsz*Lsz*Dsz];      // tf32-prerounded
__device__ float g_QP[Bsz*Lsz*Dsz];     // tf32-prerounded
__device__ float g_KP[Bsz*Lsz*Dsz];     // tf32-prerounded
__device__ float g_W[6*Dsz*Dsz];        // tf32-prerounded weights (wq,wk,wv,mpq,mpk,dense)
__device__ __nv_bfloat16 g_EMb[Bsz*Lsz*Lsz];              // exp(1-m), bf16
__device__ float g_G[Bsz*Lsz];
__device__ __nv_bfloat16 g_Sb[(size_t)Bsz*Hsz*Lsz*Lsz];   // exp(scores), bf16 (67MB)
__device__ float g_Z[Bsz*Hsz*Lsz];
__device__ float g_CTX[Bsz*Lsz*Dsz];    // tf32-prerounded (feeds dense NOCVT)

// ---------------- helpers ----------------
__device__ __forceinline__ unsigned f2tf(float f) {
    unsigned u;
    asm("cvt.rna.tf32.f32 %0, %1;" : "=r"(u) : "f"(f));
    return u;
}
__device__ __forceinline__ float tf32r(float f) { return __uint_as_float(f2tf(f)); }

__device__ __forceinline__ void mma_tf32(float c[4], const unsigned a[4], const unsigned b[2]) {
    asm volatile(
        "mma.sync.aligned.m16n8k8.row.col.f32.tf32.tf32.f32 "
        "{%0,%1,%2,%3}, {%4,%5,%6,%7}, {%8,%9}, {%0,%1,%2,%3};"
        : "+f"(c[0]), "+f"(c[1]), "+f"(c[2]), "+f"(c[3])
        : "r"(a[0]), "r"(a[1]), "r"(a[2]), "r"(a[3]), "r"(b[0]), "r"(b[1]));
}

__device__ __forceinline__ void cp_async16(void* smem, const void* gmem) {
    unsigned saddr = (unsigned)__cvta_generic_to_shared(smem);
    asm volatile("cp.async.cg.shared.global [%0], [%1], 16;" :: "r"(saddr), "l"(gmem));
}
__device__ __forceinline__ void cp_commit() { asm volatile("cp.async.commit_group;"); }
template<int N>
__device__ __forceinline__ void cp_wait() { asm volatile("cp.async.wait_group %0;" :: "n"(N)); }

// ---------------- tf32 GEMM core, 4-stage pipeline, prefetch-before-sync ----------------
template<int BM, int BN, bool BT, int MT, int NT, bool ACVT, bool BCVT>
__device__ __forceinline__ void gemm_core(
    const float* __restrict__ A, int lda,
    const float* __restrict__ B, int ldb,
    int K, float (&acc)[MT][NT][4])
{
    constexpr int BK = 16;
    constexpr int APITCH = BK + 4;
    constexpr int BPITCH = BT ? (BK + 4) : (BN + 8);
    constexpr int BROWS  = BT ? BN : BK;

    extern __shared__ float dynsm[];
    float* As = dynsm;
    float* Bs = dynsm + 4 * BM * APITCH;

    const int tid = threadIdx.x;
    const int lane = tid & 31;
    const int wid = tid >> 5;
    const int wm0 = (wid & 3) * (BM / 4);
    const int wn0 = (wid >> 2) * (BN / 2);

    constexpr int ALD = (BM * BK / 4) / 256;
    constexpr int BLD = (BT ? (BN * BK / 4) : (BK * BN / 4)) / 256;

    auto prefetch = [&](int k0, int s) {
        float* Asl = As + s * BM * APITCH;
        float* Bsl = Bs + s * BROWS * BPITCH;
        #pragma unroll
        for (int i = 0; i < ALD; i++) {
            int idx = tid + i * 256;
            int row = idx >> 2, kq = idx & 3;
            cp_async16(&Asl[row * APITCH + kq * 4], A + (size_t)row * lda + k0 + kq * 4);
        }
        #pragma unroll
        for (int i = 0; i < BLD; i++) {
            int idx = tid + i * 256;
            if constexpr (BT) {
                int row = idx >> 2, kq = idx & 3;
                cp_async16(&Bsl[row * BPITCH + kq * 4], B + (size_t)row * ldb + k0 + kq * 4);
            } else {
                int k = idx / (BN / 4), nq = idx % (BN / 4);
                cp_async16(&Bsl[k * BPITCH + nq * 4], B + (size_t)(k0 + k) * ldb + nq * 4);
            }
        }
        cp_commit();
    };

    const int nIter = K / BK;
    prefetch(0, 0);
    if (nIter > 1) prefetch(BK, 1);

    for (int it = 0; it < nIter; it++) {
        if (it + 2 < nIter) { prefetch((it + 2) * BK, (it + 2) & 3); cp_wait<2>(); }
        else if (it + 1 < nIter) { cp_wait<1>(); }
        else { cp_wait<0>(); }
        __syncthreads();

        const int cur = it & 3;
        const float* Asl = As + cur * BM * APITCH;
        const float* Bsl = Bs + cur * BROWS * BPITCH;
        const unsigned* Aslu = (const unsigned*)Asl;
        const unsigned* Bslu = (const unsigned*)Bsl;

        #pragma unroll
        for (int ks = 0; ks < 2; ks++) {
            unsigned af[MT][4];
            unsigned bf[NT][2];
            const int kk = ks * 8 + (lane & 3);
            #pragma unroll
            for (int mt = 0; mt < MT; mt++) {
                int row = wm0 + mt * 16 + (lane >> 2);
                if constexpr (ACVT) {
                    af[mt][0] = f2tf(Asl[row * APITCH + kk]);
                    af[mt][1] = f2tf(Asl[(row + 8) * APITCH + kk]);
                    af[mt][2] = f2tf(Asl[row * APITCH + kk + 4]);
                    af[mt][3] = f2tf(Asl[(row + 8) * APITCH + kk + 4]);
                } else {
                    af[mt][0] = Aslu[row * APITCH + kk];
                    af[mt][1] = Aslu[(row + 8) * APITCH + kk];
                    af[mt][2] = Aslu[row * APITCH + kk + 4];
                    af[mt][3] = Aslu[(row + 8) * APITCH + kk + 4];
                }
            }
            #pragma unroll
            for (int nt = 0; nt < NT; nt++) {
                int n = wn0 + nt * 8 + (lane >> 2);
                if constexpr (BT) {
                    if constexpr (BCVT) {
                        bf[nt][0] = f2tf(Bsl[n * BPITCH + kk]);
                        bf[nt][1] = f2tf(Bsl[n * BPITCH + kk + 4]);
                    } else {
                        bf[nt][0] = Bslu[n * BPITCH + kk];
                        bf[nt][1] = Bslu[n * BPITCH + kk + 4];
                    }
                } else {
                    if constexpr (BCVT) {
                        bf[nt][0] = f2tf(Bsl[kk * BPITCH + n]);
                        bf[nt][1] = f2tf(Bsl[(kk + 4) * BPITCH + n]);
                    } else {
                        bf[nt][0] = Bslu[kk * BPITCH + n];
                        bf[nt][1] = Bslu[(kk + 4) * BPITCH + n];
                    }
                }
            }
            #pragma unroll
            for (int mt = 0; mt < MT; mt++)
                #pragma unroll
                for (int nt = 0; nt < NT; nt++)
                    mma_tf32(acc[mt][nt], af[mt], bf[nt]);
        }
    }
}

// smem byte sizes (4-stage)
#define PROJ_SMEM  ((4*128*20 + 4*16*136) * 4)   // 75776
#define NTG_SMEM   ((4*128*20 * 2) * 4)          // 81920
#define CTX_S_BYTES   (4 * 128 * 24 * 2)         // 24576 (bf16)
#define CTX_E_BYTES   (4 * 128 * 24 * 2)         // 24576 (bf16)
#define CTX_V_BYTES   (4 * 16 * 72 * 4)          // 18432 (fp32)
#define CTXF_SMEM  (CTX_S_BYTES + CTX_E_BYTES + CTX_V_BYTES)  // 67584

// ---------------- weight preround: g_W[z] = tf32(src[z]) ----------------
struct WSrc { const float* p[6]; };

__global__ void preround_kernel(WSrc ws)
{
    const int z = blockIdx.y;
    const float4* src = (const float4*)ws.p[z];
    float4* dst = (float4*)(g_W + z * Dsz * Dsz);
    int idx = blockIdx.x * 256 + threadIdx.x;   // 65536 float4 per matrix
    float4 v = src[idx];
    dst[idx] = make_float4(tf32r(v.x), tf32r(v.y), tf32r(v.z), tf32r(v.w));
}

// ---------------- batched projections / dense ----------------
struct ProjArgs {
    const float* A[5];
    const float* W[5];
    const float* bias[5];
    float* C[5];
};

template<bool ACVT>
__global__ void __launch_bounds__(256, 2) proj_gemm_kernel(ProjArgs args, int N, int K, int roundOut)
{
    const int z = blockIdx.z;
    float acc[2][8][4] = {};
    const float* Ab = args.A[z] + (size_t)blockIdx.y * 128 * K;
    const float* Bb = args.W[z] + blockIdx.x * 128;
    gemm_core<128, 128, false, 2, 8, ACVT, false>(Ab, K, Bb, N, K, acc);

    const float* bias = args.bias[z];
    float* C = args.C[z];
    int lane = threadIdx.x & 31, wid = threadIdx.x >> 5;
    int rowBase = blockIdx.y * 128 + (wid & 3) * 32 + (lane >> 2);
    int colBase = blockIdx.x * 128 + (wid >> 2) * 64 + 2 * (lane & 3);
    #pragma unroll
    for (int mt = 0; mt < 2; mt++)
        #pragma unroll
        for (int nt = 0; nt < 8; nt++) {
            int row = rowBase + mt * 16;
            int col = colBase + nt * 8;
            float b0 = bias[col], b1 = bias[col + 1];
            float v0 = acc[mt][nt][0] + b0, v1 = acc[mt][nt][1] + b1;
            float v2 = acc[mt][nt][2] + b0, v3 = acc[mt][nt][3] + b1;
            if (roundOut) {
                v0 = tf32r(v0); v1 = tf32r(v1); v2 = tf32r(v2); v3 = tf32r(v3);
            }
            *(float2*)&C[(size_t)row * N + col]       = make_float2(v0, v1);
            *(float2*)&C[(size_t)(row + 8) * N + col] = make_float2(v2, v3);
        }
}

// ---------------- merged m + score GEMM launch (all operands tf32-prerounded) ----------
__global__ void __launch_bounds__(256, 2) ms_gemm_kernel(float* __restrict__ m_out)
{
    const int zz = blockIdx.z;
    int lane = threadIdx.x & 31, wid = threadIdx.x >> 5;
    int fcol = lane & 3;

    if (zz < Bsz) {
        const float SCALE = 0.04419417382415922f; // 1/sqrt(512)
        const int zb = zz;
        float acc[2][8][4] = {};
        const float* Ab = g_QP + (size_t)zb * Lsz * Dsz + (size_t)blockIdx.y * 128 * Dsz;
        const float* Bb = g_KP + (size_t)zb * Lsz * Dsz + (size_t)blockIdx.x * 128 * Dsz;
        gemm_core<128, 128, true, 2, 8, false, false>(Ab, Dsz, Bb, Dsz, Dsz, acc);

        float* Mo = m_out + (size_t)zb * Lsz * Lsz;
        __nv_bfloat16* Eo = g_EMb + (size_t)zb * Lsz * Lsz;
        int rowBase = blockIdx.y * 128 + (wid & 3) * 32 + (lane >> 2);
        int colBase = blockIdx.x * 128 + (wid >> 2) * 64 + 2 * fcol;
        #pragma unroll
        for (int mt = 0; mt < 2; mt++)
            #pragma unroll
            for (int nt = 0; nt < 8; nt++) {
                int row = rowBase + mt * 16;
                int col = colBase + nt * 8;
                #pragma unroll
                for (int h = 0; h < 2; h++) {
                    int r = row + h * 8;
                    float s0 = 1.0f / (1.0f + __expf(-acc[mt][nt][2*h] * SCALE));
                    float s1 = 1.0f / (1.0f + __expf(-acc[mt][nt][2*h+1] * SCALE));
                    *(float2*)&Mo[(size_t)r * Lsz + col] = make_float2(s0, s1);
                    *(__nv_bfloat162*)&Eo[(size_t)r * Lsz + col] =
                        __float22bfloat162_rn(make_float2(__expf(1.0f - s0), __expf(1.0f - s1)));
                }
            }
    } else {
        const float SCALE = 0.125f;
        const int z = zz - Bsz;
        const int b = z >> 3, h = z & 7;
        float acc[2][8][4] = {};
        const float* Ab = g_Q + (size_t)b * Lsz * Dsz + h * DKsz + (size_t)blockIdx.y * 128 * Dsz;
        const float* Bb = g_K + (size_t)b * Lsz * Dsz + h * DKsz + (size_t)blockIdx.x * 128 * Dsz;
        gemm_core<128, 128, true, 2, 8, false, false>(Ab, Dsz, Bb, Dsz, DKsz, acc);

        __nv_bfloat16* Cp = g_Sb + (size_t)z * Lsz * Lsz;
        int rowBase = blockIdx.y * 128 + (wid & 3) * 32 + (lane >> 2);
        int colBase = blockIdx.x * 128 + (wid >> 2) * 64 + 2 * fcol;

        float rs[2][2] = {};
        #pragma unroll
        for (int mt = 0; mt < 2; mt++)
            #pragma unroll
            for (int nt = 0; nt < 8; nt++) {
                int row = rowBase + mt * 16;
                int col = colBase + nt * 8;
                float p0 = __expf(acc[mt][nt][0] * SCALE);
                float p1 = __expf(acc[mt][nt][1] * SCALE);
                float p2 = __expf(acc[mt][nt][2] * SCALE);
                float p3 = __expf(acc[mt][nt][3] * SCALE);
                *(__nv_bfloat162*)&Cp[(size_t)row * Lsz + col] =
                    __float22bfloat162_rn(make_float2(p0, p1));
                *(__nv_bfloat162*)&Cp[(size_t)(row + 8) * Lsz + col] =
                    __float22bfloat162_rn(make_float2(p2, p3));
                rs[mt][0] += p0 + p1;
                rs[mt][1] += p2 + p3;
            }

        #pragma unroll
        for (int mt = 0; mt < 2; mt++)
            #pragma unroll
            for (int hh = 0; hh < 2; hh++) {
                float v = rs[mt][hh];
                v += __shfl_xor_sync(0xffffffffu, v, 1);
                v += __shfl_xor_sync(0xffffffffu, v, 2);
                if (fcol == 0)
                    atomicAdd(&g_Z[(size_t)z * Lsz + rowBase + mt * 16 + hh * 8], v);
            }
    }
}

// ---------------- fused calibrate + ctx GEMM v3 ----------------
// Register transform with Taylor exp: x = p*invZ*w <= ~0.012, so
// exp(x) = 1 + x + x^2/2 (abs err <= x^3/6 ~ 3e-7). No MUFU in the mainloop.
__global__ void __launch_bounds__(256, 2) ctx_fused_kernel()
{
    extern __shared__ char smc[];
    __nv_bfloat16* Ss = (__nv_bfloat16*)smc;                    // 4 x 128 x 24
    __nv_bfloat16* Es = (__nv_bfloat16*)(smc + CTX_S_BYTES);    // 4 x 128 x 24
    unsigned* Vu = (unsigned*)(smc + CTX_S_BYTES + CTX_E_BYTES);// 4 x 16 x 72 (tf32 bits)
    float* Vf = (float*)Vu;

    const int tid = threadIdx.x;
    const int lane = tid & 31;
    const int wid = tid >> 5;
    const int z = blockIdx.z;
    const int b = z >> 3, h = z & 7;
    const int q0 = blockIdx.y * 128;

    const __nv_bfloat16* Sg = g_Sb + (size_t)z * Lsz * Lsz + (size_t)q0 * Lsz;
    const __nv_bfloat16* Eg = g_EMb + (size_t)b * Lsz * Lsz + (size_t)q0 * Lsz;
    const float* Vg = g_V + (size_t)b * Lsz * Dsz + h * DKsz;

    const int wm = wid * 16;
    const int frow = lane >> 2, fcol = lane & 3;
    const int r0 = wm + frow, r1 = r0 + 8;

    const float g0 = g_G[b * Lsz + q0 + r0];
    const float g1 = g_G[b * Lsz + q0 + r1];
    const float iz0 = 1.0f / g_Z[(size_t)z * Lsz + q0 + r0];
    const float iz1 = 1.0f / g_Z[(size_t)z * Lsz + q0 + r1];
    const float ga0 = g0 * iz0, gc0 = (1.0f - g0) * iz0;
    const float ga1 = g1 * iz1, gc1 = (1.0f - g1) * iz1;
    float z2a = 0.f, z2b = 0.f;

    auto prefetch = [&](int it, int s) {
        const int k0 = it * 16;
        __nv_bfloat16* Sl = Ss + s * 128 * 24;
        __nv_bfloat16* El = Es + s * 128 * 24;
        float* Vl = Vf + s * 16 * 72;
        {
            int row = tid >> 1, ch = tid & 1;
            cp_async16(&Sl[row * 24 + ch * 8], Sg + (size_t)row * Lsz + k0 + ch * 8);
            cp_async16(&El[row * 24 + ch * 8], Eg + (size_t)row * Lsz + k0 + ch * 8);
        }
        {
            int vr = tid >> 4, vc = tid & 15;
            cp_async16(&Vl[vr * 72 + vc * 4], Vg + (size_t)(k0 + vr) * Dsz + vc * 4);
        }
        cp_commit();
    };

    float acc[8][4] = {};
    const int nIter = Lsz / 16;   // 64
    prefetch(0, 0);
    prefetch(1, 1);

    for (int it = 0; it < nIter; it++) {
        if (it + 2 < nIter) { prefetch(it + 2, (it + 2) & 3); cp_wait<2>(); }
        else if (it + 1 < nIter) { cp_wait<1>(); }
        else { cp_wait<0>(); }
        __syncthreads();

        const int cur = it & 3;
        const __nv_bfloat16* Sl = Ss + cur * 128 * 24;
        const __nv_bfloat16* El = Es + cur * 128 * 24;
        const unsigned* Vl = Vu + cur * 16 * 72;

        #pragma unroll
        for (int ks = 0; ks < 2; ks++) {
            const int kk = ks * 8 + fcol;

            float p00 = __bfloat162float(Sl[r0 * 24 + kk]);
            float p10 = __bfloat162float(Sl[r1 * 24 + kk]);
            float p01 = __bfloat162float(Sl[r0 * 24 + kk + 4]);
            float p11 = __bfloat162float(Sl[r1 * 24 + kk + 4]);
            float e00 = __bfloat162float(El[r0 * 24 + kk]);
            float e10 = __bfloat162float(El[r1 * 24 + kk]);
            float e01 = __bfloat162float(El[r0 * 24 + kk + 4]);
            float e11 = __bfloat162float(El[r1 * 24 + kk + 4]);

            float x00 = p00 * fmaf(gc0, e00, ga0);
            float x10 = p10 * fmaf(gc1, e10, ga1);
            float x01 = p01 * fmaf(gc0, e01, ga0);
            float x11 = p11 * fmaf(gc1, e11, ga1);

            unsigned af[4];
            af[0] = f2tf(fmaf(x00, fmaf(x00, 0.5f, 1.0f), 1.0f));
            af[1] = f2tf(fmaf(x10, fmaf(x10, 0.5f, 1.0f), 1.0f));
            af[2] = f2tf(fmaf(x01, fmaf(x01, 0.5f, 1.0f), 1.0f));
            af[3] = f2tf(fmaf(x11, fmaf(x11, 0.5f, 1.0f), 1.0f));
            z2a += __uint_as_float(af[0]) + __uint_as_float(af[2]);
            z2b += __uint_as_float(af[1]) + __uint_as_float(af[3]);

            #pragma unroll
            for (int nt = 0; nt < 8; nt++) {
                const int n = nt * 8 + frow;
                unsigned bf[2] = { Vl[kk * 72 + n], Vl[(kk + 4) * 72 + n] };
                mma_tf32(acc[nt], af, bf);
            }
        }
    }

    z2a += __shfl_xor_sync(0xffffffffu, z2a, 1);
    z2a += __shfl_xor_sync(0xffffffffu, z2a, 2);
    z2b += __shfl_xor_sync(0xffffffffu, z2b, 1);
    z2b += __shfl_xor_sync(0xffffffffu, z2b, 2);
    const float iza = 1.0f / z2a;
    const float izb = 1.0f / z2b;

    // write CTX tf32-prerounded (dense consumes it NOCVT)
    float* Cp = g_CTX + (size_t)b * Lsz * Dsz + (size_t)q0 * Dsz + h * DKsz;
    #pragma unroll
    for (int nt = 0; nt < 8; nt++) {
        const int col = nt * 8 + 2 * fcol;
        *(float2*)&Cp[(size_t)r0 * Dsz + col] =
            make_float2(tf32r(acc[nt][0] * iza), tf32r(acc[nt][1] * iza));
        *(float2*)&Cp[(size_t)r1 * Dsz + col] =
            make_float2(tf32r(acc[nt][2] * izb), tf32r(acc[nt][3] * izb));
    }
}

// ---------------- gate (+ zero g_Z for the score atomics) ----------------
__global__ void gate_kernel(const float* __restrict__ query,
                            const float* __restrict__ gw,
                            const float* __restrict__ gb)
{
    int gidx = blockIdx.x * blockDim.x + threadIdx.x;
    if (gidx < Bsz * Hsz * Lsz) g_Z[gidx] = 0.f;

    int warp = gidx >> 5;
    int lane = threadIdx.x & 31;
    if (warp >= Bsz * Lsz) return;
    const float* row = query + (size_t)warp * Dsz;
    float s = 0.f;
    for (int d = lane; d < Dsz; d += 32) s += row[d] * gw[d];
    #pragma unroll
    for (int o = 16; o; o >>= 1) s += __shfl_xor_sync(0xffffffffu, s, o);
    if (lane == 0) g_G[warp] = 1.0f / (1.0f + __expf(-(s + gb[0])));
}

// ---------------- launch ----------------
extern "C" void kernel_launch(void* const* d_in, const int* in_sizes, int n_in,
                              void* d_out, int out_size)
{
    const float* query   = (const float*)d_in[0];
    const float* key     = (const float*)d_in[1];
    const float* value   = (const float*)d_in[2];
    const float* wq_w    = (const float*)d_in[3];
    const float* wq_b    = (const float*)d_in[4];
    const float* wk_w    = (const float*)d_in[5];
    const float* wk_b    = (const float*)d_in[6];
    const float* wv_w    = (const float*)d_in[7];
    const float* wv_b    = (const float*)d_in[8];
    const float* dense_w = (const float*)d_in[9];
    const float* dense_b = (const float*)d_in[10];
    const float* gate_w  = (const float*)d_in[11];
    const float* gate_b  = (const float*)d_in[12];
    const float* mp_wq_w = (const float*)d_in[13];
    const float* mp_wq_b = (const float*)d_in[14];
    const float* mp_wk_w = (const float*)d_in[15];
    const float* mp_wk_b = (const float*)d_in[16];

    float* out   = (float*)d_out;
    float* m_out = out + (size_t)Bsz * Lsz * Dsz;

    float *pQ, *pK, *pV, *pQP, *pKP, *pCTX, *pW;
    cudaGetSymbolAddress((void**)&pQ,   g_Q);
    cudaGetSymbolAddress((void**)&pK,   g_K);
    cudaGetSymbolAddress((void**)&pV,   g_V);
    cudaGetSymbolAddress((void**)&pQP,  g_QP);
    cudaGetSymbolAddress((void**)&pKP,  g_KP);
    cudaGetSymbolAddress((void**)&pCTX, g_CTX);
    cudaGetSymbolAddress((void**)&pW,   g_W);

    static int attr_set = 0;
    if (!attr_set) {
        cudaFuncSetAttribute(proj_gemm_kernel<true>,
                             cudaFuncAttributeMaxDynamicSharedMemorySize, PROJ_SMEM);
        cudaFuncSetAttribute(proj_gemm_kernel<false>,
                             cudaFuncAttributeMaxDynamicSharedMemorySize, PROJ_SMEM);
        cudaFuncSetAttribute(ms_gemm_kernel,
                             cudaFuncAttributeMaxDynamicSharedMemorySize, NTG_SMEM);
        cudaFuncSetAttribute(ctx_fused_kernel,
                             cudaFuncAttributeMaxDynamicSharedMemorySize, CTXF_SMEM);
        attr_set = 1;
    }

    dim3 t256(256);

    // preround all weight matrices to tf32 (B-side NOCVT everywhere)
    WSrc ws;
    ws.p[0] = wq_w; ws.p[1] = wk_w; ws.p[2] = wv_w;
    ws.p[3] = mp_wq_w; ws.p[4] = mp_wk_w; ws.p[5] = dense_w;
    preround_kernel<<<dim3(256, 6), t256>>>(ws);

    gate_kernel<<<(Bsz * Lsz * 32) / 256, t256>>>(query, gate_w, gate_b);

    ProjArgs pa;
    pa.A[0] = query; pa.W[0] = pW + 0*Dsz*Dsz; pa.bias[0] = wq_b;    pa.C[0] = pQ;
    pa.A[1] = key;   pa.W[1] = pW + 1*Dsz*Dsz; pa.bias[1] = wk_b;    pa.C[1] = pK;
    pa.A[2] = value; pa.W[2] = pW + 2*Dsz*Dsz; pa.bias[2] = wv_b;    pa.C[2] = pV;
    pa.A[3] = query; pa.W[3] = pW + 3*Dsz*Dsz; pa.bias[3] = mp_wq_b; pa.C[3] = pQP;
    pa.A[4] = key;   pa.W[4] = pW + 4*Dsz*Dsz; pa.bias[4] = mp_wk_b; pa.C[4] = pKP;
    proj_gemm_kernel<true><<<dim3(4, 32, 5), t256, PROJ_SMEM>>>(pa, Dsz, Dsz, 1);

    ms_gemm_kernel<<<dim3(8, 8, Bsz + Bsz * Hsz), t256, NTG_SMEM>>>(m_out);

    ctx_fused_kernel<<<dim3(1, 8, Bsz * Hsz), t256, CTXF_SMEM>>>();

    ProjArgs da;
    da.A[0] = pCTX; da.W[0] = pW + 5*Dsz*Dsz; da.bias[0] = dense_b; da.C[0] = out;
    proj_gemm_kernel<false><<<dim3(4, 32, 1), t256, PROJ_SMEM>>>(da, Dsz, Dsz, 0);
}

// round 10
// speedup vs baseline: 1.0241x; 1.0241x over previous
#include <cuda_runtime.h>
#include <cuda_bf16.h>
#include <math.h>

#define Bsz 4
#define Lsz 1024
#define Dsz 512
#define Hsz 8
#define DKsz 64

// ---------------- scratch (static device globals; no allocation) ----------------
__device__ float g_Q[Bsz*Lsz*Dsz];      // tf32-prerounded
__device__ float g_K[Bsz*Lsz*Dsz];      // tf32-prerounded
__device__ float g_V[Bsz*Lsz*Dsz];      // tf32-prerounded
__device__ float g_QP[Bsz*Lsz*Dsz];     // tf32-prerounded
__device__ float g_KP[Bsz*Lsz*Dsz];     // tf32-prerounded
__device__ float g_W[6*Dsz*Dsz];        // tf32-prerounded weights
__device__ __nv_bfloat16 g_EMb[Bsz*Lsz*Lsz];              // exp(1-m), bf16
__device__ float g_G[Bsz*Lsz];
__device__ __nv_bfloat16 g_Sb[(size_t)Bsz*Hsz*Lsz*Lsz];   // exp(scores), bf16
__device__ float g_Z[Bsz*Hsz*Lsz];
__device__ float g_CTX[Bsz*Lsz*Dsz];    // tf32-prerounded

// ---------------- helpers ----------------
__device__ __forceinline__ unsigned f2tf(float f) {
    unsigned u;
    asm("cvt.rna.tf32.f32 %0, %1;" : "=r"(u) : "f"(f));
    return u;
}
__device__ __forceinline__ float tf32r(float f) { return __uint_as_float(f2tf(f)); }

__device__ __forceinline__ void mma_tf32(float c[4], const unsigned a[4], const unsigned b[2]) {
    asm volatile(
        "mma.sync.aligned.m16n8k8.row.col.f32.tf32.tf32.f32 "
        "{%0,%1,%2,%3}, {%4,%5,%6,%7}, {%8,%9}, {%0,%1,%2,%3};"
        : "+f"(c[0]), "+f"(c[1]), "+f"(c[2]), "+f"(c[3])
        : "r"(a[0]), "r"(a[1]), "r"(a[2]), "r"(a[3]), "r"(b[0]), "r"(b[1]));
}

__device__ __forceinline__ void cp_async16(void* smem, const void* gmem) {
    unsigned saddr = (unsigned)__cvta_generic_to_shared(smem);
    asm volatile("cp.async.cg.shared.global [%0], [%1], 16;" :: "r"(saddr), "l"(gmem));
}
__device__ __forceinline__ void cp_commit() { asm volatile("cp.async.commit_group;"); }
template<int N>
__device__ __forceinline__ void cp_wait() { asm volatile("cp.async.wait_group %0;" :: "n"(N)); }

// ---------------- tf32 GEMM core, 4-stage pipeline, prefetch-before-sync ----------------
template<int BM, int BN, bool BT, int MT, int NT, bool ACVT, bool BCVT>
__device__ __forceinline__ void gemm_core(
    const float* __restrict__ A, int lda,
    const float* __restrict__ B, int ldb,
    int K, float (&acc)[MT][NT][4])
{
    constexpr int BK = 16;
    constexpr int APITCH = BK + 4;
    constexpr int BPITCH = BT ? (BK + 4) : (BN + 8);
    constexpr int BROWS  = BT ? BN : BK;

    extern __shared__ float dynsm[];
    float* As = dynsm;
    float* Bs = dynsm + 4 * BM * APITCH;

    const int tid = threadIdx.x;
    const int lane = tid & 31;
    const int wid = tid >> 5;
    const int wm0 = (wid & 3) * (BM / 4);
    const int wn0 = (wid >> 2) * (BN / 2);

    constexpr int ALD = (BM * BK / 4) / 256;
    constexpr int BLD = (BT ? (BN * BK / 4) : (BK * BN / 4)) / 256;

    auto prefetch = [&](int k0, int s) {
        float* Asl = As + s * BM * APITCH;
        float* Bsl = Bs + s * BROWS * BPITCH;
        #pragma unroll
        for (int i = 0; i < ALD; i++) {
            int idx = tid + i * 256;
            int row = idx >> 2, kq = idx & 3;
            cp_async16(&Asl[row * APITCH + kq * 4], A + (size_t)row * lda + k0 + kq * 4);
        }
        #pragma unroll
        for (int i = 0; i < BLD; i++) {
            int idx = tid + i * 256;
            if constexpr (BT) {
                int row = idx >> 2, kq = idx & 3;
                cp_async16(&Bsl[row * BPITCH + kq * 4], B + (size_t)row * ldb + k0 + kq * 4);
            } else {
                int k = idx / (BN / 4), nq = idx % (BN / 4);
                cp_async16(&Bsl[k * BPITCH + nq * 4], B + (size_t)(k0 + k) * ldb + nq * 4);
            }
        }
        cp_commit();
    };

    const int nIter = K / BK;
    prefetch(0, 0);
    if (nIter > 1) prefetch(BK, 1);

    for (int it = 0; it < nIter; it++) {
        if (it + 2 < nIter) { prefetch((it + 2) * BK, (it + 2) & 3); cp_wait<2>(); }
        else if (it + 1 < nIter) { cp_wait<1>(); }
        else { cp_wait<0>(); }
        __syncthreads();

        const int cur = it & 3;
        const float* Asl = As + cur * BM * APITCH;
        const float* Bsl = Bs + cur * BROWS * BPITCH;
        const unsigned* Aslu = (const unsigned*)Asl;
        const unsigned* Bslu = (const unsigned*)Bsl;

        #pragma unroll
        for (int ks = 0; ks < 2; ks++) {
            unsigned af[MT][4];
            unsigned bf[NT][2];
            const int kk = ks * 8 + (lane & 3);
            #pragma unroll
            for (int mt = 0; mt < MT; mt++) {
                int row = wm0 + mt * 16 + (lane >> 2);
                if constexpr (ACVT) {
                    af[mt][0] = f2tf(Asl[row * APITCH + kk]);
                    af[mt][1] = f2tf(Asl[(row + 8) * APITCH + kk]);
                    af[mt][2] = f2tf(Asl[row * APITCH + kk + 4]);
                    af[mt][3] = f2tf(Asl[(row + 8) * APITCH + kk + 4]);
                } else {
                    af[mt][0] = Aslu[row * APITCH + kk];
                    af[mt][1] = Aslu[(row + 8) * APITCH + kk];
                    af[mt][2] = Aslu[row * APITCH + kk + 4];
                    af[mt][3] = Aslu[(row + 8) * APITCH + kk + 4];
                }
            }
            #pragma unroll
            for (int nt = 0; nt < NT; nt++) {
                int n = wn0 + nt * 8 + (lane >> 2);
                if constexpr (BT) {
                    if constexpr (BCVT) {
                        bf[nt][0] = f2tf(Bsl[n * BPITCH + kk]);
                        bf[nt][1] = f2tf(Bsl[n * BPITCH + kk + 4]);
                    } else {
                        bf[nt][0] = Bslu[n * BPITCH + kk];
                        bf[nt][1] = Bslu[n * BPITCH + kk + 4];
                    }
                } else {
                    if constexpr (BCVT) {
                        bf[nt][0] = f2tf(Bsl[kk * BPITCH + n]);
                        bf[nt][1] = f2tf(Bsl[(kk + 4) * BPITCH + n]);
                    } else {
                        bf[nt][0] = Bslu[kk * BPITCH + n];
                        bf[nt][1] = Bslu[(kk + 4) * BPITCH + n];
                    }
                }
            }
            #pragma unroll
            for (int mt = 0; mt < MT; mt++)
                #pragma unroll
                for (int nt = 0; nt < NT; nt++)
                    mma_tf32(acc[mt][nt], af[mt], bf[nt]);
        }
    }
}

// smem byte sizes
#define PROJ_SMEM  ((4*128*20 + 4*16*136) * 4)   // 75776
#define NTG_SMEM   ((4*128*20 * 2) * 4)          // 81920 (m path; score single-shot uses 69632 of it)
#define CTX_S_BYTES   (4 * 128 * 24 * 2)
#define CTX_E_BYTES   (4 * 128 * 24 * 2)
#define CTX_V_BYTES   (4 * 16 * 72 * 4)
#define CTXF_SMEM  (CTX_S_BYTES + CTX_E_BYTES + CTX_V_BYTES)  // 67584

// ---------------- weight preround ----------------
struct WSrc { const float* p[6]; };

__global__ void preround_kernel(WSrc ws)
{
    const int z = blockIdx.y;
    const float4* src = (const float4*)ws.p[z];
    float4* dst = (float4*)(g_W + z * Dsz * Dsz);
    int idx = blockIdx.x * 256 + threadIdx.x;
    float4 v = src[idx];
    dst[idx] = make_float4(tf32r(v.x), tf32r(v.y), tf32r(v.z), tf32r(v.w));
}

// ---------------- batched projections / dense ----------------
struct ProjArgs {
    const float* A[5];
    const float* W[5];
    const float* bias[5];
    float* C[5];
};

template<bool ACVT>
__global__ void __launch_bounds__(256, 2) proj_gemm_kernel(ProjArgs args, int N, int K, int roundOut)
{
    const int z = blockIdx.z;
    float acc[2][8][4] = {};
    const float* Ab = args.A[z] + (size_t)blockIdx.y * 128 * K;
    const float* Bb = args.W[z] + blockIdx.x * 128;
    gemm_core<128, 128, false, 2, 8, ACVT, false>(Ab, K, Bb, N, K, acc);

    const float* bias = args.bias[z];
    float* C = args.C[z];
    int lane = threadIdx.x & 31, wid = threadIdx.x >> 5;
    int rowBase = blockIdx.y * 128 + (wid & 3) * 32 + (lane >> 2);
    int colBase = blockIdx.x * 128 + (wid >> 2) * 64 + 2 * (lane & 3);
    #pragma unroll
    for (int mt = 0; mt < 2; mt++)
        #pragma unroll
        for (int nt = 0; nt < 8; nt++) {
            int row = rowBase + mt * 16;
            int col = colBase + nt * 8;
            float b0 = bias[col], b1 = bias[col + 1];
            float v0 = acc[mt][nt][0] + b0, v1 = acc[mt][nt][1] + b1;
            float v2 = acc[mt][nt][2] + b0, v3 = acc[mt][nt][3] + b1;
            if (roundOut) {
                v0 = tf32r(v0); v1 = tf32r(v1); v2 = tf32r(v2); v3 = tf32r(v3);
            }
            *(float2*)&C[(size_t)row * N + col]       = make_float2(v0, v1);
            *(float2*)&C[(size_t)(row + 8) * N + col] = make_float2(v2, v3);
        }
}

// ---------------- merged m + score launch ----------------
// z in [0,4): m path, pipelined K=512.
// z in [4,36): score path, SINGLE-SHOT K=64: whole A(128x64)+B(128x64) loaded in one
// cp.async batch, one sync, then 128 uninterrupted MMAs. Pitch 68 -> conflict-free
// frag LDS (bank = 4*row + fcol, all 32 distinct).
__global__ void __launch_bounds__(256, 2) ms_gemm_kernel(float* __restrict__ m_out)
{
    const int zz = blockIdx.z;
    int lane = threadIdx.x & 31, wid = threadIdx.x >> 5;
    int fcol = lane & 3;

    if (zz < Bsz) {
        const float SCALE = 0.04419417382415922f; // 1/sqrt(512)
        const int zb = zz;
        float acc[2][8][4] = {};
        const float* Ab = g_QP + (size_t)zb * Lsz * Dsz + (size_t)blockIdx.y * 128 * Dsz;
        const float* Bb = g_KP + (size_t)zb * Lsz * Dsz + (size_t)blockIdx.x * 128 * Dsz;
        gemm_core<128, 128, true, 2, 8, false, false>(Ab, Dsz, Bb, Dsz, Dsz, acc);

        float* Mo = m_out + (size_t)zb * Lsz * Lsz;
        __nv_bfloat16* Eo = g_EMb + (size_t)zb * Lsz * Lsz;
        int rowBase = blockIdx.y * 128 + (wid & 3) * 32 + (lane >> 2);
        int colBase = blockIdx.x * 128 + (wid >> 2) * 64 + 2 * fcol;
        #pragma unroll
        for (int mt = 0; mt < 2; mt++)
            #pragma unroll
            for (int nt = 0; nt < 8; nt++) {
                int row = rowBase + mt * 16;
                int col = colBase + nt * 8;
                #pragma unroll
                for (int h = 0; h < 2; h++) {
                    int r = row + h * 8;
                    float s0 = 1.0f / (1.0f + __expf(-acc[mt][nt][2*h] * SCALE));
                    float s1 = 1.0f / (1.0f + __expf(-acc[mt][nt][2*h+1] * SCALE));
                    *(float2*)&Mo[(size_t)r * Lsz + col] = make_float2(s0, s1);
                    *(__nv_bfloat162*)&Eo[(size_t)r * Lsz + col] =
                        __float22bfloat162_rn(make_float2(__expf(1.0f - s0), __expf(1.0f - s1)));
                }
            }
    } else {
        const float SCALE = 0.125f;
        const int z = zz - Bsz;
        const int b = z >> 3, h = z & 7;
        const float* Ab = g_Q + (size_t)b * Lsz * Dsz + h * DKsz + (size_t)blockIdx.y * 128 * Dsz;
        const float* Bb = g_K + (size_t)b * Lsz * Dsz + h * DKsz + (size_t)blockIdx.x * 128 * Dsz;

        extern __shared__ float dynsm[];
        float* As = dynsm;              // 128 x 68
        float* Bs = dynsm + 128 * 68;   // 128 x 68
        const unsigned* Asu = (const unsigned*)As;
        const unsigned* Bsu = (const unsigned*)Bs;
        const int tid = threadIdx.x;

        // one-shot load: 128 rows x 16 float4 each for A and B
        #pragma unroll
        for (int i = 0; i < 8; i++) {
            int idx = tid + i * 256;
            int row = idx >> 4, q = idx & 15;
            cp_async16(&As[row * 68 + q * 4], Ab + (size_t)row * Dsz + q * 4);
        }
        #pragma unroll
        for (int i = 0; i < 8; i++) {
            int idx = tid + i * 256;
            int row = idx >> 4, q = idx & 15;
            cp_async16(&Bs[row * 68 + q * 4], Bb + (size_t)row * Dsz + q * 4);
        }
        cp_commit();
        cp_wait<0>();
        __syncthreads();

        const int wm0 = (wid & 3) * 32;
        const int wn0 = (wid >> 2) * 64;
        const int frow = lane >> 2;
        float acc[2][8][4] = {};

        #pragma unroll
        for (int ks = 0; ks < 8; ks++) {
            const int kk = ks * 8 + fcol;
            unsigned af[2][4];
            #pragma unroll
            for (int mt = 0; mt < 2; mt++) {
                int row = wm0 + mt * 16 + frow;
                af[mt][0] = Asu[row * 68 + kk];
                af[mt][1] = Asu[(row + 8) * 68 + kk];
                af[mt][2] = Asu[row * 68 + kk + 4];
                af[mt][3] = Asu[(row + 8) * 68 + kk + 4];
            }
            #pragma unroll
            for (int nt = 0; nt < 8; nt++) {
                int n = wn0 + nt * 8 + frow;
                unsigned bf[2] = { Bsu[n * 68 + kk], Bsu[n * 68 + kk + 4] };
                #pragma unroll
                for (int mt = 0; mt < 2; mt++)
                    mma_tf32(acc[mt][nt], af[mt], bf);
            }
        }

        __nv_bfloat16* Cp = g_Sb + (size_t)z * Lsz * Lsz;
        int rowBase = blockIdx.y * 128 + wm0 + frow;
        int colBase = blockIdx.x * 128 + wn0 + 2 * fcol;

        float rs[2][2] = {};
        #pragma unroll
        for (int mt = 0; mt < 2; mt++)
            #pragma unroll
            for (int nt = 0; nt < 8; nt++) {
                int row = rowBase + mt * 16;
                int col = colBase + nt * 8;
                float p0 = __expf(acc[mt][nt][0] * SCALE);
                float p1 = __expf(acc[mt][nt][1] * SCALE);
                float p2 = __expf(acc[mt][nt][2] * SCALE);
                float p3 = __expf(acc[mt][nt][3] * SCALE);
                *(__nv_bfloat162*)&Cp[(size_t)row * Lsz + col] =
                    __float22bfloat162_rn(make_float2(p0, p1));
                *(__nv_bfloat162*)&Cp[(size_t)(row + 8) * Lsz + col] =
                    __float22bfloat162_rn(make_float2(p2, p3));
                rs[mt][0] += p0 + p1;
                rs[mt][1] += p2 + p3;
            }

        #pragma unroll
        for (int mt = 0; mt < 2; mt++)
            #pragma unroll
            for (int hh = 0; hh < 2; hh++) {
                float v = rs[mt][hh];
                v += __shfl_xor_sync(0xffffffffu, v, 1);
                v += __shfl_xor_sync(0xffffffffu, v, 2);
                if (fcol == 0)
                    atomicAdd(&g_Z[(size_t)z * Lsz + rowBase + mt * 16 + hh * 8], v);
            }
    }
}

// ---------------- fused calibrate + ctx GEMM (Taylor exp, register transform) ----------------
__global__ void __launch_bounds__(256, 2) ctx_fused_kernel()
{
    extern __shared__ char smc[];
    __nv_bfloat16* Ss = (__nv_bfloat16*)smc;
    __nv_bfloat16* Es = (__nv_bfloat16*)(smc + CTX_S_BYTES);
    unsigned* Vu = (unsigned*)(smc + CTX_S_BYTES + CTX_E_BYTES);
    float* Vf = (float*)Vu;

    const int tid = threadIdx.x;
    const int lane = tid & 31;
    const int wid = tid >> 5;
    const int z = blockIdx.z;
    const int b = z >> 3, h = z & 7;
    const int q0 = blockIdx.y * 128;

    const __nv_bfloat16* Sg = g_Sb + (size_t)z * Lsz * Lsz + (size_t)q0 * Lsz;
    const __nv_bfloat16* Eg = g_EMb + (size_t)b * Lsz * Lsz + (size_t)q0 * Lsz;
    const float* Vg = g_V + (size_t)b * Lsz * Dsz + h * DKsz;

    const int wm = wid * 16;
    const int frow = lane >> 2, fcol = lane & 3;
    const int r0 = wm + frow, r1 = r0 + 8;

    const float g0 = g_G[b * Lsz + q0 + r0];
    const float g1 = g_G[b * Lsz + q0 + r1];
    const float iz0 = 1.0f / g_Z[(size_t)z * Lsz + q0 + r0];
    const float iz1 = 1.0f / g_Z[(size_t)z * Lsz + q0 + r1];
    const float ga0 = g0 * iz0, gc0 = (1.0f - g0) * iz0;
    const float ga1 = g1 * iz1, gc1 = (1.0f - g1) * iz1;
    float z2a = 0.f, z2b = 0.f;

    auto prefetch = [&](int it, int s) {
        const int k0 = it * 16;
        __nv_bfloat16* Sl = Ss + s * 128 * 24;
        __nv_bfloat16* El = Es + s * 128 * 24;
        float* Vl = Vf + s * 16 * 72;
        {
            int row = tid >> 1, ch = tid & 1;
            cp_async16(&Sl[row * 24 + ch * 8], Sg + (size_t)row * Lsz + k0 + ch * 8);
            cp_async16(&El[row * 24 + ch * 8], Eg + (size_t)row * Lsz + k0 + ch * 8);
        }
        {
            int vr = tid >> 4, vc = tid & 15;
            cp_async16(&Vl[vr * 72 + vc * 4], Vg + (size_t)(k0 + vr) * Dsz + vc * 4);
        }
        cp_commit();
    };

    float acc[8][4] = {};
    const int nIter = Lsz / 16;
    prefetch(0, 0);
    prefetch(1, 1);

    for (int it = 0; it < nIter; it++) {
        if (it + 2 < nIter) { prefetch(it + 2, (it + 2) & 3); cp_wait<2>(); }
        else if (it + 1 < nIter) { cp_wait<1>(); }
        else { cp_wait<0>(); }
        __syncthreads();

        const int cur = it & 3;
        const __nv_bfloat16* Sl = Ss + cur * 128 * 24;
        const __nv_bfloat16* El = Es + cur * 128 * 24;
        const unsigned* Vl = Vu + cur * 16 * 72;

        #pragma unroll
        for (int ks = 0; ks < 2; ks++) {
            const int kk = ks * 8 + fcol;

            float p00 = __bfloat162float(Sl[r0 * 24 + kk]);
            float p10 = __bfloat162float(Sl[r1 * 24 + kk]);
            float p01 = __bfloat162float(Sl[r0 * 24 + kk + 4]);
            float p11 = __bfloat162float(Sl[r1 * 24 + kk + 4]);
            float e00 = __bfloat162float(El[r0 * 24 + kk]);
            float e10 = __bfloat162float(El[r1 * 24 + kk]);
            float e01 = __bfloat162float(El[r0 * 24 + kk + 4]);
            float e11 = __bfloat162float(El[r1 * 24 + kk + 4]);

            float x00 = p00 * fmaf(gc0, e00, ga0);
            float x10 = p10 * fmaf(gc1, e10, ga1);
            float x01 = p01 * fmaf(gc0, e01, ga0);
            float x11 = p11 * fmaf(gc1, e11, ga1);

            unsigned af[4];
            af[0] = f2tf(fmaf(x00, fmaf(x00, 0.5f, 1.0f), 1.0f));
            af[1] = f2tf(fmaf(x10, fmaf(x10, 0.5f, 1.0f), 1.0f));
            af[2] = f2tf(fmaf(x01, fmaf(x01, 0.5f, 1.0f), 1.0f));
            af[3] = f2tf(fmaf(x11, fmaf(x11, 0.5f, 1.0f), 1.0f));
            z2a += __uint_as_float(af[0]) + __uint_as_float(af[2]);
            z2b += __uint_as_float(af[1]) + __uint_as_float(af[3]);

            #pragma unroll
            for (int nt = 0; nt < 8; nt++) {
                const int n = nt * 8 + frow;
                unsigned bf[2] = { Vl[kk * 72 + n], Vl[(kk + 4) * 72 + n] };
                mma_tf32(acc[nt], af, bf);
            }
        }
    }

    z2a += __shfl_xor_sync(0xffffffffu, z2a, 1);
    z2a += __shfl_xor_sync(0xffffffffu, z2a, 2);
    z2b += __shfl_xor_sync(0xffffffffu, z2b, 1);
    z2b += __shfl_xor_sync(0xffffffffu, z2b, 2);
    const float iza = 1.0f / z2a;
    const float izb = 1.0f / z2b;

    float* Cp = g_CTX + (size_t)b * Lsz * Dsz + (size_t)q0 * Dsz + h * DKsz;
    #pragma unroll
    for (int nt = 0; nt < 8; nt++) {
        const int col = nt * 8 + 2 * fcol;
        *(float2*)&Cp[(size_t)r0 * Dsz + col] =
            make_float2(tf32r(acc[nt][0] * iza), tf32r(acc[nt][1] * iza));
        *(float2*)&Cp[(size_t)r1 * Dsz + col] =
            make_float2(tf32r(acc[nt][2] * izb), tf32r(acc[nt][3] * izb));
    }
}

// ---------------- gate (+ zero g_Z) ----------------
__global__ void gate_kernel(const float* __restrict__ query,
                            const float* __restrict__ gw,
                            const float* __restrict__ gb)
{
    int gidx = blockIdx.x * blockDim.x + threadIdx.x;
    if (gidx < Bsz * Hsz * Lsz) g_Z[gidx] = 0.f;

    int warp = gidx >> 5;
    int lane = threadIdx.x & 31;
    if (warp >= Bsz * Lsz) return;
    const float* row = query + (size_t)warp * Dsz;
    float s = 0.f;
    for (int d = lane; d < Dsz; d += 32) s += row[d] * gw[d];
    #pragma unroll
    for (int o = 16; o; o >>= 1) s += __shfl_xor_sync(0xffffffffu, s, o);
    if (lane == 0) g_G[warp] = 1.0f / (1.0f + __expf(-(s + gb[0])));
}

// ---------------- launch ----------------
extern "C" void kernel_launch(void* const* d_in, const int* in_sizes, int n_in,
                              void* d_out, int out_size)
{
    const float* query   = (const float*)d_in[0];
    const float* key     = (const float*)d_in[1];
    const float* value   = (const float*)d_in[2];
    const float* wq_w    = (const float*)d_in[3];
    const float* wq_b    = (const float*)d_in[4];
    const float* wk_w    = (const float*)d_in[5];
    const float* wk_b    = (const float*)d_in[6];
    const float* wv_w    = (const float*)d_in[7];
    const float* wv_b    = (const float*)d_in[8];
    const float* dense_w = (const float*)d_in[9];
    const float* dense_b = (const float*)d_in[10];
    const float* gate_w  = (const float*)d_in[11];
    const float* gate_b  = (const float*)d_in[12];
    const float* mp_wq_w = (const float*)d_in[13];
    const float* mp_wq_b = (const float*)d_in[14];
    const float* mp_wk_w = (const float*)d_in[15];
    const float* mp_wk_b = (const float*)d_in[16];

    float* out   = (float*)d_out;
    float* m_out = out + (size_t)Bsz * Lsz * Dsz;

    float *pQ, *pK, *pV, *pQP, *pKP, *pCTX, *pW;
    cudaGetSymbolAddress((void**)&pQ,   g_Q);
    cudaGetSymbolAddress((void**)&pK,   g_K);
    cudaGetSymbolAddress((void**)&pV,   g_V);
    cudaGetSymbolAddress((void**)&pQP,  g_QP);
    cudaGetSymbolAddress((void**)&pKP,  g_KP);
    cudaGetSymbolAddress((void**)&pCTX, g_CTX);
    cudaGetSymbolAddress((void**)&pW,   g_W);

    static int attr_set = 0;
    if (!attr_set) {
        cudaFuncSetAttribute(proj_gemm_kernel<true>,
                             cudaFuncAttributeMaxDynamicSharedMemorySize, PROJ_SMEM);
        cudaFuncSetAttribute(proj_gemm_kernel<false>,
                             cudaFuncAttributeMaxDynamicSharedMemorySize, PROJ_SMEM);
        cudaFuncSetAttribute(ms_gemm_kernel,
                             cudaFuncAttributeMaxDynamicSharedMemorySize, NTG_SMEM);
        cudaFuncSetAttribute(ctx_fused_kernel,
                             cudaFuncAttributeMaxDynamicSharedMemorySize, CTXF_SMEM);
        attr_set = 1;
    }

    dim3 t256(256);

    WSrc ws;
    ws.p[0] = wq_w; ws.p[1] = wk_w; ws.p[2] = wv_w;
    ws.p[3] = mp_wq_w; ws.p[4] = mp_wk_w; ws.p[5] = dense_w;
    preround_kernel<<<dim3(256, 6), t256>>>(ws);

    gate_kernel<<<(Bsz * Lsz * 32) / 256, t256>>>(query, gate_w, gate_b);

    ProjArgs pa;
    pa.A[0] = query; pa.W[0] = pW + 0*Dsz*Dsz; pa.bias[0] = wq_b;    pa.C[0] = pQ;
    pa.A[1] = key;   pa.W[1] = pW + 1*Dsz*Dsz; pa.bias[1] = wk_b;    pa.C[1] = pK;
    pa.A[2] = value; pa.W[2] = pW + 2*Dsz*Dsz; pa.bias[2] = wv_b;    pa.C[2] = pV;
    pa.A[3] = query; pa.W[3] = pW + 3*Dsz*Dsz; pa.bias[3] = mp_wq_b; pa.C[3] = pQP;
    pa.A[4] = key;   pa.W[4] = pW + 4*Dsz*Dsz; pa.bias[4] = mp_wk_b; pa.C[4] = pKP;
    proj_gemm_kernel<true><<<dim3(4, 32, 5), t256, PROJ_SMEM>>>(pa, Dsz, Dsz, 1);

    ms_gemm_kernel<<<dim3(8, 8, Bsz + Bsz * Hsz), t256, NTG_SMEM>>>(m_out);

    ctx_fused_kernel<<<dim3(1, 8, Bsz * Hsz), t256, CTXF_SMEM>>>();

    ProjArgs da;
    da.A[0] = pCTX; da.W[0] = pW + 5*Dsz*Dsz; da.bias[0] = dense_b; da.C[0] = out;
    proj_gemm_kernel<false><<<dim3(4, 32, 1), t256, PROJ_SMEM>>>(da, Dsz, Dsz, 0);
}

// round 11
// speedup vs baseline: 1.0635x; 1.0385x over previous
#include <cuda_runtime.h>
#include <cuda_bf16.h>
#include <math.h>

#define Bsz 4
#define Lsz 1024
#define Dsz 512
#define Hsz 8
#define DKsz 64

// ---------------- scratch (static device globals; no allocation) ----------------
__device__ __nv_bfloat16 g_Qbf[Bsz*Lsz*Dsz];   // projected q, bf16 (score path only)
__device__ __nv_bfloat16 g_Kbf[Bsz*Lsz*Dsz];   // projected k, bf16
__device__ float g_V[Bsz*Lsz*Dsz];      // tf32-prerounded
__device__ float g_QP[Bsz*Lsz*Dsz];     // tf32-prerounded
__device__ float g_KP[Bsz*Lsz*Dsz];     // tf32-prerounded
__device__ float g_W[6*Dsz*Dsz];        // tf32-prerounded weights
__device__ __nv_bfloat16 g_EMb[Bsz*Lsz*Lsz];              // exp(1-m), bf16
__device__ float g_G[Bsz*Lsz];
__device__ __nv_bfloat16 g_Sb[(size_t)Bsz*Hsz*Lsz*Lsz];   // exp(scores), bf16
__device__ float g_Z[Bsz*Hsz*Lsz];
__device__ float g_CTX[Bsz*Lsz*Dsz];    // tf32-prerounded

// ---------------- helpers ----------------
__device__ __forceinline__ unsigned f2tf(float f) {
    unsigned u;
    asm("cvt.rna.tf32.f32 %0, %1;" : "=r"(u) : "f"(f));
    return u;
}
__device__ __forceinline__ float tf32r(float f) { return __uint_as_float(f2tf(f)); }

__device__ __forceinline__ void mma_tf32(float c[4], const unsigned a[4], const unsigned b[2]) {
    asm volatile(
        "mma.sync.aligned.m16n8k8.row.col.f32.tf32.tf32.f32 "
        "{%0,%1,%2,%3}, {%4,%5,%6,%7}, {%8,%9}, {%0,%1,%2,%3};"
        : "+f"(c[0]), "+f"(c[1]), "+f"(c[2]), "+f"(c[3])
        : "r"(a[0]), "r"(a[1]), "r"(a[2]), "r"(a[3]), "r"(b[0]), "r"(b[1]));
}

__device__ __forceinline__ void mma_bf16(float c[4], const unsigned a[4], const unsigned b[2]) {
    asm volatile(
        "mma.sync.aligned.m16n8k16.row.col.f32.bf16.bf16.f32 "
        "{%0,%1,%2,%3}, {%4,%5,%6,%7}, {%8,%9}, {%0,%1,%2,%3};"
        : "+f"(c[0]), "+f"(c[1]), "+f"(c[2]), "+f"(c[3])
        : "r"(a[0]), "r"(a[1]), "r"(a[2]), "r"(a[3]), "r"(b[0]), "r"(b[1]));
}

__device__ __forceinline__ void cp_async16(void* smem, const void* gmem) {
    unsigned saddr = (unsigned)__cvta_generic_to_shared(smem);
    asm volatile("cp.async.cg.shared.global [%0], [%1], 16;" :: "r"(saddr), "l"(gmem));
}
__device__ __forceinline__ void cp_commit() { asm volatile("cp.async.commit_group;"); }
template<int N>
__device__ __forceinline__ void cp_wait() { asm volatile("cp.async.wait_group %0;" :: "n"(N)); }

// ---------------- tf32 GEMM core, 4-stage pipeline, prefetch-before-sync ----------------
template<int BM, int BN, bool BT, int MT, int NT, bool ACVT, bool BCVT>
__device__ __forceinline__ void gemm_core(
    const float* __restrict__ A, int lda,
    const float* __restrict__ B, int ldb,
    int K, float (&acc)[MT][NT][4])
{
    constexpr int BK = 16;
    constexpr int APITCH = BK + 4;
    constexpr int BPITCH = BT ? (BK + 4) : (BN + 8);
    constexpr int BROWS  = BT ? BN : BK;

    extern __shared__ float dynsm[];
    float* As = dynsm;
    float* Bs = dynsm + 4 * BM * APITCH;

    const int tid = threadIdx.x;
    const int lane = tid & 31;
    const int wid = tid >> 5;
    const int wm0 = (wid & 3) * (BM / 4);
    const int wn0 = (wid >> 2) * (BN / 2);

    constexpr int ALD = (BM * BK / 4) / 256;
    constexpr int BLD = (BT ? (BN * BK / 4) : (BK * BN / 4)) / 256;

    auto prefetch = [&](int k0, int s) {
        float* Asl = As + s * BM * APITCH;
        float* Bsl = Bs + s * BROWS * BPITCH;
        #pragma unroll
        for (int i = 0; i < ALD; i++) {
            int idx = tid + i * 256;
            int row = idx >> 2, kq = idx & 3;
            cp_async16(&Asl[row * APITCH + kq * 4], A + (size_t)row * lda + k0 + kq * 4);
        }
        #pragma unroll
        for (int i = 0; i < BLD; i++) {
            int idx = tid + i * 256;
            if constexpr (BT) {
                int row = idx >> 2, kq = idx & 3;
                cp_async16(&Bsl[row * BPITCH + kq * 4], B + (size_t)row * ldb + k0 + kq * 4);
            } else {
                int k = idx / (BN / 4), nq = idx % (BN / 4);
                cp_async16(&Bsl[k * BPITCH + nq * 4], B + (size_t)(k0 + k) * ldb + nq * 4);
            }
        }
        cp_commit();
    };

    const int nIter = K / BK;
    prefetch(0, 0);
    if (nIter > 1) prefetch(BK, 1);

    for (int it = 0; it < nIter; it++) {
        if (it + 2 < nIter) { prefetch((it + 2) * BK, (it + 2) & 3); cp_wait<2>(); }
        else if (it + 1 < nIter) { cp_wait<1>(); }
        else { cp_wait<0>(); }
        __syncthreads();

        const int cur = it & 3;
        const float* Asl = As + cur * BM * APITCH;
        const float* Bsl = Bs + cur * BROWS * BPITCH;
        const unsigned* Aslu = (const unsigned*)Asl;
        const unsigned* Bslu = (const unsigned*)Bsl;

        #pragma unroll
        for (int ks = 0; ks < 2; ks++) {
            unsigned af[MT][4];
            unsigned bf[NT][2];
            const int kk = ks * 8 + (lane & 3);
            #pragma unroll
            for (int mt = 0; mt < MT; mt++) {
                int row = wm0 + mt * 16 + (lane >> 2);
                if constexpr (ACVT) {
                    af[mt][0] = f2tf(Asl[row * APITCH + kk]);
                    af[mt][1] = f2tf(Asl[(row + 8) * APITCH + kk]);
                    af[mt][2] = f2tf(Asl[row * APITCH + kk + 4]);
                    af[mt][3] = f2tf(Asl[(row + 8) * APITCH + kk + 4]);
                } else {
                    af[mt][0] = Aslu[row * APITCH + kk];
                    af[mt][1] = Aslu[(row + 8) * APITCH + kk];
                    af[mt][2] = Aslu[row * APITCH + kk + 4];
                    af[mt][3] = Aslu[(row + 8) * APITCH + kk + 4];
                }
            }
            #pragma unroll
            for (int nt = 0; nt < NT; nt++) {
                int n = wn0 + nt * 8 + (lane >> 2);
                if constexpr (BT) {
                    if constexpr (BCVT) {
                        bf[nt][0] = f2tf(Bsl[n * BPITCH + kk]);
                        bf[nt][1] = f2tf(Bsl[n * BPITCH + kk + 4]);
                    } else {
                        bf[nt][0] = Bslu[n * BPITCH + kk];
                        bf[nt][1] = Bslu[n * BPITCH + kk + 4];
                    }
                } else {
                    if constexpr (BCVT) {
                        bf[nt][0] = f2tf(Bsl[kk * BPITCH + n]);
                        bf[nt][1] = f2tf(Bsl[(kk + 4) * BPITCH + n]);
                    } else {
                        bf[nt][0] = Bslu[kk * BPITCH + n];
                        bf[nt][1] = Bslu[(kk + 4) * BPITCH + n];
                    }
                }
            }
            #pragma unroll
            for (int mt = 0; mt < MT; mt++)
                #pragma unroll
                for (int nt = 0; nt < NT; nt++)
                    mma_tf32(acc[mt][nt], af[mt], bf[nt]);
        }
    }
}

// smem byte sizes
#define PROJ_SMEM  ((4*128*20 + 4*16*136) * 4)   // 75776
#define NTG_SMEM   ((4*128*20 * 2) * 4)          // 81920 (m path; score bf16 uses 45056)
#define CTX_S_BYTES   (4 * 128 * 24 * 2)
#define CTX_E_BYTES   (4 * 128 * 24 * 2)
#define CTX_V_BYTES   (4 * 16 * 72 * 4)
#define CTXF_SMEM  (CTX_S_BYTES + CTX_E_BYTES + CTX_V_BYTES)  // 67584

// ---------------- weight preround ----------------
struct WSrc { const float* p[6]; };

__global__ void preround_kernel(WSrc ws)
{
    const int z = blockIdx.y;
    const float4* src = (const float4*)ws.p[z];
    float4* dst = (float4*)(g_W + z * Dsz * Dsz);
    int idx = blockIdx.x * 256 + threadIdx.x;
    float4 v = src[idx];
    dst[idx] = make_float4(tf32r(v.x), tf32r(v.y), tf32r(v.z), tf32r(v.w));
}

// ---------------- batched projections / dense ----------------
// mode: 0 = plain fp32, 1 = tf32-rounded fp32, 2 = bf16
struct ProjArgs {
    const float* A[5];
    const float* W[5];
    const float* bias[5];
    void* C[5];
    int mode[5];
};

template<bool ACVT>
__global__ void __launch_bounds__(256, 2) proj_gemm_kernel(ProjArgs args, int N, int K)
{
    const int z = blockIdx.z;
    float acc[2][8][4] = {};
    const float* Ab = args.A[z] + (size_t)blockIdx.y * 128 * K;
    const float* Bb = args.W[z] + blockIdx.x * 128;
    gemm_core<128, 128, false, 2, 8, ACVT, false>(Ab, K, Bb, N, K, acc);

    const float* bias = args.bias[z];
    const int mode = args.mode[z];
    int lane = threadIdx.x & 31, wid = threadIdx.x >> 5;
    int rowBase = blockIdx.y * 128 + (wid & 3) * 32 + (lane >> 2);
    int colBase = blockIdx.x * 128 + (wid >> 2) * 64 + 2 * (lane & 3);
    #pragma unroll
    for (int mt = 0; mt < 2; mt++)
        #pragma unroll
        for (int nt = 0; nt < 8; nt++) {
            int row = rowBase + mt * 16;
            int col = colBase + nt * 8;
            float b0 = bias[col], b1 = bias[col + 1];
            float v0 = acc[mt][nt][0] + b0, v1 = acc[mt][nt][1] + b1;
            float v2 = acc[mt][nt][2] + b0, v3 = acc[mt][nt][3] + b1;
            if (mode == 2) {
                __nv_bfloat16* Cb = (__nv_bfloat16*)args.C[z];
                *(__nv_bfloat162*)&Cb[(size_t)row * N + col] =
                    __float22bfloat162_rn(make_float2(v0, v1));
                *(__nv_bfloat162*)&Cb[(size_t)(row + 8) * N + col] =
                    __float22bfloat162_rn(make_float2(v2, v3));
            } else {
                if (mode == 1) {
                    v0 = tf32r(v0); v1 = tf32r(v1); v2 = tf32r(v2); v3 = tf32r(v3);
                }
                float* C = (float*)args.C[z];
                *(float2*)&C[(size_t)row * N + col]       = make_float2(v0, v1);
                *(float2*)&C[(size_t)(row + 8) * N + col] = make_float2(v2, v3);
            }
        }
}

// ---------------- merged m + score launch ----------------
// z in [0,4): m path, tf32 pipelined K=512 (m is a checked output; keep precision).
// z in [4,36): score path, bf16 m16n8k16 single-shot K=64. Pitch 88 bf16 = word
// pitch 44 (≡12 mod 32) -> conflict-free fragment LDS; each 32-bit reg holds an
// adjacent bf16 k-pair, so LDS count per MMA halves and MMA count halves vs tf32.
__global__ void __launch_bounds__(256, 2) ms_gemm_kernel(float* __restrict__ m_out)
{
    const int zz = blockIdx.z;
    int lane = threadIdx.x & 31, wid = threadIdx.x >> 5;
    int fcol = lane & 3;

    if (zz < Bsz) {
        const float SCALE = 0.04419417382415922f; // 1/sqrt(512)
        const int zb = zz;
        float acc[2][8][4] = {};
        const float* Ab = g_QP + (size_t)zb * Lsz * Dsz + (size_t)blockIdx.y * 128 * Dsz;
        const float* Bb = g_KP + (size_t)zb * Lsz * Dsz + (size_t)blockIdx.x * 128 * Dsz;
        gemm_core<128, 128, true, 2, 8, false, false>(Ab, Dsz, Bb, Dsz, Dsz, acc);

        float* Mo = m_out + (size_t)zb * Lsz * Lsz;
        __nv_bfloat16* Eo = g_EMb + (size_t)zb * Lsz * Lsz;
        int rowBase = blockIdx.y * 128 + (wid & 3) * 32 + (lane >> 2);
        int colBase = blockIdx.x * 128 + (wid >> 2) * 64 + 2 * fcol;
        #pragma unroll
        for (int mt = 0; mt < 2; mt++)
            #pragma unroll
            for (int nt = 0; nt < 8; nt++) {
                int row = rowBase + mt * 16;
                int col = colBase + nt * 8;
                #pragma unroll
                for (int h = 0; h < 2; h++) {
                    int r = row + h * 8;
                    float s0 = 1.0f / (1.0f + __expf(-acc[mt][nt][2*h] * SCALE));
                    float s1 = 1.0f / (1.0f + __expf(-acc[mt][nt][2*h+1] * SCALE));
                    *(float2*)&Mo[(size_t)r * Lsz + col] = make_float2(s0, s1);
                    *(__nv_bfloat162*)&Eo[(size_t)r * Lsz + col] =
                        __float22bfloat162_rn(make_float2(__expf(1.0f - s0), __expf(1.0f - s1)));
                }
            }
    } else {
        const float SCALE = 0.125f;
        const int z = zz - Bsz;
        const int b = z >> 3, h = z & 7;
        const __nv_bfloat16* Ab = g_Qbf + ((size_t)b * Lsz + blockIdx.y * 128) * Dsz + h * DKsz;
        const __nv_bfloat16* Bb = g_Kbf + ((size_t)b * Lsz + blockIdx.x * 128) * Dsz + h * DKsz;

        extern __shared__ float dynsm[];
        __nv_bfloat16* Qs = (__nv_bfloat16*)dynsm;        // 128 x 88 bf16
        __nv_bfloat16* Ks = Qs + 128 * 88;                // 128 x 88 bf16
        const unsigned* Qw = (const unsigned*)Qs;          // word pitch 44
        const unsigned* Kw = (const unsigned*)Ks;
        const int tid = threadIdx.x;

        // one-shot load: 128 rows x 8 x 16B (64 bf16) per tensor
        #pragma unroll
        for (int i = 0; i < 4; i++) {
            int idx = tid + i * 256;
            int row = idx >> 3, ch = idx & 7;
            cp_async16(&Qs[row * 88 + ch * 8], Ab + (size_t)row * Dsz + ch * 8);
        }
        #pragma unroll
        for (int i = 0; i < 4; i++) {
            int idx = tid + i * 256;
            int row = idx >> 3, ch = idx & 7;
            cp_async16(&Ks[row * 88 + ch * 8], Bb + (size_t)row * Dsz + ch * 8);
        }
        cp_commit();
        cp_wait<0>();
        __syncthreads();

        const int wm0 = (wid & 3) * 32;
        const int wn0 = (wid >> 2) * 64;
        const int frow = lane >> 2;
        float acc[2][8][4] = {};

        #pragma unroll
        for (int ks = 0; ks < 4; ks++) {
            const int kw = ks * 8 + fcol;
            unsigned af[2][4];
            #pragma unroll
            for (int mt = 0; mt < 2; mt++) {
                int row = wm0 + mt * 16 + frow;
                af[mt][0] = Qw[row * 44 + kw];
                af[mt][1] = Qw[(row + 8) * 44 + kw];
                af[mt][2] = Qw[row * 44 + kw + 4];
                af[mt][3] = Qw[(row + 8) * 44 + kw + 4];
            }
            #pragma unroll
            for (int nt = 0; nt < 8; nt++) {
                int n = wn0 + nt * 8 + frow;
                unsigned bf[2] = { Kw[n * 44 + kw], Kw[n * 44 + kw + 4] };
                #pragma unroll
                for (int mt = 0; mt < 2; mt++)
                    mma_bf16(acc[mt][nt], af[mt], bf);
            }
        }

        __nv_bfloat16* Cp = g_Sb + (size_t)z * Lsz * Lsz;
        int rowBase = blockIdx.y * 128 + wm0 + frow;
        int colBase = blockIdx.x * 128 + wn0 + 2 * fcol;

        float rs[2][2] = {};
        #pragma unroll
        for (int mt = 0; mt < 2; mt++)
            #pragma unroll
            for (int nt = 0; nt < 8; nt++) {
                int row = rowBase + mt * 16;
                int col = colBase + nt * 8;
                float p0 = __expf(acc[mt][nt][0] * SCALE);
                float p1 = __expf(acc[mt][nt][1] * SCALE);
                float p2 = __expf(acc[mt][nt][2] * SCALE);
                float p3 = __expf(acc[mt][nt][3] * SCALE);
                *(__nv_bfloat162*)&Cp[(size_t)row * Lsz + col] =
                    __float22bfloat162_rn(make_float2(p0, p1));
                *(__nv_bfloat162*)&Cp[(size_t)(row + 8) * Lsz + col] =
                    __float22bfloat162_rn(make_float2(p2, p3));
                rs[mt][0] += p0 + p1;
                rs[mt][1] += p2 + p3;
            }

        #pragma unroll
        for (int mt = 0; mt < 2; mt++)
            #pragma unroll
            for (int hh = 0; hh < 2; hh++) {
                float v = rs[mt][hh];
                v += __shfl_xor_sync(0xffffffffu, v, 1);
                v += __shfl_xor_sync(0xffffffffu, v, 2);
                if (fcol == 0)
                    atomicAdd(&g_Z[(size_t)z * Lsz + rowBase + mt * 16 + hh * 8], v);
            }
    }
}

// ---------------- fused calibrate + ctx GEMM (Taylor exp, register transform) ----------------
__global__ void __launch_bounds__(256, 2) ctx_fused_kernel()
{
    extern __shared__ char smc[];
    __nv_bfloat16* Ss = (__nv_bfloat16*)smc;
    __nv_bfloat16* Es = (__nv_bfloat16*)(smc + CTX_S_BYTES);
    unsigned* Vu = (unsigned*)(smc + CTX_S_BYTES + CTX_E_BYTES);
    float* Vf = (float*)Vu;

    const int tid = threadIdx.x;
    const int lane = tid & 31;
    const int wid = tid >> 5;
    const int z = blockIdx.z;
    const int b = z >> 3, h = z & 7;
    const int q0 = blockIdx.y * 128;

    const __nv_bfloat16* Sg = g_Sb + (size_t)z * Lsz * Lsz + (size_t)q0 * Lsz;
    const __nv_bfloat16* Eg = g_EMb + (size_t)b * Lsz * Lsz + (size_t)q0 * Lsz;
    const float* Vg = g_V + (size_t)b * Lsz * Dsz + h * DKsz;

    const int wm = wid * 16;
    const int frow = lane >> 2, fcol = lane & 3;
    const int r0 = wm + frow, r1 = r0 + 8;

    const float g0 = g_G[b * Lsz + q0 + r0];
    const float g1 = g_G[b * Lsz + q0 + r1];
    const float iz0 = 1.0f / g_Z[(size_t)z * Lsz + q0 + r0];
    const float iz1 = 1.0f / g_Z[(size_t)z * Lsz + q0 + r1];
    const float ga0 = g0 * iz0, gc0 = (1.0f - g0) * iz0;
    const float ga1 = g1 * iz1, gc1 = (1.0f - g1) * iz1;
    float z2a = 0.f, z2b = 0.f;

    auto prefetch = [&](int it, int s) {
        const int k0 = it * 16;
        __nv_bfloat16* Sl = Ss + s * 128 * 24;
        __nv_bfloat16* El = Es + s * 128 * 24;
        float* Vl = Vf + s * 16 * 72;
        {
            int row = tid >> 1, ch = tid & 1;
            cp_async16(&Sl[row * 24 + ch * 8], Sg + (size_t)row * Lsz + k0 + ch * 8);
            cp_async16(&El[row * 24 + ch * 8], Eg + (size_t)row * Lsz + k0 + ch * 8);
        }
        {
            int vr = tid >> 4, vc = tid & 15;
            cp_async16(&Vl[vr * 72 + vc * 4], Vg + (size_t)(k0 + vr) * Dsz + vc * 4);
        }
        cp_commit();
    };

    float acc[8][4] = {};
    const int nIter = Lsz / 16;
    prefetch(0, 0);
    prefetch(1, 1);

    for (int it = 0; it < nIter; it++) {
        if (it + 2 < nIter) { prefetch(it + 2, (it + 2) & 3); cp_wait<2>(); }
        else if (it + 1 < nIter) { cp_wait<1>(); }
        else { cp_wait<0>(); }
        __syncthreads();

        const int cur = it & 3;
        const __nv_bfloat16* Sl = Ss + cur * 128 * 24;
        const __nv_bfloat16* El = Es + cur * 128 * 24;
        const unsigned* Vl = Vu + cur * 16 * 72;

        #pragma unroll
        for (int ks = 0; ks < 2; ks++) {
            const int kk = ks * 8 + fcol;

            float p00 = __bfloat162float(Sl[r0 * 24 + kk]);
            float p10 = __bfloat162float(Sl[r1 * 24 + kk]);
            float p01 = __bfloat162float(Sl[r0 * 24 + kk + 4]);
            float p11 = __bfloat162float(Sl[r1 * 24 + kk + 4]);
            float e00 = __bfloat162float(El[r0 * 24 + kk]);
            float e10 = __bfloat162float(El[r1 * 24 + kk]);
            float e01 = __bfloat162float(El[r0 * 24 + kk + 4]);
            float e11 = __bfloat162float(El[r1 * 24 + kk + 4]);

            float x00 = p00 * fmaf(gc0, e00, ga0);
            float x10 = p10 * fmaf(gc1, e10, ga1);
            float x01 = p01 * fmaf(gc0, e01, ga0);
            float x11 = p11 * fmaf(gc1, e11, ga1);

            unsigned af[4];
            af[0] = f2tf(fmaf(x00, fmaf(x00, 0.5f, 1.0f), 1.0f));
            af[1] = f2tf(fmaf(x10, fmaf(x10, 0.5f, 1.0f), 1.0f));
            af[2] = f2tf(fmaf(x01, fmaf(x01, 0.5f, 1.0f), 1.0f));
            af[3] = f2tf(fmaf(x11, fmaf(x11, 0.5f, 1.0f), 1.0f));
            z2a += __uint_as_float(af[0]) + __uint_as_float(af[2]);
            z2b += __uint_as_float(af[1]) + __uint_as_float(af[3]);

            #pragma unroll
            for (int nt = 0; nt < 8; nt++) {
                const int n = nt * 8 + frow;
                unsigned bf[2] = { Vl[kk * 72 + n], Vl[(kk + 4) * 72 + n] };
                mma_tf32(acc[nt], af, bf);
            }
        }
    }

    z2a += __shfl_xor_sync(0xffffffffu, z2a, 1);
    z2a += __shfl_xor_sync(0xffffffffu, z2a, 2);
    z2b += __shfl_xor_sync(0xffffffffu, z2b, 1);
    z2b += __shfl_xor_sync(0xffffffffu, z2b, 2);
    const float iza = 1.0f / z2a;
    const float izb = 1.0f / z2b;

    float* Cp = g_CTX + (size_t)b * Lsz * Dsz + (size_t)q0 * Dsz + h * DKsz;
    #pragma unroll
    for (int nt = 0; nt < 8; nt++) {
        const int col = nt * 8 + 2 * fcol;
        *(float2*)&Cp[(size_t)r0 * Dsz + col] =
            make_float2(tf32r(acc[nt][0] * iza), tf32r(acc[nt][1] * iza));
        *(float2*)&Cp[(size_t)r1 * Dsz + col] =
            make_float2(tf32r(acc[nt][2] * izb), tf32r(acc[nt][3] * izb));
    }
}

// ---------------- gate (+ zero g_Z) ----------------
__global__ void gate_kernel(const float* __restrict__ query,
                            const float* __restrict__ gw,
                            const float* __restrict__ gb)
{
    int gidx = blockIdx.x * blockDim.x + threadIdx.x;
    if (gidx < Bsz * Hsz * Lsz) g_Z[gidx] = 0.f;

    int warp = gidx >> 5;
    int lane = threadIdx.x & 31;
    if (warp >= Bsz * Lsz) return;
    const float* row = query + (size_t)warp * Dsz;
    float s = 0.f;
    for (int d = lane; d < Dsz; d += 32) s += row[d] * gw[d];
    #pragma unroll
    for (int o = 16; o; o >>= 1) s += __shfl_xor_sync(0xffffffffu, s, o);
    if (lane == 0) g_G[warp] = 1.0f / (1.0f + __expf(-(s + gb[0])));
}

// ---------------- launch ----------------
extern "C" void kernel_launch(void* const* d_in, const int* in_sizes, int n_in,
                              void* d_out, int out_size)
{
    const float* query   = (const float*)d_in[0];
    const float* key     = (const float*)d_in[1];
    const float* value   = (const float*)d_in[2];
    const float* wq_w    = (const float*)d_in[3];
    const float* wq_b    = (const float*)d_in[4];
    const float* wk_w    = (const float*)d_in[5];
    const float* wk_b    = (const float*)d_in[6];
    const float* wv_w    = (const float*)d_in[7];
    const float* wv_b    = (const float*)d_in[8];
    const float* dense_w = (const float*)d_in[9];
    const float* dense_b = (const float*)d_in[10];
    const float* gate_w  = (const float*)d_in[11];
    const float* gate_b  = (const float*)d_in[12];
    const float* mp_wq_w = (const float*)d_in[13];
    const float* mp_wq_b = (const float*)d_in[14];
    const float* mp_wk_w = (const float*)d_in[15];
    const float* mp_wk_b = (const float*)d_in[16];

    float* out   = (float*)d_out;
    float* m_out = out + (size_t)Bsz * Lsz * Dsz;

    void *pQbf, *pKbf;
    float *pV, *pQP, *pKP, *pCTX, *pW;
    cudaGetSymbolAddress(&pQbf, g_Qbf);
    cudaGetSymbolAddress(&pKbf, g_Kbf);
    cudaGetSymbolAddress((void**)&pV,   g_V);
    cudaGetSymbolAddress((void**)&pQP,  g_QP);
    cudaGetSymbolAddress((void**)&pKP,  g_KP);
    cudaGetSymbolAddress((void**)&pCTX, g_CTX);
    cudaGetSymbolAddress((void**)&pW,   g_W);

    static int attr_set = 0;
    if (!attr_set) {
        cudaFuncSetAttribute(proj_gemm_kernel<true>,
                             cudaFuncAttributeMaxDynamicSharedMemorySize, PROJ_SMEM);
        cudaFuncSetAttribute(proj_gemm_kernel<false>,
                             cudaFuncAttributeMaxDynamicSharedMemorySize, PROJ_SMEM);
        cudaFuncSetAttribute(ms_gemm_kernel,
                             cudaFuncAttributeMaxDynamicSharedMemorySize, NTG_SMEM);
        cudaFuncSetAttribute(ctx_fused_kernel,
                             cudaFuncAttributeMaxDynamicSharedMemorySize, CTXF_SMEM);
        attr_set = 1;
    }

    dim3 t256(256);

    WSrc ws;
    ws.p[0] = wq_w; ws.p[1] = wk_w; ws.p[2] = wv_w;
    ws.p[3] = mp_wq_w; ws.p[4] = mp_wk_w; ws.p[5] = dense_w;
    preround_kernel<<<dim3(256, 6), t256>>>(ws);

    gate_kernel<<<(Bsz * Lsz * 32) / 256, t256>>>(query, gate_w, gate_b);

    ProjArgs pa;
    pa.A[0] = query; pa.W[0] = pW + 0*Dsz*Dsz; pa.bias[0] = wq_b;    pa.C[0] = pQbf; pa.mode[0] = 2;
    pa.A[1] = key;   pa.W[1] = pW + 1*Dsz*Dsz; pa.bias[1] = wk_b;    pa.C[1] = pKbf; pa.mode[1] = 2;
    pa.A[2] = value; pa.W[2] = pW + 2*Dsz*Dsz; pa.bias[2] = wv_b;    pa.C[2] = pV;   pa.mode[2] = 1;
    pa.A[3] = query; pa.W[3] = pW + 3*Dsz*Dsz; pa.bias[3] = mp_wq_b; pa.C[3] = pQP;  pa.mode[3] = 1;
    pa.A[4] = key;   pa.W[4] = pW + 4*Dsz*Dsz; pa.bias[4] = mp_wk_b; pa.C[4] = pKP;  pa.mode[4] = 1;
    proj_gemm_kernel<true><<<dim3(4, 32, 5), t256, PROJ_SMEM>>>(pa, Dsz, Dsz);

    ms_gemm_kernel<<<dim3(8, 8, Bsz + Bsz * Hsz), t256, NTG_SMEM>>>(m_out);

    ctx_fused_kernel<<<dim3(1, 8, Bsz * Hsz), t256, CTXF_SMEM>>>();

    ProjArgs da;
    da.A[0] = pCTX; da.W[0] = pW + 5*Dsz*Dsz; da.bias[0] = dense_b; da.C[0] = out; da.mode[0] = 0;
    da.A[1] = da.A[0]; da.W[1] = da.W[0]; da.bias[1] = da.bias[0]; da.C[1] = da.C[0]; da.mode[1] = 0;
    da.A[2] = da.A[0]; da.W[2] = da.W[0]; da.bias[2] = da.bias[0]; da.C[2] = da.C[0]; da.mode[2] = 0;
    da.A[3] = da.A[0]; da.W[3] = da.W[0]; da.bias[3] = da.bias[0]; da.C[3] = da.C[0]; da.mode[3] = 0;
    da.A[4] = da.A[0]; da.W[4] = da.W[0]; da.bias[4] = da.bias[0]; da.C[4] = da.C[0]; da.mode[4] = 0;
    proj_gemm_kernel<false><<<dim3(4, 32, 1), t256, PROJ_SMEM>>>(da, Dsz, Dsz);
}

// round 12
// speedup vs baseline: 1.0916x; 1.0264x over previous
#include <cuda_runtime.h>
#include <cuda_bf16.h>
#include <math.h>

#define Bsz 4
#define Lsz 1024
#define Dsz 512
#define Hsz 8
#define DKsz 64

// ---------------- scratch (static device globals; no allocation) ----------------
__device__ __nv_bfloat16 g_Qbf[Bsz*Lsz*Dsz];   // projected q, bf16 (score path)
__device__ __nv_bfloat16 g_Kbf[Bsz*Lsz*Dsz];   // projected k, bf16
__device__ float g_V[Bsz*Lsz*Dsz];      // tf32-prerounded (vprep reads)
__device__ __nv_bfloat16 g_Vtb[Bsz*Hsz*DKsz*Lsz];  // V transposed [b,h,d,k], bf16
__device__ float g_CS[Bsz*Hsz*DKsz];    // colsum of V per (b,h,d), fp32
__device__ float g_QP[Bsz*Lsz*Dsz];     // tf32-prerounded
__device__ float g_KP[Bsz*Lsz*Dsz];     // tf32-prerounded
__device__ float g_W[6*Dsz*Dsz];        // tf32-prerounded weights
__device__ __nv_bfloat16 g_EMb[Bsz*Lsz*Lsz];              // exp(1-m), bf16
__device__ float g_G[Bsz*Lsz];
__device__ __nv_bfloat16 g_Sb[(size_t)Bsz*Hsz*Lsz*Lsz];   // exp(scores), bf16
__device__ float g_Z[Bsz*Hsz*Lsz];
__device__ float g_CTX[Bsz*Lsz*Dsz];    // tf32-prerounded

// ---------------- helpers ----------------
__device__ __forceinline__ unsigned f2tf(float f) {
    unsigned u;
    asm("cvt.rna.tf32.f32 %0, %1;" : "=r"(u) : "f"(f));
    return u;
}
__device__ __forceinline__ float tf32r(float f) { return __uint_as_float(f2tf(f)); }

__device__ __forceinline__ unsigned packbf2(float lo, float hi) {
    unsigned r;
    asm("cvt.rn.bf16x2.f32 %0, %1, %2;" : "=r"(r) : "f"(hi), "f"(lo));
    return r;
}
__device__ __forceinline__ float2 unpackbf2(unsigned u) {
    __nv_bfloat162 v = *reinterpret_cast<__nv_bfloat162*>(&u);
    return __bfloat1622float2(v);
}

__device__ __forceinline__ void mma_tf32(float c[4], const unsigned a[4], const unsigned b[2]) {
    asm volatile(
        "mma.sync.aligned.m16n8k8.row.col.f32.tf32.tf32.f32 "
        "{%0,%1,%2,%3}, {%4,%5,%6,%7}, {%8,%9}, {%0,%1,%2,%3};"
        : "+f"(c[0]), "+f"(c[1]), "+f"(c[2]), "+f"(c[3])
        : "r"(a[0]), "r"(a[1]), "r"(a[2]), "r"(a[3]), "r"(b[0]), "r"(b[1]));
}

__device__ __forceinline__ void mma_bf16(float c[4], const unsigned a[4], const unsigned b[2]) {
    asm volatile(
        "mma.sync.aligned.m16n8k16.row.col.f32.bf16.bf16.f32 "
        "{%0,%1,%2,%3}, {%4,%5,%6,%7}, {%8,%9}, {%0,%1,%2,%3};"
        : "+f"(c[0]), "+f"(c[1]), "+f"(c[2]), "+f"(c[3])
        : "r"(a[0]), "r"(a[1]), "r"(a[2]), "r"(a[3]), "r"(b[0]), "r"(b[1]));
}

__device__ __forceinline__ void cp_async16(void* smem, const void* gmem) {
    unsigned saddr = (unsigned)__cvta_generic_to_shared(smem);
    asm volatile("cp.async.cg.shared.global [%0], [%1], 16;" :: "r"(saddr), "l"(gmem));
}
__device__ __forceinline__ void cp_commit() { asm volatile("cp.async.commit_group;"); }
template<int N>
__device__ __forceinline__ void cp_wait() { asm volatile("cp.async.wait_group %0;" :: "n"(N)); }

// ---------------- tf32 GEMM core, 4-stage pipeline, prefetch-before-sync ----------------
template<int BM, int BN, bool BT, int MT, int NT, bool ACVT, bool BCVT>
__device__ __forceinline__ void gemm_core(
    const float* __restrict__ A, int lda,
    const float* __restrict__ B, int ldb,
    int K, float (&acc)[MT][NT][4])
{
    constexpr int BK = 16;
    constexpr int APITCH = BK + 4;
    constexpr int BPITCH = BT ? (BK + 4) : (BN + 8);
    constexpr int BROWS  = BT ? BN : BK;

    extern __shared__ float dynsm[];
    float* As = dynsm;
    float* Bs = dynsm + 4 * BM * APITCH;

    const int tid = threadIdx.x;
    const int lane = tid & 31;
    const int wid = tid >> 5;
    const int wm0 = (wid & 3) * (BM / 4);
    const int wn0 = (wid >> 2) * (BN / 2);

    constexpr int ALD = (BM * BK / 4) / 256;
    constexpr int BLD = (BT ? (BN * BK / 4) : (BK * BN / 4)) / 256;

    auto prefetch = [&](int k0, int s) {
        float* Asl = As + s * BM * APITCH;
        float* Bsl = Bs + s * BROWS * BPITCH;
        #pragma unroll
        for (int i = 0; i < ALD; i++) {
            int idx = tid + i * 256;
            int row = idx >> 2, kq = idx & 3;
            cp_async16(&Asl[row * APITCH + kq * 4], A + (size_t)row * lda + k0 + kq * 4);
        }
        #pragma unroll
        for (int i = 0; i < BLD; i++) {
            int idx = tid + i * 256;
            if constexpr (BT) {
                int row = idx >> 2, kq = idx & 3;
                cp_async16(&Bsl[row * BPITCH + kq * 4], B + (size_t)row * ldb + k0 + kq * 4);
            } else {
                int k = idx / (BN / 4), nq = idx % (BN / 4);
                cp_async16(&Bsl[k * BPITCH + nq * 4], B + (size_t)(k0 + k) * ldb + nq * 4);
            }
        }
        cp_commit();
    };

    const int nIter = K / BK;
    prefetch(0, 0);
    if (nIter > 1) prefetch(BK, 1);

    for (int it = 0; it < nIter; it++) {
        if (it + 2 < nIter) { prefetch((it + 2) * BK, (it + 2) & 3); cp_wait<2>(); }
        else if (it + 1 < nIter) { cp_wait<1>(); }
        else { cp_wait<0>(); }
        __syncthreads();

        const int cur = it & 3;
        const float* Asl = As + cur * BM * APITCH;
        const float* Bsl = Bs + cur * BROWS * BPITCH;
        const unsigned* Aslu = (const unsigned*)Asl;
        const unsigned* Bslu = (const unsigned*)Bsl;

        #pragma unroll
        for (int ks = 0; ks < 2; ks++) {
            unsigned af[MT][4];
            unsigned bf[NT][2];
            const int kk = ks * 8 + (lane & 3);
            #pragma unroll
            for (int mt = 0; mt < MT; mt++) {
                int row = wm0 + mt * 16 + (lane >> 2);
                if constexpr (ACVT) {
                    af[mt][0] = f2tf(Asl[row * APITCH + kk]);
                    af[mt][1] = f2tf(Asl[(row + 8) * APITCH + kk]);
                    af[mt][2] = f2tf(Asl[row * APITCH + kk + 4]);
                    af[mt][3] = f2tf(Asl[(row + 8) * APITCH + kk + 4]);
                } else {
                    af[mt][0] = Aslu[row * APITCH + kk];
                    af[mt][1] = Aslu[(row + 8) * APITCH + kk];
                    af[mt][2] = Aslu[row * APITCH + kk + 4];
                    af[mt][3] = Aslu[(row + 8) * APITCH + kk + 4];
                }
            }
            #pragma unroll
            for (int nt = 0; nt < NT; nt++) {
                int n = wn0 + nt * 8 + (lane >> 2);
                if constexpr (BT) {
                    if constexpr (BCVT) {
                        bf[nt][0] = f2tf(Bsl[n * BPITCH + kk]);
                        bf[nt][1] = f2tf(Bsl[n * BPITCH + kk + 4]);
                    } else {
                        bf[nt][0] = Bslu[n * BPITCH + kk];
                        bf[nt][1] = Bslu[n * BPITCH + kk + 4];
                    }
                } else {
                    if constexpr (BCVT) {
                        bf[nt][0] = f2tf(Bsl[kk * BPITCH + n]);
                        bf[nt][1] = f2tf(Bsl[(kk + 4) * BPITCH + n]);
                    } else {
                        bf[nt][0] = Bslu[kk * BPITCH + n];
                        bf[nt][1] = Bslu[(kk + 4) * BPITCH + n];
                    }
                }
            }
            #pragma unroll
            for (int mt = 0; mt < MT; mt++)
                #pragma unroll
                for (int nt = 0; nt < NT; nt++)
                    mma_tf32(acc[mt][nt], af[mt], bf[nt]);
        }
    }
}

// smem byte sizes
#define PROJ_SMEM  ((4*128*20 + 4*16*136) * 4)   // 75776
#define NTG_SMEM   ((4*128*20 * 2) * 4)          // 81920
#define CTX_S_BYTES   (4 * 128 * 24 * 2)         // 24576 (bf16, pitch 24)
#define CTX_E_BYTES   (4 * 128 * 24 * 2)         // 24576
#define CTX_V_BYTES   (4 * 64 * 24 * 2)          // 12288 (Vt bf16, 64 rows pitch 24)
#define CTXF_SMEM  (CTX_S_BYTES + CTX_E_BYTES + CTX_V_BYTES)  // 61440

// ---------------- weight preround ----------------
struct WSrc { const float* p[6]; };

__global__ void preround_kernel(WSrc ws)
{
    const int z = blockIdx.y;
    const float4* src = (const float4*)ws.p[z];
    float4* dst = (float4*)(g_W + z * Dsz * Dsz);
    int idx = blockIdx.x * 256 + threadIdx.x;
    float4 v = src[idx];
    dst[idx] = make_float4(tf32r(v.x), tf32r(v.y), tf32r(v.z), tf32r(v.w));
}

// ---------------- batched projections / dense ----------------
// mode: 0 = plain fp32, 1 = tf32-rounded fp32, 2 = bf16
struct ProjArgs {
    const float* A[5];
    const float* W[5];
    const float* bias[5];
    void* C[5];
    int mode[5];
};

template<bool ACVT>
__global__ void __launch_bounds__(256, 2) proj_gemm_kernel(ProjArgs args, int N, int K)
{
    const int z = blockIdx.z;
    float acc[2][8][4] = {};
    const float* Ab = args.A[z] + (size_t)blockIdx.y * 128 * K;
    const float* Bb = args.W[z] + blockIdx.x * 128;
    gemm_core<128, 128, false, 2, 8, ACVT, false>(Ab, K, Bb, N, K, acc);

    const float* bias = args.bias[z];
    const int mode = args.mode[z];
    int lane = threadIdx.x & 31, wid = threadIdx.x >> 5;
    int rowBase = blockIdx.y * 128 + (wid & 3) * 32 + (lane >> 2);
    int colBase = blockIdx.x * 128 + (wid >> 2) * 64 + 2 * (lane & 3);
    #pragma unroll
    for (int mt = 0; mt < 2; mt++)
        #pragma unroll
        for (int nt = 0; nt < 8; nt++) {
            int row = rowBase + mt * 16;
            int col = colBase + nt * 8;
            float b0 = bias[col], b1 = bias[col + 1];
            float v0 = acc[mt][nt][0] + b0, v1 = acc[mt][nt][1] + b1;
            float v2 = acc[mt][nt][2] + b0, v3 = acc[mt][nt][3] + b1;
            if (mode == 2) {
                __nv_bfloat16* Cb = (__nv_bfloat16*)args.C[z];
                *(__nv_bfloat162*)&Cb[(size_t)row * N + col] =
                    __float22bfloat162_rn(make_float2(v0, v1));
                *(__nv_bfloat162*)&Cb[(size_t)(row + 8) * N + col] =
                    __float22bfloat162_rn(make_float2(v2, v3));
            } else {
                if (mode == 1) {
                    v0 = tf32r(v0); v1 = tf32r(v1); v2 = tf32r(v2); v3 = tf32r(v3);
                }
                float* C = (float*)args.C[z];
                *(float2*)&C[(size_t)row * N + col]       = make_float2(v0, v1);
                *(float2*)&C[(size_t)(row + 8) * N + col] = make_float2(v2, v3);
            }
        }
}

// ---------------- V prep: transpose to bf16 [b,h,d,k] + fp32 colsum ----------------
__global__ void __launch_bounds__(256) vprep_kernel()
{
    __shared__ __nv_bfloat16 sm[128][72];   // pitch 72 bf16 -> conflict-free transposed reads
    const int b = blockIdx.z, h = blockIdx.y, kt = blockIdx.x;
    const int k0 = kt * 128;
    const int tid = threadIdx.x;

    // load 128 rows x 64 cols (this head's slice), accumulate column partial sums
    const int d = tid & 63, rg = tid >> 6;
    float psum = 0.f;
    #pragma unroll
    for (int j = 0; j < 32; j++) {
        int row = rg + 4 * j;
        float v = g_V[((size_t)(b * Lsz + k0 + row)) * Dsz + h * DKsz + d];
        psum += v;
        sm[row][d] = __float2bfloat16(v);
    }
    atomicAdd(&g_CS[(b * Hsz + h) * DKsz + d], psum);
    __syncthreads();

    // write out transposed: row d2, k-chunks of 32 (16B-vectorized)
    const int d2 = tid >> 2, c = tid & 3;
    __nv_bfloat16* dst = g_Vtb + ((size_t)((b * Hsz + h) * DKsz + d2)) * Lsz + k0 + c * 32;
    #pragma unroll
    for (int q = 0; q < 4; q++) {
        __nv_bfloat16 tmp[8];
        #pragma unroll
        for (int e = 0; e < 8; e++) tmp[e] = sm[c * 32 + q * 8 + e][d2];
        *(uint4*)(dst + q * 8) = *(uint4*)tmp;
    }
}

// ---------------- merged m + score launch (unchanged from R11) ----------------
__global__ void __launch_bounds__(256, 2) ms_gemm_kernel(float* __restrict__ m_out)
{
    const int zz = blockIdx.z;
    int lane = threadIdx.x & 31, wid = threadIdx.x >> 5;
    int fcol = lane & 3;

    if (zz < Bsz) {
        const float SCALE = 0.04419417382415922f; // 1/sqrt(512)
        const int zb = zz;
        float acc[2][8][4] = {};
        const float* Ab = g_QP + (size_t)zb * Lsz * Dsz + (size_t)blockIdx.y * 128 * Dsz;
        const float* Bb = g_KP + (size_t)zb * Lsz * Dsz + (size_t)blockIdx.x * 128 * Dsz;
        gemm_core<128, 128, true, 2, 8, false, false>(Ab, Dsz, Bb, Dsz, Dsz, acc);

        float* Mo = m_out + (size_t)zb * Lsz * Lsz;
        __nv_bfloat16* Eo = g_EMb + (size_t)zb * Lsz * Lsz;
        int rowBase = blockIdx.y * 128 + (wid & 3) * 32 + (lane >> 2);
        int colBase = blockIdx.x * 128 + (wid >> 2) * 64 + 2 * fcol;
        #pragma unroll
        for (int mt = 0; mt < 2; mt++)
            #pragma unroll
            for (int nt = 0; nt < 8; nt++) {
                int row = rowBase + mt * 16;
                int col = colBase + nt * 8;
                #pragma unroll
                for (int h = 0; h < 2; h++) {
                    int r = row + h * 8;
                    float s0 = 1.0f / (1.0f + __expf(-acc[mt][nt][2*h] * SCALE));
                    float s1 = 1.0f / (1.0f + __expf(-acc[mt][nt][2*h+1] * SCALE));
                    *(float2*)&Mo[(size_t)r * Lsz + col] = make_float2(s0, s1);
                    *(__nv_bfloat162*)&Eo[(size_t)r * Lsz + col] =
                        __float22bfloat162_rn(make_float2(__expf(1.0f - s0), __expf(1.0f - s1)));
                }
            }
    } else {
        const float SCALE = 0.125f;
        const int z = zz - Bsz;
        const int b = z >> 3, h = z & 7;
        const __nv_bfloat16* Ab = g_Qbf + ((size_t)b * Lsz + blockIdx.y * 128) * Dsz + h * DKsz;
        const __nv_bfloat16* Bb = g_Kbf + ((size_t)b * Lsz + blockIdx.x * 128) * Dsz + h * DKsz;

        extern __shared__ float dynsm[];
        __nv_bfloat16* Qs = (__nv_bfloat16*)dynsm;        // 128 x 88 bf16
        __nv_bfloat16* Ks = Qs + 128 * 88;
        const unsigned* Qw = (const unsigned*)Qs;          // word pitch 44
        const unsigned* Kw = (const unsigned*)Ks;
        const int tid = threadIdx.x;

        #pragma unroll
        for (int i = 0; i < 4; i++) {
            int idx = tid + i * 256;
            int row = idx >> 3, ch = idx & 7;
            cp_async16(&Qs[row * 88 + ch * 8], Ab + (size_t)row * Dsz + ch * 8);
        }
        #pragma unroll
        for (int i = 0; i < 4; i++) {
            int idx = tid + i * 256;
            int row = idx >> 3, ch = idx & 7;
            cp_async16(&Ks[row * 88 + ch * 8], Bb + (size_t)row * Dsz + ch * 8);
        }
        cp_commit();
        cp_wait<0>();
        __syncthreads();

        const int wm0 = (wid & 3) * 32;
        const int wn0 = (wid >> 2) * 64;
        const int frow = lane >> 2;
        float acc[2][8][4] = {};

        #pragma unroll
        for (int ks = 0; ks < 4; ks++) {
            const int kw = ks * 8 + fcol;
            unsigned af[2][4];
            #pragma unroll
            for (int mt = 0; mt < 2; mt++) {
                int row = wm0 + mt * 16 + frow;
                af[mt][0] = Qw[row * 44 + kw];
                af[mt][1] = Qw[(row + 8) * 44 + kw];
                af[mt][2] = Qw[row * 44 + kw + 4];
                af[mt][3] = Qw[(row + 8) * 44 + kw + 4];
            }
            #pragma unroll
            for (int nt = 0; nt < 8; nt++) {
                int n = wn0 + nt * 8 + frow;
                unsigned bf[2] = { Kw[n * 44 + kw], Kw[n * 44 + kw + 4] };
                #pragma unroll
                for (int mt = 0; mt < 2; mt++)
                    mma_bf16(acc[mt][nt], af[mt], bf);
            }
        }

        __nv_bfloat16* Cp = g_Sb + (size_t)z * Lsz * Lsz;
        int rowBase = blockIdx.y * 128 + wm0 + frow;
        int colBase = blockIdx.x * 128 + wn0 + 2 * fcol;

        float rs[2][2] = {};
        #pragma unroll
        for (int mt = 0; mt < 2; mt++)
            #pragma unroll
            for (int nt = 0; nt < 8; nt++) {
                int row = rowBase + mt * 16;
                int col = colBase + nt * 8;
                float p0 = __expf(acc[mt][nt][0] * SCALE);
                float p1 = __expf(acc[mt][nt][1] * SCALE);
                float p2 = __expf(acc[mt][nt][2] * SCALE);
                float p3 = __expf(acc[mt][nt][3] * SCALE);
                *(__nv_bfloat162*)&Cp[(size_t)row * Lsz + col] =
                    __float22bfloat162_rn(make_float2(p0, p1));
                *(__nv_bfloat162*)&Cp[(size_t)(row + 8) * Lsz + col] =
                    __float22bfloat162_rn(make_float2(p2, p3));
                rs[mt][0] += p0 + p1;
                rs[mt][1] += p2 + p3;
            }

        #pragma unroll
        for (int mt = 0; mt < 2; mt++)
            #pragma unroll
            for (int hh = 0; hh < 2; hh++) {
                float v = rs[mt][hh];
                v += __shfl_xor_sync(0xffffffffu, v, 1);
                v += __shfl_xor_sync(0xffffffffu, v, 2);
                if (fcol == 0)
                    atomicAdd(&g_Z[(size_t)z * Lsz + rowBase + mt * 16 + hh * 8], v);
            }
    }
}

// ---------------- fused calibrate + ctx GEMM v4: Σ-decomposition ----------------
// attn = e2/Z2 with e2 = 1 + y, y = x + x^2/2 (x = p*invZ*w, |x|<=~0.012).
// CTX = (colsumV + Y@V) / (1024 + Σy). colsumV fp32-exact (97% of magnitude);
// Y@V in bf16 m16n8k16 (error 0.4% of a 0.3% term -> ~1e-5 on output).
__global__ void __launch_bounds__(256, 2) ctx_fused_kernel()
{
    extern __shared__ char smc[];
    __nv_bfloat16* Ss = (__nv_bfloat16*)smc;                    // 4 x 128 x 24
    __nv_bfloat16* Es = (__nv_bfloat16*)(smc + CTX_S_BYTES);    // 4 x 128 x 24
    __nv_bfloat16* Vs = (__nv_bfloat16*)(smc + CTX_S_BYTES + CTX_E_BYTES); // 4 x 64 x 24

    const int tid = threadIdx.x;
    const int lane = tid & 31;
    const int wid = tid >> 5;
    const int z = blockIdx.z;
    const int b = z >> 3, h = z & 7;
    const int q0 = blockIdx.y * 128;

    const __nv_bfloat16* Sg = g_Sb + (size_t)z * Lsz * Lsz + (size_t)q0 * Lsz;
    const __nv_bfloat16* Eg = g_EMb + (size_t)b * Lsz * Lsz + (size_t)q0 * Lsz;
    const __nv_bfloat16* Vtg = g_Vtb + (size_t)z * DKsz * Lsz;

    const int wm = wid * 16;
    const int frow = lane >> 2, fcol = lane & 3;
    const int r0 = wm + frow, r1 = r0 + 8;

    const float g0 = g_G[b * Lsz + q0 + r0];
    const float g1 = g_G[b * Lsz + q0 + r1];
    const float iz0 = 1.0f / g_Z[(size_t)z * Lsz + q0 + r0];
    const float iz1 = 1.0f / g_Z[(size_t)z * Lsz + q0 + r1];
    const float ga0 = g0 * iz0, gc0 = (1.0f - g0) * iz0;
    const float ga1 = g1 * iz1, gc1 = (1.0f - g1) * iz1;
    float z2a = 0.f, z2b = 0.f;

    auto prefetch = [&](int it, int s) {
        const int k0 = it * 16;
        __nv_bfloat16* Sl = Ss + s * 128 * 24;
        __nv_bfloat16* El = Es + s * 128 * 24;
        __nv_bfloat16* Vl = Vs + s * 64 * 24;
        {
            int row = tid >> 1, ch = tid & 1;
            cp_async16(&Sl[row * 24 + ch * 8], Sg + (size_t)row * Lsz + k0 + ch * 8);
            cp_async16(&El[row * 24 + ch * 8], Eg + (size_t)row * Lsz + k0 + ch * 8);
        }
        if (tid < 128) {
            int d = tid >> 1, half = tid & 1;
            cp_async16(&Vl[d * 24 + half * 8], Vtg + (size_t)d * Lsz + k0 + half * 8);
        }
        cp_commit();
    };

    float acc[8][4] = {};
    const int nIter = Lsz / 16;   // 64
    prefetch(0, 0);
    prefetch(1, 1);

    for (int it = 0; it < nIter; it++) {
        if (it + 2 < nIter) { prefetch(it + 2, (it + 2) & 3); cp_wait<2>(); }
        else if (it + 1 < nIter) { cp_wait<1>(); }
        else { cp_wait<0>(); }
        __syncthreads();

        const int cur = it & 3;
        const unsigned* Sw = (const unsigned*)(Ss + cur * 128 * 24);  // word pitch 12
        const unsigned* Ew = (const unsigned*)(Es + cur * 128 * 24);
        const unsigned* Vw = (const unsigned*)(Vs + cur * 64 * 24);

        // this lane's A-fragment elements: rows r0,r1 x k-pairs (2fcol, 8+2fcol)
        float2 p00 = unpackbf2(Sw[r0 * 12 + fcol]);
        float2 p01 = unpackbf2(Sw[r0 * 12 + fcol + 4]);
        float2 p10 = unpackbf2(Sw[r1 * 12 + fcol]);
        float2 p11 = unpackbf2(Sw[r1 * 12 + fcol + 4]);
        float2 e00 = unpackbf2(Ew[r0 * 12 + fcol]);
        float2 e01 = unpackbf2(Ew[r0 * 12 + fcol + 4]);
        float2 e10 = unpackbf2(Ew[r1 * 12 + fcol]);
        float2 e11 = unpackbf2(Ew[r1 * 12 + fcol + 4]);

        // y = x*(1 + x/2), x = p*(ga + gc*em)
        float x0 = p00.x * fmaf(gc0, e00.x, ga0);
        float x1 = p00.y * fmaf(gc0, e00.y, ga0);
        float x2 = p01.x * fmaf(gc0, e01.x, ga0);
        float x3 = p01.y * fmaf(gc0, e01.y, ga0);
        float x4 = p10.x * fmaf(gc1, e10.x, ga1);
        float x5 = p10.y * fmaf(gc1, e10.y, ga1);
        float x6 = p11.x * fmaf(gc1, e11.x, ga1);
        float x7 = p11.y * fmaf(gc1, e11.y, ga1);

        float y0 = x0 * fmaf(x0, 0.5f, 1.0f);
        float y1 = x1 * fmaf(x1, 0.5f, 1.0f);
        float y2 = x2 * fmaf(x2, 0.5f, 1.0f);
        float y3 = x3 * fmaf(x3, 0.5f, 1.0f);
        float y4 = x4 * fmaf(x4, 0.5f, 1.0f);
        float y5 = x5 * fmaf(x5, 0.5f, 1.0f);
        float y6 = x6 * fmaf(x6, 0.5f, 1.0f);
        float y7 = x7 * fmaf(x7, 0.5f, 1.0f);

        z2a += (y0 + y1) + (y2 + y3);
        z2b += (y4 + y5) + (y6 + y7);

        unsigned af[4];
        af[0] = packbf2(y0, y1);   // (r0, k 2fcol..)
        af[1] = packbf2(y4, y5);   // (r1, k 2fcol..)
        af[2] = packbf2(y2, y3);   // (r0, k 8+2fcol..)
        af[3] = packbf2(y6, y7);   // (r1, k 8+2fcol..)

        #pragma unroll
        for (int nt = 0; nt < 8; nt++) {
            const int n = nt * 8 + frow;
            unsigned bf[2] = { Vw[n * 12 + fcol], Vw[n * 12 + fcol + 4] };
            mma_bf16(acc[nt], af, bf);
        }
    }

    z2a += __shfl_xor_sync(0xffffffffu, z2a, 1);
    z2a += __shfl_xor_sync(0xffffffffu, z2a, 2);
    z2b += __shfl_xor_sync(0xffffffffu, z2b, 1);
    z2b += __shfl_xor_sync(0xffffffffu, z2b, 2);
    const float iza = 1.0f / (1024.0f + z2a);
    const float izb = 1.0f / (1024.0f + z2b);

    float* Cp = g_CTX + (size_t)b * Lsz * Dsz + (size_t)q0 * Dsz + h * DKsz;
    const float* CSp = g_CS + z * DKsz;
    #pragma unroll
    for (int nt = 0; nt < 8; nt++) {
        const int col = nt * 8 + 2 * fcol;
        float cs0 = CSp[col], cs1 = CSp[col + 1];
        *(float2*)&Cp[(size_t)r0 * Dsz + col] =
            make_float2(tf32r((cs0 + acc[nt][0]) * iza), tf32r((cs1 + acc[nt][1]) * iza));
        *(float2*)&Cp[(size_t)r1 * Dsz + col] =
            make_float2(tf32r((cs0 + acc[nt][2]) * izb), tf32r((cs1 + acc[nt][3]) * izb));
    }
}

// ---------------- gate (+ zero g_Z and g_CS) ----------------
__global__ void gate_kernel(const float* __restrict__ query,
                            const float* __restrict__ gw,
                            const float* __restrict__ gb)
{
    int gidx = blockIdx.x * blockDim.x + threadIdx.x;
    if (gidx < Bsz * Hsz * Lsz) g_Z[gidx] = 0.f;
    if (gidx < Bsz * Hsz * DKsz) g_CS[gidx] = 0.f;

    int warp = gidx >> 5;
    int lane = threadIdx.x & 31;
    if (warp >= Bsz * Lsz) return;
    const float* row = query + (size_t)warp * Dsz;
    float s = 0.f;
    for (int d = lane; d < Dsz; d += 32) s += row[d] * gw[d];
    #pragma unroll
    for (int o = 16; o; o >>= 1) s += __shfl_xor_sync(0xffffffffu, s, o);
    if (lane == 0) g_G[warp] = 1.0f / (1.0f + __expf(-(s + gb[0])));
}

// ---------------- launch ----------------
extern "C" void kernel_launch(void* const* d_in, const int* in_sizes, int n_in,
                              void* d_out, int out_size)
{
    const float* query   = (const float*)d_in[0];
    const float* key     = (const float*)d_in[1];
    const float* value   = (const float*)d_in[2];
    const float* wq_w    = (const float*)d_in[3];
    const float* wq_b    = (const float*)d_in[4];
    const float* wk_w    = (const float*)d_in[5];
    const float* wk_b    = (const float*)d_in[6];
    const float* wv_w    = (const float*)d_in[7];
    const float* wv_b    = (const float*)d_in[8];
    const float* dense_w = (const float*)d_in[9];
    const float* dense_b = (const float*)d_in[10];
    const float* gate_w  = (const float*)d_in[11];
    const float* gate_b  = (const float*)d_in[12];
    const float* mp_wq_w = (const float*)d_in[13];
    const float* mp_wq_b = (const float*)d_in[14];
    const float* mp_wk_w = (const float*)d_in[15];
    const float* mp_wk_b = (const float*)d_in[16];

    float* out   = (float*)d_out;
    float* m_out = out + (size_t)Bsz * Lsz * Dsz;

    void *pQbf, *pKbf;
    float *pV, *pQP, *pKP, *pCTX, *pW;
    cudaGetSymbolAddress(&pQbf, g_Qbf);
    cudaGetSymbolAddress(&pKbf, g_Kbf);
    cudaGetSymbolAddress((void**)&pV,   g_V);
    cudaGetSymbolAddress((void**)&pQP,  g_QP);
    cudaGetSymbolAddress((void**)&pKP,  g_KP);
    cudaGetSymbolAddress((void**)&pCTX, g_CTX);
    cudaGetSymbolAddress((void**)&pW,   g_W);

    static int attr_set = 0;
    if (!attr_set) {
        cudaFuncSetAttribute(proj_gemm_kernel<true>,
                             cudaFuncAttributeMaxDynamicSharedMemorySize, PROJ_SMEM);
        cudaFuncSetAttribute(proj_gemm_kernel<false>,
                             cudaFuncAttributeMaxDynamicSharedMemorySize, PROJ_SMEM);
        cudaFuncSetAttribute(ms_gemm_kernel,
                             cudaFuncAttributeMaxDynamicSharedMemorySize, NTG_SMEM);
        cudaFuncSetAttribute(ctx_fused_kernel,
                             cudaFuncAttributeMaxDynamicSharedMemorySize, CTXF_SMEM);
        attr_set = 1;
    }

    dim3 t256(256);

    WSrc ws;
    ws.p[0] = wq_w; ws.p[1] = wk_w; ws.p[2] = wv_w;
    ws.p[3] = mp_wq_w; ws.p[4] = mp_wk_w; ws.p[5] = dense_w;
    preround_kernel<<<dim3(256, 6), t256>>>(ws);

    gate_kernel<<<(Bsz * Lsz * 32) / 256, t256>>>(query, gate_w, gate_b);

    ProjArgs pa;
    pa.A[0] = query; pa.W[0] = pW + 0*Dsz*Dsz; pa.bias[0] = wq_b;    pa.C[0] = pQbf; pa.mode[0] = 2;
    pa.A[1] = key;   pa.W[1] = pW + 1*Dsz*Dsz; pa.bias[1] = wk_b;    pa.C[1] = pKbf; pa.mode[1] = 2;
    pa.A[2] = value; pa.W[2] = pW + 2*Dsz*Dsz; pa.bias[2] = wv_b;    pa.C[2] = pV;   pa.mode[2] = 1;
    pa.A[3] = query; pa.W[3] = pW + 3*Dsz*Dsz; pa.bias[3] = mp_wq_b; pa.C[3] = pQP;  pa.mode[3] = 1;
    pa.A[4] = key;   pa.W[4] = pW + 4*Dsz*Dsz; pa.bias[4] = mp_wk_b; pa.C[4] = pKP;  pa.mode[4] = 1;
    proj_gemm_kernel<true><<<dim3(4, 32, 5), t256, PROJ_SMEM>>>(pa, Dsz, Dsz);

    // V transpose + colsum (needs g_V from proj)
    vprep_kernel<<<dim3(8, Hsz, Bsz), t256>>>();

    ms_gemm_kernel<<<dim3(8, 8, Bsz + Bsz * Hsz), t256, NTG_SMEM>>>(m_out);

    ctx_fused_kernel<<<dim3(1, 8, Bsz * Hsz), t256, CTXF_SMEM>>>();

    ProjArgs da;
    da.A[0] = pCTX; da.W[0] = pW + 5*Dsz*Dsz; da.bias[0] = dense_b; da.C[0] = out; da.mode[0] = 0;
    da.A[1] = da.A[0]; da.W[1] = da.W[0]; da.bias[1] = da.bias[0]; da.C[1] = da.C[0]; da.mode[1] = 0;
    da.A[2] = da.A[0]; da.W[2] = da.W[0]; da.bias[2] = da.bias[0]; da.C[2] = da.C[0]; da.mode[2] = 0;
    da.A[3] = da.A[0]; da.W[3] = da.W[0]; da.bias[3] = da.bias[0]; da.C[3] = da.C[0]; da.mode[3] = 0;
    da.A[4] = da.A[0]; da.W[4] = da.W[0]; da.bias[4] = da.bias[0]; da.C[4] = da.C[0]; da.mode[4] = 0;
    proj_gemm_kernel<false><<<dim3(4, 32, 1), t256, PROJ_SMEM>>>(da, Dsz, Dsz);
}

// round 13
// speedup vs baseline: 1.1608x; 1.0634x over previous
#include <cuda_runtime.h>
#include <cuda_bf16.h>
#include <math.h>

#define Bsz 4
#define Lsz 1024
#define Dsz 512
#define Hsz 8
#define DKsz 64

// ---------------- scratch (static device globals; no allocation) ----------------
__device__ __nv_bfloat16 g_Qbf[Bsz*Lsz*Dsz];   // projected q, bf16 (score path)
__device__ __nv_bfloat16 g_Kbf[Bsz*Lsz*Dsz];   // projected k, bf16
__device__ float g_V[Bsz*Lsz*Dsz];      // tf32-prerounded (vprep reads)
__device__ __nv_bfloat16 g_Vtb[Bsz*Hsz*DKsz*Lsz];  // V transposed [b,h,d,k], bf16
__device__ float g_CS[Bsz*Hsz*DKsz];    // colsum of V per (b,h,d), fp32
__device__ __nv_bfloat16 g_QPb[Bsz*Lsz*Dsz];   // mask-perturb q proj, bf16
__device__ __nv_bfloat16 g_KPb[Bsz*Lsz*Dsz];   // mask-perturb k proj, bf16
__device__ float g_W[6*Dsz*Dsz];        // tf32-prerounded weights
__device__ __nv_bfloat16 g_EMb[Bsz*Lsz*Lsz];              // exp(1-m), bf16
__device__ float g_G[Bsz*Lsz];
__device__ __nv_bfloat16 g_Sb[(size_t)Bsz*Hsz*Lsz*Lsz];   // exp(scores), bf16
__device__ float g_Z[Bsz*Hsz*Lsz];
__device__ float g_CTX[Bsz*Lsz*Dsz];    // tf32-prerounded

// ---------------- helpers ----------------
__device__ __forceinline__ unsigned f2tf(float f) {
    unsigned u;
    asm("cvt.rna.tf32.f32 %0, %1;" : "=r"(u) : "f"(f));
    return u;
}
__device__ __forceinline__ float tf32r(float f) { return __uint_as_float(f2tf(f)); }

__device__ __forceinline__ unsigned packbf2(float lo, float hi) {
    unsigned r;
    asm("cvt.rn.bf16x2.f32 %0, %1, %2;" : "=r"(r) : "f"(hi), "f"(lo));
    return r;
}
__device__ __forceinline__ float2 unpackbf2(unsigned u) {
    __nv_bfloat162 v = *reinterpret_cast<__nv_bfloat162*>(&u);
    return __bfloat1622float2(v);
}

__device__ __forceinline__ void mma_tf32(float c[4], const unsigned a[4], const unsigned b[2]) {
    asm volatile(
        "mma.sync.aligned.m16n8k8.row.col.f32.tf32.tf32.f32 "
        "{%0,%1,%2,%3}, {%4,%5,%6,%7}, {%8,%9}, {%0,%1,%2,%3};"
        : "+f"(c[0]), "+f"(c[1]), "+f"(c[2]), "+f"(c[3])
        : "r"(a[0]), "r"(a[1]), "r"(a[2]), "r"(a[3]), "r"(b[0]), "r"(b[1]));
}

__device__ __forceinline__ void mma_bf16(float c[4], const unsigned a[4], const unsigned b[2]) {
    asm volatile(
        "mma.sync.aligned.m16n8k16.row.col.f32.bf16.bf16.f32 "
        "{%0,%1,%2,%3}, {%4,%5,%6,%7}, {%8,%9}, {%0,%1,%2,%3};"
        : "+f"(c[0]), "+f"(c[1]), "+f"(c[2]), "+f"(c[3])
        : "r"(a[0]), "r"(a[1]), "r"(a[2]), "r"(a[3]), "r"(b[0]), "r"(b[1]));
}

__device__ __forceinline__ void cp_async16(void* smem, const void* gmem) {
    unsigned saddr = (unsigned)__cvta_generic_to_shared(smem);
    asm volatile("cp.async.cg.shared.global [%0], [%1], 16;" :: "r"(saddr), "l"(gmem));
}
__device__ __forceinline__ void cp_commit() { asm volatile("cp.async.commit_group;"); }
template<int N>
__device__ __forceinline__ void cp_wait() { asm volatile("cp.async.wait_group %0;" :: "n"(N)); }

// ---------------- tf32 GEMM core, 4-stage pipeline (proj/dense only now) ----------------
template<int BM, int BN, bool BT, int MT, int NT, bool ACVT, bool BCVT>
__device__ __forceinline__ void gemm_core(
    const float* __restrict__ A, int lda,
    const float* __restrict__ B, int ldb,
    int K, float (&acc)[MT][NT][4])
{
    constexpr int BK = 16;
    constexpr int APITCH = BK + 4;
    constexpr int BPITCH = BT ? (BK + 4) : (BN + 8);
    constexpr int BROWS  = BT ? BN : BK;

    extern __shared__ float dynsm[];
    float* As = dynsm;
    float* Bs = dynsm + 4 * BM * APITCH;

    const int tid = threadIdx.x;
    const int lane = tid & 31;
    const int wid = tid >> 5;
    const int wm0 = (wid & 3) * (BM / 4);
    const int wn0 = (wid >> 2) * (BN / 2);

    constexpr int ALD = (BM * BK / 4) / 256;
    constexpr int BLD = (BT ? (BN * BK / 4) : (BK * BN / 4)) / 256;

    auto prefetch = [&](int k0, int s) {
        float* Asl = As + s * BM * APITCH;
        float* Bsl = Bs + s * BROWS * BPITCH;
        #pragma unroll
        for (int i = 0; i < ALD; i++) {
            int idx = tid + i * 256;
            int row = idx >> 2, kq = idx & 3;
            cp_async16(&Asl[row * APITCH + kq * 4], A + (size_t)row * lda + k0 + kq * 4);
        }
        #pragma unroll
        for (int i = 0; i < BLD; i++) {
            int idx = tid + i * 256;
            if constexpr (BT) {
                int row = idx >> 2, kq = idx & 3;
                cp_async16(&Bsl[row * BPITCH + kq * 4], B + (size_t)row * ldb + k0 + kq * 4);
            } else {
                int k = idx / (BN / 4), nq = idx % (BN / 4);
                cp_async16(&Bsl[k * BPITCH + nq * 4], B + (size_t)(k0 + k) * ldb + nq * 4);
            }
        }
        cp_commit();
    };

    const int nIter = K / BK;
    prefetch(0, 0);
    if (nIter > 1) prefetch(BK, 1);

    for (int it = 0; it < nIter; it++) {
        if (it + 2 < nIter) { prefetch((it + 2) * BK, (it + 2) & 3); cp_wait<2>(); }
        else if (it + 1 < nIter) { cp_wait<1>(); }
        else { cp_wait<0>(); }
        __syncthreads();

        const int cur = it & 3;
        const float* Asl = As + cur * BM * APITCH;
        const float* Bsl = Bs + cur * BROWS * BPITCH;
        const unsigned* Aslu = (const unsigned*)Asl;
        const unsigned* Bslu = (const unsigned*)Bsl;

        #pragma unroll
        for (int ks = 0; ks < 2; ks++) {
            unsigned af[MT][4];
            unsigned bf[NT][2];
            const int kk = ks * 8 + (lane & 3);
            #pragma unroll
            for (int mt = 0; mt < MT; mt++) {
                int row = wm0 + mt * 16 + (lane >> 2);
                if constexpr (ACVT) {
                    af[mt][0] = f2tf(Asl[row * APITCH + kk]);
                    af[mt][1] = f2tf(Asl[(row + 8) * APITCH + kk]);
                    af[mt][2] = f2tf(Asl[row * APITCH + kk + 4]);
                    af[mt][3] = f2tf(Asl[(row + 8) * APITCH + kk + 4]);
                } else {
                    af[mt][0] = Aslu[row * APITCH + kk];
                    af[mt][1] = Aslu[(row + 8) * APITCH + kk];
                    af[mt][2] = Aslu[row * APITCH + kk + 4];
                    af[mt][3] = Aslu[(row + 8) * APITCH + kk + 4];
                }
            }
            #pragma unroll
            for (int nt = 0; nt < NT; nt++) {
                int n = wn0 + nt * 8 + (lane >> 2);
                if constexpr (BT) {
                    if constexpr (BCVT) {
                        bf[nt][0] = f2tf(Bsl[n * BPITCH + kk]);
                        bf[nt][1] = f2tf(Bsl[n * BPITCH + kk + 4]);
                    } else {
                        bf[nt][0] = Bslu[n * BPITCH + kk];
                        bf[nt][1] = Bslu[n * BPITCH + kk + 4];
                    }
                } else {
                    if constexpr (BCVT) {
                        bf[nt][0] = f2tf(Bsl[kk * BPITCH + n]);
                        bf[nt][1] = f2tf(Bsl[(kk + 4) * BPITCH + n]);
                    } else {
                        bf[nt][0] = Bslu[kk * BPITCH + n];
                        bf[nt][1] = Bslu[(kk + 4) * BPITCH + n];
                    }
                }
            }
            #pragma unroll
            for (int mt = 0; mt < MT; mt++)
                #pragma unroll
                for (int nt = 0; nt < NT; nt++)
                    mma_tf32(acc[mt][nt], af[mt], bf[nt]);
        }
    }
}

// smem byte sizes
#define PROJ_SMEM  ((4*128*20 + 4*16*136) * 4)   // 75776
#define NTG_SMEM   (4*128*40*2 * 2)              // 81920 (m-path bf16 4-stage; score uses 45056; vprep 18432)
#define CTX_S_BYTES   (4 * 128 * 24 * 2)
#define CTX_E_BYTES   (4 * 128 * 24 * 2)
#define CTX_V_BYTES   (4 * 64 * 24 * 2)
#define CTXF_SMEM  (CTX_S_BYTES + CTX_E_BYTES + CTX_V_BYTES)  // 61440

// ---------------- weight preround ----------------
struct WSrc { const float* p[6]; };

__global__ void preround_kernel(WSrc ws)
{
    const int z = blockIdx.y;
    const float4* src = (const float4*)ws.p[z];
    float4* dst = (float4*)(g_W + z * Dsz * Dsz);
    int idx = blockIdx.x * 256 + threadIdx.x;
    float4 v = src[idx];
    dst[idx] = make_float4(tf32r(v.x), tf32r(v.y), tf32r(v.z), tf32r(v.w));
}

// ---------------- batched projections / dense ----------------
// mode: 0 = plain fp32, 1 = tf32-rounded fp32, 2 = bf16
struct ProjArgs {
    const float* A[5];
    const float* W[5];
    const float* bias[5];
    void* C[5];
    int mode[5];
};

template<bool ACVT>
__global__ void __launch_bounds__(256, 2) proj_gemm_kernel(ProjArgs args, int N, int K)
{
    const int z = blockIdx.z;
    float acc[2][8][4] = {};
    const float* Ab = args.A[z] + (size_t)blockIdx.y * 128 * K;
    const float* Bb = args.W[z] + blockIdx.x * 128;
    gemm_core<128, 128, false, 2, 8, ACVT, false>(Ab, K, Bb, N, K, acc);

    const float* bias = args.bias[z];
    const int mode = args.mode[z];
    int lane = threadIdx.x & 31, wid = threadIdx.x >> 5;
    int rowBase = blockIdx.y * 128 + (wid & 3) * 32 + (lane >> 2);
    int colBase = blockIdx.x * 128 + (wid >> 2) * 64 + 2 * (lane & 3);
    #pragma unroll
    for (int mt = 0; mt < 2; mt++)
        #pragma unroll
        for (int nt = 0; nt < 8; nt++) {
            int row = rowBase + mt * 16;
            int col = colBase + nt * 8;
            float b0 = bias[col], b1 = bias[col + 1];
            float v0 = acc[mt][nt][0] + b0, v1 = acc[mt][nt][1] + b1;
            float v2 = acc[mt][nt][2] + b0, v3 = acc[mt][nt][3] + b1;
            if (mode == 2) {
                __nv_bfloat16* Cb = (__nv_bfloat16*)args.C[z];
                *(__nv_bfloat162*)&Cb[(size_t)row * N + col] =
                    __float22bfloat162_rn(make_float2(v0, v1));
                *(__nv_bfloat162*)&Cb[(size_t)(row + 8) * N + col] =
                    __float22bfloat162_rn(make_float2(v2, v3));
            } else {
                if (mode == 1) {
                    v0 = tf32r(v0); v1 = tf32r(v1); v2 = tf32r(v2); v3 = tf32r(v3);
                }
                float* C = (float*)args.C[z];
                *(float2*)&C[(size_t)row * N + col]       = make_float2(v0, v1);
                *(float2*)&C[(size_t)(row + 8) * N + col] = make_float2(v2, v3);
            }
        }
}

// ---------------- merged m + score + vprep launch ----------------
// z in [0,4):   m path, bf16 m16n8k16 pipelined K=512 (4-stage, pitch 40 bf16)
// z in [4,36):  score path, bf16 single-shot K=64
// z in [36,40): vprep (V transpose + colsum), b = z-36, kt = blockIdx.x, h = blockIdx.y
__global__ void __launch_bounds__(256, 2) ms_gemm_kernel(float* __restrict__ m_out)
{
    const int zz = blockIdx.z;
    const int tid = threadIdx.x;
    int lane = tid & 31, wid = tid >> 5;
    int fcol = lane & 3;
    extern __shared__ float dynsm[];

    if (zz < Bsz) {
        // ---- m path: bf16 k16, 4-stage pipeline, BK=32 ----
        const float SCALE = 0.04419417382415922f; // 1/sqrt(512)
        const int zb = zz;
        const __nv_bfloat16* Ab = g_QPb + ((size_t)zb * Lsz + blockIdx.y * 128) * Dsz;
        const __nv_bfloat16* Bb = g_KPb + ((size_t)zb * Lsz + blockIdx.x * 128) * Dsz;

        __nv_bfloat16* As = (__nv_bfloat16*)dynsm;     // 4 stages x 128 x 40
        __nv_bfloat16* Bs = As + 4 * 128 * 40;

        auto pre = [&](int it, int s) {
            const int k0 = it * 32;
            __nv_bfloat16* Al = As + s * 128 * 40;
            __nv_bfloat16* Bl = Bs + s * 128 * 40;
            #pragma unroll
            for (int i = 0; i < 2; i++) {
                int idx = tid + i * 256;
                int row = idx >> 2, ch = idx & 3;
                cp_async16(&Al[row * 40 + ch * 8], Ab + (size_t)row * Dsz + k0 + ch * 8);
                cp_async16(&Bl[row * 40 + ch * 8], Bb + (size_t)row * Dsz + k0 + ch * 8);
            }
            cp_commit();
        };

        const int wm0 = (wid & 3) * 32;
        const int wn0 = (wid >> 2) * 64;
        const int frow = lane >> 2;
        float acc[2][8][4] = {};

        const int nIter = Dsz / 32;   // 16
        pre(0, 0);
        pre(1, 1);

        for (int it = 0; it < nIter; it++) {
            if (it + 2 < nIter) { pre(it + 2, (it + 2) & 3); cp_wait<2>(); }
            else if (it + 1 < nIter) { cp_wait<1>(); }
            else { cp_wait<0>(); }
            __syncthreads();

            const int cur = it & 3;
            const unsigned* Aw = (const unsigned*)(As + cur * 128 * 40);  // word pitch 20
            const unsigned* Bw = (const unsigned*)(Bs + cur * 128 * 40);

            #pragma unroll
            for (int ks = 0; ks < 2; ks++) {
                const int kw = ks * 8 + fcol;
                unsigned af[2][4];
                #pragma unroll
                for (int mt = 0; mt < 2; mt++) {
                    int row = wm0 + mt * 16 + frow;
                    af[mt][0] = Aw[row * 20 + kw];
                    af[mt][1] = Aw[(row + 8) * 20 + kw];
                    af[mt][2] = Aw[row * 20 + kw + 4];
                    af[mt][3] = Aw[(row + 8) * 20 + kw + 4];
                }
                #pragma unroll
                for (int nt = 0; nt < 8; nt++) {
                    int n = wn0 + nt * 8 + frow;
                    unsigned bf[2] = { Bw[n * 20 + kw], Bw[n * 20 + kw + 4] };
                    #pragma unroll
                    for (int mt = 0; mt < 2; mt++)
                        mma_bf16(acc[mt][nt], af[mt], bf);
                }
            }
        }

        float* Mo = m_out + (size_t)zb * Lsz * Lsz;
        __nv_bfloat16* Eo = g_EMb + (size_t)zb * Lsz * Lsz;
        int rowBase = blockIdx.y * 128 + wm0 + frow;
        int colBase = blockIdx.x * 128 + wn0 + 2 * fcol;
        #pragma unroll
        for (int mt = 0; mt < 2; mt++)
            #pragma unroll
            for (int nt = 0; nt < 8; nt++) {
                int row = rowBase + mt * 16;
                int col = colBase + nt * 8;
                #pragma unroll
                for (int h = 0; h < 2; h++) {
                    int r = row + h * 8;
                    float s0 = 1.0f / (1.0f + __expf(-acc[mt][nt][2*h] * SCALE));
                    float s1 = 1.0f / (1.0f + __expf(-acc[mt][nt][2*h+1] * SCALE));
                    *(float2*)&Mo[(size_t)r * Lsz + col] = make_float2(s0, s1);
                    *(__nv_bfloat162*)&Eo[(size_t)r * Lsz + col] =
                        __float22bfloat162_rn(make_float2(__expf(1.0f - s0), __expf(1.0f - s1)));
                }
            }
    } else if (zz < Bsz + Bsz * Hsz) {
        // ---- score path: bf16 k16 single-shot K=64 ----
        const float SCALE = 0.125f;
        const int z = zz - Bsz;
        const int b = z >> 3, h = z & 7;
        const __nv_bfloat16* Ab = g_Qbf + ((size_t)b * Lsz + blockIdx.y * 128) * Dsz + h * DKsz;
        const __nv_bfloat16* Bb = g_Kbf + ((size_t)b * Lsz + blockIdx.x * 128) * Dsz + h * DKsz;

        __nv_bfloat16* Qs = (__nv_bfloat16*)dynsm;        // 128 x 88 bf16
        __nv_bfloat16* Ks = Qs + 128 * 88;
        const unsigned* Qw = (const unsigned*)Qs;          // word pitch 44
        const unsigned* Kw = (const unsigned*)Ks;

        #pragma unroll
        for (int i = 0; i < 4; i++) {
            int idx = tid + i * 256;
            int row = idx >> 3, ch = idx & 7;
            cp_async16(&Qs[row * 88 + ch * 8], Ab + (size_t)row * Dsz + ch * 8);
        }
        #pragma unroll
        for (int i = 0; i < 4; i++) {
            int idx = tid + i * 256;
            int row = idx >> 3, ch = idx & 7;
            cp_async16(&Ks[row * 88 + ch * 8], Bb + (size_t)row * Dsz + ch * 8);
        }
        cp_commit();
        cp_wait<0>();
        __syncthreads();

        const int wm0 = (wid & 3) * 32;
        const int wn0 = (wid >> 2) * 64;
        const int frow = lane >> 2;
        float acc[2][8][4] = {};

        #pragma unroll
        for (int ks = 0; ks < 4; ks++) {
            const int kw = ks * 8 + fcol;
            unsigned af[2][4];
            #pragma unroll
            for (int mt = 0; mt < 2; mt++) {
                int row = wm0 + mt * 16 + frow;
                af[mt][0] = Qw[row * 44 + kw];
                af[mt][1] = Qw[(row + 8) * 44 + kw];
                af[mt][2] = Qw[row * 44 + kw + 4];
                af[mt][3] = Qw[(row + 8) * 44 + kw + 4];
            }
            #pragma unroll
            for (int nt = 0; nt < 8; nt++) {
                int n = wn0 + nt * 8 + frow;
                unsigned bf[2] = { Kw[n * 44 + kw], Kw[n * 44 + kw + 4] };
                #pragma unroll
                for (int mt = 0; mt < 2; mt++)
                    mma_bf16(acc[mt][nt], af[mt], bf);
            }
        }

        __nv_bfloat16* Cp = g_Sb + (size_t)z * Lsz * Lsz;
        int rowBase = blockIdx.y * 128 + wm0 + frow;
        int colBase = blockIdx.x * 128 + wn0 + 2 * fcol;

        float rs[2][2] = {};
        #pragma unroll
        for (int mt = 0; mt < 2; mt++)
            #pragma unroll
            for (int nt = 0; nt < 8; nt++) {
                int row = rowBase + mt * 16;
                int col = colBase + nt * 8;
                float p0 = __expf(acc[mt][nt][0] * SCALE);
                float p1 = __expf(acc[mt][nt][1] * SCALE);
                float p2 = __expf(acc[mt][nt][2] * SCALE);
                float p3 = __expf(acc[mt][nt][3] * SCALE);
                *(__nv_bfloat162*)&Cp[(size_t)row * Lsz + col] =
                    __float22bfloat162_rn(make_float2(p0, p1));
                *(__nv_bfloat162*)&Cp[(size_t)(row + 8) * Lsz + col] =
                    __float22bfloat162_rn(make_float2(p2, p3));
                rs[mt][0] += p0 + p1;
                rs[mt][1] += p2 + p3;
            }

        #pragma unroll
        for (int mt = 0; mt < 2; mt++)
            #pragma unroll
            for (int hh = 0; hh < 2; hh++) {
                float v = rs[mt][hh];
                v += __shfl_xor_sync(0xffffffffu, v, 1);
                v += __shfl_xor_sync(0xffffffffu, v, 2);
                if (fcol == 0)
                    atomicAdd(&g_Z[(size_t)z * Lsz + rowBase + mt * 16 + hh * 8], v);
            }
    } else {
        // ---- vprep: V transpose to bf16 [b,h,d,k] + fp32 colsum ----
        __nv_bfloat16 (*sm)[72] = (__nv_bfloat16(*)[72])dynsm;   // 128 x 72
        const int b = zz - (Bsz + Bsz * Hsz);
        const int h = blockIdx.y, kt = blockIdx.x;
        const int k0 = kt * 128;

        const int d = tid & 63, rg = tid >> 6;
        float psum = 0.f;
        #pragma unroll
        for (int j = 0; j < 32; j++) {
            int row = rg + 4 * j;
            float v = g_V[((size_t)(b * Lsz + k0 + row)) * Dsz + h * DKsz + d];
            psum += v;
            sm[row][d] = __float2bfloat16(v);
        }
        atomicAdd(&g_CS[(b * Hsz + h) * DKsz + d], psum);
        __syncthreads();

        const int d2 = tid >> 2, c = tid & 3;
        __nv_bfloat16* dst = g_Vtb + ((size_t)((b * Hsz + h) * DKsz + d2)) * Lsz + k0 + c * 32;
        #pragma unroll
        for (int q = 0; q < 4; q++) {
            __nv_bfloat16 tmp[8];
            #pragma unroll
            for (int e = 0; e < 8; e++) tmp[e] = sm[c * 32 + q * 8 + e][d2];
            *(uint4*)(dst + q * 8) = *(uint4*)tmp;
        }
    }
}

// ---------------- fused calibrate + ctx GEMM (Σ-decomposition, bf16 correction) ----------------
__global__ void __launch_bounds__(256, 2) ctx_fused_kernel()
{
    extern __shared__ char smc[];
    __nv_bfloat16* Ss = (__nv_bfloat16*)smc;
    __nv_bfloat16* Es = (__nv_bfloat16*)(smc + CTX_S_BYTES);
    __nv_bfloat16* Vs = (__nv_bfloat16*)(smc + CTX_S_BYTES + CTX_E_BYTES);

    const int tid = threadIdx.x;
    const int lane = tid & 31;
    const int wid = tid >> 5;
    const int z = blockIdx.z;
    const int b = z >> 3, h = z & 7;
    const int q0 = blockIdx.y * 128;

    const __nv_bfloat16* Sg = g_Sb + (size_t)z * Lsz * Lsz + (size_t)q0 * Lsz;
    const __nv_bfloat16* Eg = g_EMb + (size_t)b * Lsz * Lsz + (size_t)q0 * Lsz;
    const __nv_bfloat16* Vtg = g_Vtb + (size_t)z * DKsz * Lsz;

    const int wm = wid * 16;
    const int frow = lane >> 2, fcol = lane & 3;
    const int r0 = wm + frow, r1 = r0 + 8;

    const float g0 = g_G[b * Lsz + q0 + r0];
    const float g1 = g_G[b * Lsz + q0 + r1];
    const float iz0 = 1.0f / g_Z[(size_t)z * Lsz + q0 + r0];
    const float iz1 = 1.0f / g_Z[(size_t)z * Lsz + q0 + r1];
    const float ga0 = g0 * iz0, gc0 = (1.0f - g0) * iz0;
    const float ga1 = g1 * iz1, gc1 = (1.0f - g1) * iz1;
    float z2a = 0.f, z2b = 0.f;

    auto prefetch = [&](int it, int s) {
        const int k0 = it * 16;
        __nv_bfloat16* Sl = Ss + s * 128 * 24;
        __nv_bfloat16* El = Es + s * 128 * 24;
        __nv_bfloat16* Vl = Vs + s * 64 * 24;
        {
            int row = tid >> 1, ch = tid & 1;
            cp_async16(&Sl[row * 24 + ch * 8], Sg + (size_t)row * Lsz + k0 + ch * 8);
            cp_async16(&El[row * 24 + ch * 8], Eg + (size_t)row * Lsz + k0 + ch * 8);
        }
        if (tid < 128) {
            int d = tid >> 1, half = tid & 1;
            cp_async16(&Vl[d * 24 + half * 8], Vtg + (size_t)d * Lsz + k0 + half * 8);
        }
        cp_commit();
    };

    float acc[8][4] = {};
    const int nIter = Lsz / 16;
    prefetch(0, 0);
    prefetch(1, 1);

    for (int it = 0; it < nIter; it++) {
        if (it + 2 < nIter) { prefetch(it + 2, (it + 2) & 3); cp_wait<2>(); }
        else if (it + 1 < nIter) { cp_wait<1>(); }
        else { cp_wait<0>(); }
        __syncthreads();

        const int cur = it & 3;
        const unsigned* Sw = (const unsigned*)(Ss + cur * 128 * 24);
        const unsigned* Ew = (const unsigned*)(Es + cur * 128 * 24);
        const unsigned* Vw = (const unsigned*)(Vs + cur * 64 * 24);

        float2 p00 = unpackbf2(Sw[r0 * 12 + fcol]);
        float2 p01 = unpackbf2(Sw[r0 * 12 + fcol + 4]);
        float2 p10 = unpackbf2(Sw[r1 * 12 + fcol]);
        float2 p11 = unpackbf2(Sw[r1 * 12 + fcol + 4]);
        float2 e00 = unpackbf2(Ew[r0 * 12 + fcol]);
        float2 e01 = unpackbf2(Ew[r0 * 12 + fcol + 4]);
        float2 e10 = unpackbf2(Ew[r1 * 12 + fcol]);
        float2 e11 = unpackbf2(Ew[r1 * 12 + fcol + 4]);

        float x0 = p00.x * fmaf(gc0, e00.x, ga0);
        float x1 = p00.y * fmaf(gc0, e00.y, ga0);
        float x2 = p01.x * fmaf(gc0, e01.x, ga0);
        float x3 = p01.y * fmaf(gc0, e01.y, ga0);
        float x4 = p10.x * fmaf(gc1, e10.x, ga1);
        float x5 = p10.y * fmaf(gc1, e10.y, ga1);
        float x6 = p11.x * fmaf(gc1, e11.x, ga1);
        float x7 = p11.y * fmaf(gc1, e11.y, ga1);

        float y0 = x0 * fmaf(x0, 0.5f, 1.0f);
        float y1 = x1 * fmaf(x1, 0.5f, 1.0f);
        float y2 = x2 * fmaf(x2, 0.5f, 1.0f);
        float y3 = x3 * fmaf(x3, 0.5f, 1.0f);
        float y4 = x4 * fmaf(x4, 0.5f, 1.0f);
        float y5 = x5 * fmaf(x5, 0.5f, 1.0f);
        float y6 = x6 * fmaf(x6, 0.5f, 1.0f);
        float y7 = x7 * fmaf(x7, 0.5f, 1.0f);

        z2a += (y0 + y1) + (y2 + y3);
        z2b += (y4 + y5) + (y6 + y7);

        unsigned af[4];
        af[0] = packbf2(y0, y1);
        af[1] = packbf2(y4, y5);
        af[2] = packbf2(y2, y3);
        af[3] = packbf2(y6, y7);

        #pragma unroll
        for (int nt = 0; nt < 8; nt++) {
            const int n = nt * 8 + frow;
            unsigned bf[2] = { Vw[n * 12 + fcol], Vw[n * 12 + fcol + 4] };
            mma_bf16(acc[nt], af, bf);
        }
    }

    z2a += __shfl_xor_sync(0xffffffffu, z2a, 1);
    z2a += __shfl_xor_sync(0xffffffffu, z2a, 2);
    z2b += __shfl_xor_sync(0xffffffffu, z2b, 1);
    z2b += __shfl_xor_sync(0xffffffffu, z2b, 2);
    const float iza = 1.0f / (1024.0f + z2a);
    const float izb = 1.0f / (1024.0f + z2b);

    float* Cp = g_CTX + (size_t)b * Lsz * Dsz + (size_t)q0 * Dsz + h * DKsz;
    const float* CSp = g_CS + z * DKsz;
    #pragma unroll
    for (int nt = 0; nt < 8; nt++) {
        const int col = nt * 8 + 2 * fcol;
        float cs0 = CSp[col], cs1 = CSp[col + 1];
        *(float2*)&Cp[(size_t)r0 * Dsz + col] =
            make_float2(tf32r((cs0 + acc[nt][0]) * iza), tf32r((cs1 + acc[nt][1]) * iza));
        *(float2*)&Cp[(size_t)r1 * Dsz + col] =
            make_float2(tf32r((cs0 + acc[nt][2]) * izb), tf32r((cs1 + acc[nt][3]) * izb));
    }
}

// ---------------- gate (+ zero g_Z and g_CS) ----------------
__global__ void gate_kernel(const float* __restrict__ query,
                            const float* __restrict__ gw,
                            const float* __restrict__ gb)
{
    int gidx = blockIdx.x * blockDim.x + threadIdx.x;
    if (gidx < Bsz * Hsz * Lsz) g_Z[gidx] = 0.f;
    if (gidx < Bsz * Hsz * DKsz) g_CS[gidx] = 0.f;

    int warp = gidx >> 5;
    int lane = threadIdx.x & 31;
    if (warp >= Bsz * Lsz) return;
    const float* row = query + (size_t)warp * Dsz;
    float s = 0.f;
    for (int d = lane; d < Dsz; d += 32) s += row[d] * gw[d];
    #pragma unroll
    for (int o = 16; o; o >>= 1) s += __shfl_xor_sync(0xffffffffu, s, o);
    if (lane == 0) g_G[warp] = 1.0f / (1.0f + __expf(-(s + gb[0])));
}

// ---------------- launch ----------------
extern "C" void kernel_launch(void* const* d_in, const int* in_sizes, int n_in,
                              void* d_out, int out_size)
{
    const float* query   = (const float*)d_in[0];
    const float* key     = (const float*)d_in[1];
    const float* value   = (const float*)d_in[2];
    const float* wq_w    = (const float*)d_in[3];
    const float* wq_b    = (const float*)d_in[4];
    const float* wk_w    = (const float*)d_in[5];
    const float* wk_b    = (const float*)d_in[6];
    const float* wv_w    = (const float*)d_in[7];
    const float* wv_b    = (const float*)d_in[8];
    const float* dense_w = (const float*)d_in[9];
    const float* dense_b = (const float*)d_in[10];
    const float* gate_w  = (const float*)d_in[11];
    const float* gate_b  = (const float*)d_in[12];
    const float* mp_wq_w = (const float*)d_in[13];
    const float* mp_wq_b = (const float*)d_in[14];
    const float* mp_wk_w = (const float*)d_in[15];
    const float* mp_wk_b = (const float*)d_in[16];

    float* out   = (float*)d_out;
    float* m_out = out + (size_t)Bsz * Lsz * Dsz;

    void *pQbf, *pKbf, *pQPb, *pKPb;
    float *pV, *pCTX, *pW;
    cudaGetSymbolAddress(&pQbf, g_Qbf);
    cudaGetSymbolAddress(&pKbf, g_Kbf);
    cudaGetSymbolAddress(&pQPb, g_QPb);
    cudaGetSymbolAddress(&pKPb, g_KPb);
    cudaGetSymbolAddress((void**)&pV,   g_V);
    cudaGetSymbolAddress((void**)&pCTX, g_CTX);
    cudaGetSymbolAddress((void**)&pW,   g_W);

    static int attr_set = 0;
    if (!attr_set) {
        cudaFuncSetAttribute(proj_gemm_kernel<true>,
                             cudaFuncAttributeMaxDynamicSharedMemorySize, PROJ_SMEM);
        cudaFuncSetAttribute(proj_gemm_kernel<false>,
                             cudaFuncAttributeMaxDynamicSharedMemorySize, PROJ_SMEM);
        cudaFuncSetAttribute(ms_gemm_kernel,
                             cudaFuncAttributeMaxDynamicSharedMemorySize, NTG_SMEM);
        cudaFuncSetAttribute(ctx_fused_kernel,
                             cudaFuncAttributeMaxDynamicSharedMemorySize, CTXF_SMEM);
        attr_set = 1;
    }

    dim3 t256(256);

    WSrc ws;
    ws.p[0] = wq_w; ws.p[1] = wk_w; ws.p[2] = wv_w;
    ws.p[3] = mp_wq_w; ws.p[4] = mp_wk_w; ws.p[5] = dense_w;
    preround_kernel<<<dim3(256, 6), t256>>>(ws);

    gate_kernel<<<(Bsz * Lsz * 32) / 256, t256>>>(query, gate_w, gate_b);

    ProjArgs pa;
    pa.A[0] = query; pa.W[0] = pW + 0*Dsz*Dsz; pa.bias[0] = wq_b;    pa.C[0] = pQbf; pa.mode[0] = 2;
    pa.A[1] = key;   pa.W[1] = pW + 1*Dsz*Dsz; pa.bias[1] = wk_b;    pa.C[1] = pKbf; pa.mode[1] = 2;
    pa.A[2] = value; pa.W[2] = pW + 2*Dsz*Dsz; pa.bias[2] = wv_b;    pa.C[2] = pV;   pa.mode[2] = 1;
    pa.A[3] = query; pa.W[3] = pW + 3*Dsz*Dsz; pa.bias[3] = mp_wq_b; pa.C[3] = pQPb; pa.mode[3] = 2;
    pa.A[4] = key;   pa.W[4] = pW + 4*Dsz*Dsz; pa.bias[4] = mp_wk_b; pa.C[4] = pKPb; pa.mode[4] = 2;
    proj_gemm_kernel<true><<<dim3(4, 32, 5), t256, PROJ_SMEM>>>(pa, Dsz, Dsz);

    // m GEMM + score GEMM + vprep in one launch
    ms_gemm_kernel<<<dim3(8, 8, Bsz + Bsz * Hsz + Bsz), t256, NTG_SMEM>>>(m_out);

    ctx_fused_kernel<<<dim3(1, 8, Bsz * Hsz), t256, CTXF_SMEM>>>();

    ProjArgs da;
    da.A[0] = pCTX; da.W[0] = pW + 5*Dsz*Dsz; da.bias[0] = dense_b; da.C[0] = out; da.mode[0] = 0;
    da.A[1] = da.A[0]; da.W[1] = da.W[0]; da.bias[1] = da.bias[0]; da.C[1] = da.C[0]; da.mode[1] = 0;
    da.A[2] = da.A[0]; da.W[2] = da.W[0]; da.bias[2] = da.bias[0]; da.C[2] = da.C[0]; da.mode[2] = 0;
    da.A[3] = da.A[0]; da.W[3] = da.W[0]; da.bias[3] = da.bias[0]; da.C[3] = da.C[0]; da.mode[3] = 0;
    da.A[4] = da.A[0]; da.W[4] = da.W[0]; da.bias[4] = da.bias[0]; da.C[4] = da.C[0]; da.mode[4] = 0;
    proj_gemm_kernel<false><<<dim3(4, 32, 1), t256, PROJ_SMEM>>>(da, Dsz, Dsz);
}

// round 14
// speedup vs baseline: 1.2749x; 1.0983x over previous
#include <cuda_runtime.h>
#include <cuda_bf16.h>
#include <math.h>

#define Bsz 4
#define Lsz 1024
#define Dsz 512
#define Hsz 8
#define DKsz 64

// ---------------- scratch (static device globals; no allocation) ----------------
__device__ __nv_bfloat16 g_Qin[Bsz*Lsz*Dsz];   // query input, bf16
__device__ __nv_bfloat16 g_Kin[Bsz*Lsz*Dsz];   // key input, bf16
__device__ __nv_bfloat16 g_Wtb[4*Dsz*Dsz];     // transposed bf16 weights (wq,wk,mpq,mpk)
__device__ float g_W[2*Dsz*Dsz];               // tf32-prerounded weights (wv, dense)
__device__ __nv_bfloat16 g_Qbf[Bsz*Lsz*Dsz];   // projected q, bf16
__device__ __nv_bfloat16 g_Kbf[Bsz*Lsz*Dsz];   // projected k, bf16
__device__ __nv_bfloat16 g_QPb[Bsz*Lsz*Dsz];   // mask-perturb q proj, bf16
__device__ __nv_bfloat16 g_KPb[Bsz*Lsz*Dsz];   // mask-perturb k proj, bf16
__device__ float g_V[Bsz*Lsz*Dsz];             // tf32-prerounded
__device__ __nv_bfloat16 g_Vtb[Bsz*Hsz*DKsz*Lsz];  // V transposed [b,h,d,k], bf16
__device__ float g_CS[Bsz*Hsz*DKsz];           // colsum of V, fp32
__device__ __nv_bfloat16 g_EMb[Bsz*Lsz*Lsz];   // exp(1-m), bf16
__device__ float g_G[Bsz*Lsz];
__device__ __nv_bfloat16 g_Sb[(size_t)Bsz*Hsz*Lsz*Lsz];   // exp(scores), bf16
__device__ float g_Z[Bsz*Hsz*Lsz];
__device__ float g_CTX[Bsz*Lsz*Dsz];           // tf32-prerounded

// ---------------- helpers ----------------
__device__ __forceinline__ unsigned f2tf(float f) {
    unsigned u;
    asm("cvt.rna.tf32.f32 %0, %1;" : "=r"(u) : "f"(f));
    return u;
}
__device__ __forceinline__ float tf32r(float f) { return __uint_as_float(f2tf(f)); }

__device__ __forceinline__ unsigned packbf2(float lo, float hi) {
    unsigned r;
    asm("cvt.rn.bf16x2.f32 %0, %1, %2;" : "=r"(r) : "f"(hi), "f"(lo));
    return r;
}
__device__ __forceinline__ float2 unpackbf2(unsigned u) {
    __nv_bfloat162 v = *reinterpret_cast<__nv_bfloat162*>(&u);
    return __bfloat1622float2(v);
}

__device__ __forceinline__ void mma_tf32(float c[4], const unsigned a[4], const unsigned b[2]) {
    asm volatile(
        "mma.sync.aligned.m16n8k8.row.col.f32.tf32.tf32.f32 "
        "{%0,%1,%2,%3}, {%4,%5,%6,%7}, {%8,%9}, {%0,%1,%2,%3};"
        : "+f"(c[0]), "+f"(c[1]), "+f"(c[2]), "+f"(c[3])
        : "r"(a[0]), "r"(a[1]), "r"(a[2]), "r"(a[3]), "r"(b[0]), "r"(b[1]));
}

__device__ __forceinline__ void mma_bf16(float c[4], const unsigned a[4], const unsigned b[2]) {
    asm volatile(
        "mma.sync.aligned.m16n8k16.row.col.f32.bf16.bf16.f32 "
        "{%0,%1,%2,%3}, {%4,%5,%6,%7}, {%8,%9}, {%0,%1,%2,%3};"
        : "+f"(c[0]), "+f"(c[1]), "+f"(c[2]), "+f"(c[3])
        : "r"(a[0]), "r"(a[1]), "r"(a[2]), "r"(a[3]), "r"(b[0]), "r"(b[1]));
}

__device__ __forceinline__ void cp_async16(void* smem, const void* gmem) {
    unsigned saddr = (unsigned)__cvta_generic_to_shared(smem);
    asm volatile("cp.async.cg.shared.global [%0], [%1], 16;" :: "r"(saddr), "l"(gmem));
}
__device__ __forceinline__ void cp_commit() { asm volatile("cp.async.commit_group;"); }
template<int N>
__device__ __forceinline__ void cp_wait() { asm volatile("cp.async.wait_group %0;" :: "n"(N)); }

// ---------------- tf32 GEMM core, 4-stage pipeline (V proj + dense) ----------------
template<int BM, int BN, bool BT, int MT, int NT, bool ACVT, bool BCVT>
__device__ __forceinline__ void gemm_core(
    const float* __restrict__ A, int lda,
    const float* __restrict__ B, int ldb,
    int K, float (&acc)[MT][NT][4])
{
    constexpr int BK = 16;
    constexpr int APITCH = BK + 4;
    constexpr int BPITCH = BT ? (BK + 4) : (BN + 8);
    constexpr int BROWS  = BT ? BN : BK;

    extern __shared__ float dynsm[];
    float* As = dynsm;
    float* Bs = dynsm + 4 * BM * APITCH;

    const int tid = threadIdx.x;
    const int lane = tid & 31;
    const int wid = tid >> 5;
    const int wm0 = (wid & 3) * (BM / 4);
    const int wn0 = (wid >> 2) * (BN / 2);

    constexpr int ALD = (BM * BK / 4) / 256;
    constexpr int BLD = (BT ? (BN * BK / 4) : (BK * BN / 4)) / 256;

    auto prefetch = [&](int k0, int s) {
        float* Asl = As + s * BM * APITCH;
        float* Bsl = Bs + s * BROWS * BPITCH;
        #pragma unroll
        for (int i = 0; i < ALD; i++) {
            int idx = tid + i * 256;
            int row = idx >> 2, kq = idx & 3;
            cp_async16(&Asl[row * APITCH + kq * 4], A + (size_t)row * lda + k0 + kq * 4);
        }
        #pragma unroll
        for (int i = 0; i < BLD; i++) {
            int idx = tid + i * 256;
            if constexpr (BT) {
                int row = idx >> 2, kq = idx & 3;
                cp_async16(&Bsl[row * BPITCH + kq * 4], B + (size_t)row * ldb + k0 + kq * 4);
            } else {
                int k = idx / (BN / 4), nq = idx % (BN / 4);
                cp_async16(&Bsl[k * BPITCH + nq * 4], B + (size_t)(k0 + k) * ldb + nq * 4);
            }
        }
        cp_commit();
    };

    const int nIter = K / BK;
    prefetch(0, 0);
    if (nIter > 1) prefetch(BK, 1);

    for (int it = 0; it < nIter; it++) {
        if (it + 2 < nIter) { prefetch((it + 2) * BK, (it + 2) & 3); cp_wait<2>(); }
        else if (it + 1 < nIter) { cp_wait<1>(); }
        else { cp_wait<0>(); }
        __syncthreads();

        const int cur = it & 3;
        const float* Asl = As + cur * BM * APITCH;
        const float* Bsl = Bs + cur * BROWS * BPITCH;
        const unsigned* Aslu = (const unsigned*)Asl;
        const unsigned* Bslu = (const unsigned*)Bsl;

        #pragma unroll
        for (int ks = 0; ks < 2; ks++) {
            unsigned af[MT][4];
            unsigned bf[NT][2];
            const int kk = ks * 8 + (lane & 3);
            #pragma unroll
            for (int mt = 0; mt < MT; mt++) {
                int row = wm0 + mt * 16 + (lane >> 2);
                if constexpr (ACVT) {
                    af[mt][0] = f2tf(Asl[row * APITCH + kk]);
                    af[mt][1] = f2tf(Asl[(row + 8) * APITCH + kk]);
                    af[mt][2] = f2tf(Asl[row * APITCH + kk + 4]);
                    af[mt][3] = f2tf(Asl[(row + 8) * APITCH + kk + 4]);
                } else {
                    af[mt][0] = Aslu[row * APITCH + kk];
                    af[mt][1] = Aslu[(row + 8) * APITCH + kk];
                    af[mt][2] = Aslu[row * APITCH + kk + 4];
                    af[mt][3] = Aslu[(row + 8) * APITCH + kk + 4];
                }
            }
            #pragma unroll
            for (int nt = 0; nt < NT; nt++) {
                int n = wn0 + nt * 8 + (lane >> 2);
                if constexpr (BT) {
                    if constexpr (BCVT) {
                        bf[nt][0] = f2tf(Bsl[n * BPITCH + kk]);
                        bf[nt][1] = f2tf(Bsl[n * BPITCH + kk + 4]);
                    } else {
                        bf[nt][0] = Bslu[n * BPITCH + kk];
                        bf[nt][1] = Bslu[n * BPITCH + kk + 4];
                    }
                } else {
                    if constexpr (BCVT) {
                        bf[nt][0] = f2tf(Bsl[kk * BPITCH + n]);
                        bf[nt][1] = f2tf(Bsl[(kk + 4) * BPITCH + n]);
                    } else {
                        bf[nt][0] = Bslu[kk * BPITCH + n];
                        bf[nt][1] = Bslu[(kk + 4) * BPITCH + n];
                    }
                }
            }
            #pragma unroll
            for (int mt = 0; mt < MT; mt++)
                #pragma unroll
                for (int nt = 0; nt < NT; nt++)
                    mma_tf32(acc[mt][nt], af[mt], bf[nt]);
        }
    }
}

// smem byte sizes
#define PROJ_SMEM  ((4*128*20 + 4*16*136) * 4)   // 75776 (tf32 path)
#define NTG_SMEM   (4*128*40*2 * 2)              // 81920 (bf16 4-stage NT)
#define CTX_S_BYTES   (4 * 128 * 24 * 2)
#define CTX_E_BYTES   (4 * 128 * 24 * 2)
#define CTX_V_BYTES   (4 * 64 * 24 * 2)
#define CTXF_SMEM  (CTX_S_BYTES + CTX_E_BYTES + CTX_V_BYTES)  // 61440

// ---------------- weight preround (wv, dense -> tf32 fp32) ----------------
struct WSrc2 { const float* p[2]; };

__global__ void preround_kernel(WSrc2 ws)
{
    const int z = blockIdx.y;
    const float4* src = (const float4*)ws.p[z];
    float4* dst = (float4*)(g_W + z * Dsz * Dsz);
    int idx = blockIdx.x * 256 + threadIdx.x;
    float4 v = src[idx];
    dst[idx] = make_float4(tf32r(v.x), tf32r(v.y), tf32r(v.z), tf32r(v.w));
}

// ---------------- weight transpose to bf16: Wt[n][k] = W[k][n] ----------------
struct WSrc4 { const float* p[4]; };

__global__ void wtrans_kernel(WSrc4 ws)
{
    __shared__ float tile[32][33];
    const int z = blockIdx.z;
    const int c0 = blockIdx.x * 32, r0 = blockIdx.y * 32;
    const float* W = ws.p[z];
    const int tx = threadIdx.x & 31, ty = threadIdx.x >> 5;   // 8 rows per pass
    #pragma unroll
    for (int i = 0; i < 4; i++)
        tile[ty + i * 8][tx] = W[(size_t)(r0 + ty + i * 8) * Dsz + c0 + tx];
    __syncthreads();
    __nv_bfloat16* Wt = g_Wtb + (size_t)z * Dsz * Dsz;
    #pragma unroll
    for (int i = 0; i < 4; i++)
        Wt[(size_t)(c0 + ty + i * 8) * Dsz + r0 + tx] = __float2bfloat16(tile[tx][ty + i * 8]);
}

// ---------------- input convert: query/key fp32 -> bf16 ----------------
__global__ void incvt_kernel(const float* __restrict__ q, const float* __restrict__ k)
{
    const float* src = blockIdx.y ? k : q;
    __nv_bfloat16* dst = blockIdx.y ? g_Kin : g_Qin;
    int idx = blockIdx.x * 256 + threadIdx.x;   // float4 index; total 524288
    float4 v = ((const float4*)src)[idx];
    unsigned lo = packbf2(v.x, v.y);
    unsigned hi = packbf2(v.z, v.w);
    ((uint2*)dst)[idx] = make_uint2(lo, hi);
}

// ---------------- combined projections: 4x bf16 NT + 1x tf32 NN (V) ----------------
struct ProjAll {
    const __nv_bfloat16* A[4];
    const __nv_bfloat16* Wt[4];
    const float* bias[4];
    __nv_bfloat16* C[4];
    const float* vA; const float* vW; const float* vbias; float* vC;
};

__global__ void __launch_bounds__(256, 2) projall_kernel(ProjAll a)
{
    const int zz = blockIdx.z;
    const int tid = threadIdx.x;
    const int lane = tid & 31, wid = tid >> 5;
    const int fcol = lane & 3;
    extern __shared__ float dynsm[];

    if (zz < 4) {
        // bf16 NT pipelined: C = A @ Wt^T + bias, K=512, BK=32, 4-stage
        const __nv_bfloat16* Ab = a.A[zz] + ((size_t)blockIdx.y * 128) * Dsz;
        const __nv_bfloat16* Bb = a.Wt[zz] + ((size_t)blockIdx.x * 128) * Dsz;

        __nv_bfloat16* As = (__nv_bfloat16*)dynsm;     // 4 x 128 x 40
        __nv_bfloat16* Bs = As + 4 * 128 * 40;

        auto pre = [&](int it, int s) {
            const int k0 = it * 32;
            __nv_bfloat16* Al = As + s * 128 * 40;
            __nv_bfloat16* Bl = Bs + s * 128 * 40;
            #pragma unroll
            for (int i = 0; i < 2; i++) {
                int idx = tid + i * 256;
                int row = idx >> 2, ch = idx & 3;
                cp_async16(&Al[row * 40 + ch * 8], Ab + (size_t)row * Dsz + k0 + ch * 8);
                cp_async16(&Bl[row * 40 + ch * 8], Bb + (size_t)row * Dsz + k0 + ch * 8);
            }
            cp_commit();
        };

        const int wm0 = (wid & 3) * 32;
        const int wn0 = (wid >> 2) * 64;
        const int frow = lane >> 2;
        float acc[2][8][4] = {};

        const int nIter = Dsz / 32;   // 16
        pre(0, 0);
        pre(1, 1);

        for (int it = 0; it < nIter; it++) {
            if (it + 2 < nIter) { pre(it + 2, (it + 2) & 3); cp_wait<2>(); }
            else if (it + 1 < nIter) { cp_wait<1>(); }
            else { cp_wait<0>(); }
            __syncthreads();

            const int cur = it & 3;
            const unsigned* Aw = (const unsigned*)(As + cur * 128 * 40);  // word pitch 20
            const unsigned* Bw = (const unsigned*)(Bs + cur * 128 * 40);

            #pragma unroll
            for (int ks = 0; ks < 2; ks++) {
                const int kw = ks * 8 + fcol;
                unsigned af[2][4];
                #pragma unroll
                for (int mt = 0; mt < 2; mt++) {
                    int row = wm0 + mt * 16 + frow;
                    af[mt][0] = Aw[row * 20 + kw];
                    af[mt][1] = Aw[(row + 8) * 20 + kw];
                    af[mt][2] = Aw[row * 20 + kw + 4];
                    af[mt][3] = Aw[(row + 8) * 20 + kw + 4];
                }
                #pragma unroll
                for (int nt = 0; nt < 8; nt++) {
                    int n = wn0 + nt * 8 + frow;
                    unsigned bf[2] = { Bw[n * 20 + kw], Bw[n * 20 + kw + 4] };
                    #pragma unroll
                    for (int mt = 0; mt < 2; mt++)
                        mma_bf16(acc[mt][nt], af[mt], bf);
                }
            }
        }

        const float* bias = a.bias[zz];
        __nv_bfloat16* C = a.C[zz];
        int rowBase = blockIdx.y * 128 + wm0 + frow;
        int colBase = blockIdx.x * 128 + wn0 + 2 * fcol;
        #pragma unroll
        for (int mt = 0; mt < 2; mt++)
            #pragma unroll
            for (int nt = 0; nt < 8; nt++) {
                int row = rowBase + mt * 16;
                int col = colBase + nt * 8;
                float b0 = bias[col], b1 = bias[col + 1];
                *(__nv_bfloat162*)&C[(size_t)row * Dsz + col] =
                    __float22bfloat162_rn(make_float2(acc[mt][nt][0] + b0, acc[mt][nt][1] + b1));
                *(__nv_bfloat162*)&C[(size_t)(row + 8) * Dsz + col] =
                    __float22bfloat162_rn(make_float2(acc[mt][nt][2] + b0, acc[mt][nt][3] + b1));
            }
    } else {
        // V projection: tf32 NN, output tf32-rounded fp32
        float acc[2][8][4] = {};
        const float* Ab = a.vA + (size_t)blockIdx.y * 128 * Dsz;
        const float* Bb = a.vW + blockIdx.x * 128;
        gemm_core<128, 128, false, 2, 8, true, false>(Ab, Dsz, Bb, Dsz, Dsz, acc);

        const float* bias = a.vbias;
        float* C = a.vC;
        int rowBase = blockIdx.y * 128 + (wid & 3) * 32 + (lane >> 2);
        int colBase = blockIdx.x * 128 + (wid >> 2) * 64 + 2 * fcol;
        #pragma unroll
        for (int mt = 0; mt < 2; mt++)
            #pragma unroll
            for (int nt = 0; nt < 8; nt++) {
                int row = rowBase + mt * 16;
                int col = colBase + nt * 8;
                float b0 = bias[col], b1 = bias[col + 1];
                *(float2*)&C[(size_t)row * Dsz + col] =
                    make_float2(tf32r(acc[mt][nt][0] + b0), tf32r(acc[mt][nt][1] + b1));
                *(float2*)&C[(size_t)(row + 8) * Dsz + col] =
                    make_float2(tf32r(acc[mt][nt][2] + b0), tf32r(acc[mt][nt][3] + b1));
            }
    }
}

// ---------------- dense: tf32 NN, plain fp32 out ----------------
__global__ void __launch_bounds__(256, 2) dense_gemm_kernel(
    const float* __restrict__ A, const float* __restrict__ W,
    const float* __restrict__ bias, float* __restrict__ C)
{
    float acc[2][8][4] = {};
    const float* Ab = A + (size_t)blockIdx.y * 128 * Dsz;
    const float* Bb = W + blockIdx.x * 128;
    gemm_core<128, 128, false, 2, 8, false, false>(Ab, Dsz, Bb, Dsz, Dsz, acc);

    int lane = threadIdx.x & 31, wid = threadIdx.x >> 5;
    int rowBase = blockIdx.y * 128 + (wid & 3) * 32 + (lane >> 2);
    int colBase = blockIdx.x * 128 + (wid >> 2) * 64 + 2 * (lane & 3);
    #pragma unroll
    for (int mt = 0; mt < 2; mt++)
        #pragma unroll
        for (int nt = 0; nt < 8; nt++) {
            int row = rowBase + mt * 16;
            int col = colBase + nt * 8;
            float b0 = bias[col], b1 = bias[col + 1];
            *(float2*)&C[(size_t)row * Dsz + col] =
                make_float2(acc[mt][nt][0] + b0, acc[mt][nt][1] + b1);
            *(float2*)&C[(size_t)(row + 8) * Dsz + col] =
                make_float2(acc[mt][nt][2] + b0, acc[mt][nt][3] + b1);
        }
}

// ---------------- merged m + score + vprep launch (unchanged from R13) ----------------
__global__ void __launch_bounds__(256, 2) ms_gemm_kernel(float* __restrict__ m_out)
{
    const int zz = blockIdx.z;
    const int tid = threadIdx.x;
    int lane = tid & 31, wid = tid >> 5;
    int fcol = lane & 3;
    extern __shared__ float dynsm[];

    if (zz < Bsz) {
        const float SCALE = 0.04419417382415922f; // 1/sqrt(512)
        const int zb = zz;
        const __nv_bfloat16* Ab = g_QPb + ((size_t)zb * Lsz + blockIdx.y * 128) * Dsz;
        const __nv_bfloat16* Bb = g_KPb + ((size_t)zb * Lsz + blockIdx.x * 128) * Dsz;

        __nv_bfloat16* As = (__nv_bfloat16*)dynsm;
        __nv_bfloat16* Bs = As + 4 * 128 * 40;

        auto pre = [&](int it, int s) {
            const int k0 = it * 32;
            __nv_bfloat16* Al = As + s * 128 * 40;
            __nv_bfloat16* Bl = Bs + s * 128 * 40;
            #pragma unroll
            for (int i = 0; i < 2; i++) {
                int idx = tid + i * 256;
                int row = idx >> 2, ch = idx & 3;
                cp_async16(&Al[row * 40 + ch * 8], Ab + (size_t)row * Dsz + k0 + ch * 8);
                cp_async16(&Bl[row * 40 + ch * 8], Bb + (size_t)row * Dsz + k0 + ch * 8);
            }
            cp_commit();
        };

        const int wm0 = (wid & 3) * 32;
        const int wn0 = (wid >> 2) * 64;
        const int frow = lane >> 2;
        float acc[2][8][4] = {};

        const int nIter = Dsz / 32;
        pre(0, 0);
        pre(1, 1);

        for (int it = 0; it < nIter; it++) {
            if (it + 2 < nIter) { pre(it + 2, (it + 2) & 3); cp_wait<2>(); }
            else if (it + 1 < nIter) { cp_wait<1>(); }
            else { cp_wait<0>(); }
            __syncthreads();

            const int cur = it & 3;
            const unsigned* Aw = (const unsigned*)(As + cur * 128 * 40);
            const unsigned* Bw = (const unsigned*)(Bs + cur * 128 * 40);

            #pragma unroll
            for (int ks = 0; ks < 2; ks++) {
                const int kw = ks * 8 + fcol;
                unsigned af[2][4];
                #pragma unroll
                for (int mt = 0; mt < 2; mt++) {
                    int row = wm0 + mt * 16 + frow;
                    af[mt][0] = Aw[row * 20 + kw];
                    af[mt][1] = Aw[(row + 8) * 20 + kw];
                    af[mt][2] = Aw[row * 20 + kw + 4];
                    af[mt][3] = Aw[(row + 8) * 20 + kw + 4];
                }
                #pragma unroll
                for (int nt = 0; nt < 8; nt++) {
                    int n = wn0 + nt * 8 + frow;
                    unsigned bf[2] = { Bw[n * 20 + kw], Bw[n * 20 + kw + 4] };
                    #pragma unroll
                    for (int mt = 0; mt < 2; mt++)
                        mma_bf16(acc[mt][nt], af[mt], bf);
                }
            }
        }

        float* Mo = m_out + (size_t)zb * Lsz * Lsz;
        __nv_bfloat16* Eo = g_EMb + (size_t)zb * Lsz * Lsz;
        int rowBase = blockIdx.y * 128 + wm0 + frow;
        int colBase = blockIdx.x * 128 + wn0 + 2 * fcol;
        #pragma unroll
        for (int mt = 0; mt < 2; mt++)
            #pragma unroll
            for (int nt = 0; nt < 8; nt++) {
                int row = rowBase + mt * 16;
                int col = colBase + nt * 8;
                #pragma unroll
                for (int h = 0; h < 2; h++) {
                    int r = row + h * 8;
                    float s0 = 1.0f / (1.0f + __expf(-acc[mt][nt][2*h] * SCALE));
                    float s1 = 1.0f / (1.0f + __expf(-acc[mt][nt][2*h+1] * SCALE));
                    *(float2*)&Mo[(size_t)r * Lsz + col] = make_float2(s0, s1);
                    *(__nv_bfloat162*)&Eo[(size_t)r * Lsz + col] =
                        __float22bfloat162_rn(make_float2(__expf(1.0f - s0), __expf(1.0f - s1)));
                }
            }
    } else if (zz < Bsz + Bsz * Hsz) {
        const float SCALE = 0.125f;
        const int z = zz - Bsz;
        const int b = z >> 3, h = z & 7;
        const __nv_bfloat16* Ab = g_Qbf + ((size_t)b * Lsz + blockIdx.y * 128) * Dsz + h * DKsz;
        const __nv_bfloat16* Bb = g_Kbf + ((size_t)b * Lsz + blockIdx.x * 128) * Dsz + h * DKsz;

        __nv_bfloat16* Qs = (__nv_bfloat16*)dynsm;
        __nv_bfloat16* Ks = Qs + 128 * 88;
        const unsigned* Qw = (const unsigned*)Qs;
        const unsigned* Kw = (const unsigned*)Ks;

        #pragma unroll
        for (int i = 0; i < 4; i++) {
            int idx = tid + i * 256;
            int row = idx >> 3, ch = idx & 7;
            cp_async16(&Qs[row * 88 + ch * 8], Ab + (size_t)row * Dsz + ch * 8);
        }
        #pragma unroll
        for (int i = 0; i < 4; i++) {
            int idx = tid + i * 256;
            int row = idx >> 3, ch = idx & 7;
            cp_async16(&Ks[row * 88 + ch * 8], Bb + (size_t)row * Dsz + ch * 8);
        }
        cp_commit();
        cp_wait<0>();
        __syncthreads();

        const int wm0 = (wid & 3) * 32;
        const int wn0 = (wid >> 2) * 64;
        const int frow = lane >> 2;
        float acc[2][8][4] = {};

        #pragma unroll
        for (int ks = 0; ks < 4; ks++) {
            const int kw = ks * 8 + fcol;
            unsigned af[2][4];
            #pragma unroll
            for (int mt = 0; mt < 2; mt++) {
                int row = wm0 + mt * 16 + frow;
                af[mt][0] = Qw[row * 44 + kw];
                af[mt][1] = Qw[(row + 8) * 44 + kw];
                af[mt][2] = Qw[row * 44 + kw + 4];
                af[mt][3] = Qw[(row + 8) * 44 + kw + 4];
            }
            #pragma unroll
            for (int nt = 0; nt < 8; nt++) {
                int n = wn0 + nt * 8 + frow;
                unsigned bf[2] = { Kw[n * 44 + kw], Kw[n * 44 + kw + 4] };
                #pragma unroll
                for (int mt = 0; mt < 2; mt++)
                    mma_bf16(acc[mt][nt], af[mt], bf);
            }
        }

        __nv_bfloat16* Cp = g_Sb + (size_t)z * Lsz * Lsz;
        int rowBase = blockIdx.y * 128 + wm0 + frow;
        int colBase = blockIdx.x * 128 + wn0 + 2 * fcol;

        float rs[2][2] = {};
        #pragma unroll
        for (int mt = 0; mt < 2; mt++)
            #pragma unroll
            for (int nt = 0; nt < 8; nt++) {
                int row = rowBase + mt * 16;
                int col = colBase + nt * 8;
                float p0 = __expf(acc[mt][nt][0] * SCALE);
                float p1 = __expf(acc[mt][nt][1] * SCALE);
                float p2 = __expf(acc[mt][nt][2] * SCALE);
                float p3 = __expf(acc[mt][nt][3] * SCALE);
                *(__nv_bfloat162*)&Cp[(size_t)row * Lsz + col] =
                    __float22bfloat162_rn(make_float2(p0, p1));
                *(__nv_bfloat162*)&Cp[(size_t)(row + 8) * Lsz + col] =
                    __float22bfloat162_rn(make_float2(p2, p3));
                rs[0][0] = rs[0][0]; // no-op
                rs[mt][0] += p0 + p1;
                rs[mt][1] += p2 + p3;
            }

        #pragma unroll
        for (int mt = 0; mt < 2; mt++)
            #pragma unroll
            for (int hh = 0; hh < 2; hh++) {
                float v = rs[mt][hh];
                v += __shfl_xor_sync(0xffffffffu, v, 1);
                v += __shfl_xor_sync(0xffffffffu, v, 2);
                if (fcol == 0)
                    atomicAdd(&g_Z[(size_t)z * Lsz + rowBase + mt * 16 + hh * 8], v);
            }
    } else {
        __nv_bfloat16 (*sm)[72] = (__nv_bfloat16(*)[72])dynsm;
        const int b = zz - (Bsz + Bsz * Hsz);
        const int h = blockIdx.y, kt = blockIdx.x;
        const int k0 = kt * 128;

        const int d = tid & 63, rg = tid >> 6;
        float psum = 0.f;
        #pragma unroll
        for (int j = 0; j < 32; j++) {
            int row = rg + 4 * j;
            float v = g_V[((size_t)(b * Lsz + k0 + row)) * Dsz + h * DKsz + d];
            psum += v;
            sm[row][d] = __float2bfloat16(v);
        }
        atomicAdd(&g_CS[(b * Hsz + h) * DKsz + d], psum);
        __syncthreads();

        const int d2 = tid >> 2, c = tid & 3;
        __nv_bfloat16* dst = g_Vtb + ((size_t)((b * Hsz + h) * DKsz + d2)) * Lsz + k0 + c * 32;
        #pragma unroll
        for (int q = 0; q < 4; q++) {
            __nv_bfloat16 tmp[8];
            #pragma unroll
            for (int e = 0; e < 8; e++) tmp[e] = sm[c * 32 + q * 8 + e][d2];
            *(uint4*)(dst + q * 8) = *(uint4*)tmp;
        }
    }
}

// ---------------- fused calibrate + ctx GEMM (Σ-decomposition, unchanged) ----------------
__global__ void __launch_bounds__(256, 2) ctx_fused_kernel()
{
    extern __shared__ char smc[];
    __nv_bfloat16* Ss = (__nv_bfloat16*)smc;
    __nv_bfloat16* Es = (__nv_bfloat16*)(smc + CTX_S_BYTES);
    __nv_bfloat16* Vs = (__nv_bfloat16*)(smc + CTX_S_BYTES + CTX_E_BYTES);

    const int tid = threadIdx.x;
    const int lane = tid & 31;
    const int wid = tid >> 5;
    const int z = blockIdx.z;
    const int b = z >> 3, h = z & 7;
    const int q0 = blockIdx.y * 128;

    const __nv_bfloat16* Sg = g_Sb + (size_t)z * Lsz * Lsz + (size_t)q0 * Lsz;
    const __nv_bfloat16* Eg = g_EMb + (size_t)b * Lsz * Lsz + (size_t)q0 * Lsz;
    const __nv_bfloat16* Vtg = g_Vtb + (size_t)z * DKsz * Lsz;

    const int wm = wid * 16;
    const int frow = lane >> 2, fcol = lane & 3;
    const int r0 = wm + frow, r1 = r0 + 8;

    const float g0 = g_G[b * Lsz + q0 + r0];
    const float g1 = g_G[b * Lsz + q0 + r1];
    const float iz0 = 1.0f / g_Z[(size_t)z * Lsz + q0 + r0];
    const float iz1 = 1.0f / g_Z[(size_t)z * Lsz + q0 + r1];
    const float ga0 = g0 * iz0, gc0 = (1.0f - g0) * iz0;
    const float ga1 = g1 * iz1, gc1 = (1.0f - g1) * iz1;
    float z2a = 0.f, z2b = 0.f;

    auto prefetch = [&](int it, int s) {
        const int k0 = it * 16;
        __nv_bfloat16* Sl = Ss + s * 128 * 24;
        __nv_bfloat16* El = Es + s * 128 * 24;
        __nv_bfloat16* Vl = Vs + s * 64 * 24;
        {
            int row = tid >> 1, ch = tid & 1;
            cp_async16(&Sl[row * 24 + ch * 8], Sg + (size_t)row * Lsz + k0 + ch * 8);
            cp_async16(&El[row * 24 + ch * 8], Eg + (size_t)row * Lsz + k0 + ch * 8);
        }
        if (tid < 128) {
            int d = tid >> 1, half = tid & 1;
            cp_async16(&Vl[d * 24 + half * 8], Vtg + (size_t)d * Lsz + k0 + half * 8);
        }
        cp_commit();
    };

    float acc[8][4] = {};
    const int nIter = Lsz / 16;
    prefetch(0, 0);
    prefetch(1, 1);

    for (int it = 0; it < nIter; it++) {
        if (it + 2 < nIter) { prefetch(it + 2, (it + 2) & 3); cp_wait<2>(); }
        else if (it + 1 < nIter) { cp_wait<1>(); }
        else { cp_wait<0>(); }
        __syncthreads();

        const int cur = it & 3;
        const unsigned* Sw = (const unsigned*)(Ss + cur * 128 * 24);
        const unsigned* Ew = (const unsigned*)(Es + cur * 128 * 24);
        const unsigned* Vw = (const unsigned*)(Vs + cur * 64 * 24);

        float2 p00 = unpackbf2(Sw[r0 * 12 + fcol]);
        float2 p01 = unpackbf2(Sw[r0 * 12 + fcol + 4]);
        float2 p10 = unpackbf2(Sw[r1 * 12 + fcol]);
        float2 p11 = unpackbf2(Sw[r1 * 12 + fcol + 4]);
        float2 e00 = unpackbf2(Ew[r0 * 12 + fcol]);
        float2 e01 = unpackbf2(Ew[r0 * 12 + fcol + 4]);
        float2 e10 = unpackbf2(Ew[r1 * 12 + fcol]);
        float2 e11 = unpackbf2(Ew[r1 * 12 + fcol + 4]);

        float x0 = p00.x * fmaf(gc0, e00.x, ga0);
        float x1 = p00.y * fmaf(gc0, e00.y, ga0);
        float x2 = p01.x * fmaf(gc0, e01.x, ga0);
        float x3 = p01.y * fmaf(gc0, e01.y, ga0);
        float x4 = p10.x * fmaf(gc1, e10.x, ga1);
        float x5 = p10.y * fmaf(gc1, e10.y, ga1);
        float x6 = p11.x * fmaf(gc1, e11.x, ga1);
        float x7 = p11.y * fmaf(gc1, e11.y, ga1);

        float y0 = x0 * fmaf(x0, 0.5f, 1.0f);
        float y1 = x1 * fmaf(x1, 0.5f, 1.0f);
        float y2 = x2 * fmaf(x2, 0.5f, 1.0f);
        float y3 = x3 * fmaf(x3, 0.5f, 1.0f);
        float y4 = x4 * fmaf(x4, 0.5f, 1.0f);
        float y5 = x5 * fmaf(x5, 0.5f, 1.0f);
        float y6 = x6 * fmaf(x6, 0.5f, 1.0f);
        float y7 = x7 * fmaf(x7, 0.5f, 1.0f);

        z2a += (y0 + y1) + (y2 + y3);
        z2b += (y4 + y5) + (y6 + y7);

        unsigned af[4];
        af[0] = packbf2(y0, y1);
        af[1] = packbf2(y4, y5);
        af[2] = packbf2(y2, y3);
        af[3] = packbf2(y6, y7);

        #pragma unroll
        for (int nt = 0; nt < 8; nt++) {
            const int n = nt * 8 + frow;
            unsigned bf[2] = { Vw[n * 12 + fcol], Vw[n * 12 + fcol + 4] };
            mma_bf16(acc[nt], af, bf);
        }
    }

    z2a += __shfl_xor_sync(0xffffffffu, z2a, 1);
    z2a += __shfl_xor_sync(0xffffffffu, z2a, 2);
    z2b += __shfl_xor_sync(0xffffffffu, z2b, 1);
    z2b += __shfl_xor_sync(0xffffffffu, z2b, 2);
    const float iza = 1.0f / (1024.0f + z2a);
    const float izb = 1.0f / (1024.0f + z2b);

    float* Cp = g_CTX + (size_t)b * Lsz * Dsz + (size_t)q0 * Dsz + h * DKsz;
    const float* CSp = g_CS + z * DKsz;
    #pragma unroll
    for (int nt = 0; nt < 8; nt++) {
        const int col = nt * 8 + 2 * fcol;
        float cs0 = CSp[col], cs1 = CSp[col + 1];
        *(float2*)&Cp[(size_t)r0 * Dsz + col] =
            make_float2(tf32r((cs0 + acc[nt][0]) * iza), tf32r((cs1 + acc[nt][1]) * iza));
        *(float2*)&Cp[(size_t)r1 * Dsz + col] =
            make_float2(tf32r((cs0 + acc[nt][2]) * izb), tf32r((cs1 + acc[nt][3]) * izb));
    }
}

// ---------------- gate (+ zero g_Z and g_CS) ----------------
__global__ void gate_kernel(const float* __restrict__ query,
                            const float* __restrict__ gw,
                            const float* __restrict__ gb)
{
    int gidx = blockIdx.x * blockDim.x + threadIdx.x;
    if (gidx < Bsz * Hsz * Lsz) g_Z[gidx] = 0.f;
    if (gidx < Bsz * Hsz * DKsz) g_CS[gidx] = 0.f;

    int warp = gidx >> 5;
    int lane = threadIdx.x & 31;
    if (warp >= Bsz * Lsz) return;
    const float* row = query + (size_t)warp * Dsz;
    float s = 0.f;
    for (int d = lane; d < Dsz; d += 32) s += row[d] * gw[d];
    #pragma unroll
    for (int o = 16; o; o >>= 1) s += __shfl_xor_sync(0xffffffffu, s, o);
    if (lane == 0) g_G[warp] = 1.0f / (1.0f + __expf(-(s + gb[0])));
}

// ---------------- launch ----------------
extern "C" void kernel_launch(void* const* d_in, const int* in_sizes, int n_in,
                              void* d_out, int out_size)
{
    const float* query   = (const float*)d_in[0];
    const float* key     = (const float*)d_in[1];
    const float* value   = (const float*)d_in[2];
    const float* wq_w    = (const float*)d_in[3];
    const float* wq_b    = (const float*)d_in[4];
    const float* wk_w    = (const float*)d_in[5];
    const float* wk_b    = (const float*)d_in[6];
    const float* wv_w    = (const float*)d_in[7];
    const float* wv_b    = (const float*)d_in[8];
    const float* dense_w = (const float*)d_in[9];
    const float* dense_b = (const float*)d_in[10];
    const float* gate_w  = (const float*)d_in[11];
    const float* gate_b  = (const float*)d_in[12];
    const float* mp_wq_w = (const float*)d_in[13];
    const float* mp_wq_b = (const float*)d_in[14];
    const float* mp_wk_w = (const float*)d_in[15];
    const float* mp_wk_b = (const float*)d_in[16];

    float* out   = (float*)d_out;
    float* m_out = out + (size_t)Bsz * Lsz * Dsz;

    void *pQin, *pKin, *pWtb, *pQbf, *pKbf, *pQPb, *pKPb;
    float *pV, *pCTX, *pW;
    cudaGetSymbolAddress(&pQin, g_Qin);
    cudaGetSymbolAddress(&pKin, g_Kin);
    cudaGetSymbolAddress(&pWtb, g_Wtb);
    cudaGetSymbolAddress(&pQbf, g_Qbf);
    cudaGetSymbolAddress(&pKbf, g_Kbf);
    cudaGetSymbolAddress(&pQPb, g_QPb);
    cudaGetSymbolAddress(&pKPb, g_KPb);
    cudaGetSymbolAddress((void**)&pV,   g_V);
    cudaGetSymbolAddress((void**)&pCTX, g_CTX);
    cudaGetSymbolAddress((void**)&pW,   g_W);

    static int attr_set = 0;
    if (!attr_set) {
        cudaFuncSetAttribute(projall_kernel,
                             cudaFuncAttributeMaxDynamicSharedMemorySize, NTG_SMEM);
        cudaFuncSetAttribute(dense_gemm_kernel,
                             cudaFuncAttributeMaxDynamicSharedMemorySize, PROJ_SMEM);
        cudaFuncSetAttribute(ms_gemm_kernel,
                             cudaFuncAttributeMaxDynamicSharedMemorySize, NTG_SMEM);
        cudaFuncSetAttribute(ctx_fused_kernel,
                             cudaFuncAttributeMaxDynamicSharedMemorySize, CTXF_SMEM);
        attr_set = 1;
    }

    dim3 t256(256);

    WSrc2 ws2;
    ws2.p[0] = wv_w; ws2.p[1] = dense_w;
    preround_kernel<<<dim3(256, 2), t256>>>(ws2);

    WSrc4 ws4;
    ws4.p[0] = wq_w; ws4.p[1] = wk_w; ws4.p[2] = mp_wq_w; ws4.p[3] = mp_wk_w;
    wtrans_kernel<<<dim3(16, 16, 4), t256>>>(ws4);

    incvt_kernel<<<dim3(2048, 2), t256>>>(query, key);

    gate_kernel<<<(Bsz * Lsz * 32) / 256, t256>>>(query, gate_w, gate_b);

    ProjAll pa;
    pa.A[0] = (const __nv_bfloat16*)pQin; pa.Wt[0] = (const __nv_bfloat16*)pWtb + 0*Dsz*Dsz;
    pa.bias[0] = wq_b;    pa.C[0] = (__nv_bfloat16*)pQbf;
    pa.A[1] = (const __nv_bfloat16*)pKin; pa.Wt[1] = (const __nv_bfloat16*)pWtb + 1*Dsz*Dsz;
    pa.bias[1] = wk_b;    pa.C[1] = (__nv_bfloat16*)pKbf;
    pa.A[2] = (const __nv_bfloat16*)pQin; pa.Wt[2] = (const __nv_bfloat16*)pWtb + 2*Dsz*Dsz;
    pa.bias[2] = mp_wq_b; pa.C[2] = (__nv_bfloat16*)pQPb;
    pa.A[3] = (const __nv_bfloat16*)pKin; pa.Wt[3] = (const __nv_bfloat16*)pWtb + 3*Dsz*Dsz;
    pa.bias[3] = mp_wk_b; pa.C[3] = (__nv_bfloat16*)pKPb;
    pa.vA = value; pa.vW = pW + 0*Dsz*Dsz; pa.vbias = wv_b; pa.vC = pV;
    projall_kernel<<<dim3(4, 32, 5), t256, NTG_SMEM>>>(pa);

    ms_gemm_kernel<<<dim3(8, 8, Bsz + Bsz * Hsz + Bsz), t256, NTG_SMEM>>>(m_out);

    ctx_fused_kernel<<<dim3(1, 8, Bsz * Hsz), t256, CTXF_SMEM>>>();

    dense_gemm_kernel<<<dim3(4, 32), t256, PROJ_SMEM>>>(pCTX, pW + 1*Dsz*Dsz, dense_b, out);
}

// round 15
// speedup vs baseline: 1.2989x; 1.0189x over previous
#include <cuda_runtime.h>
#include <cuda_bf16.h>
#include <math.h>

#define Bsz 4
#define Lsz 1024
#define Dsz 512
#define Hsz 8
#define DKsz 64

// ---------------- scratch (static device globals; no allocation) ----------------
__device__ __nv_bfloat16 g_Qin[Bsz*Lsz*Dsz];   // query input, bf16
__device__ __nv_bfloat16 g_Kin[Bsz*Lsz*Dsz];   // key input, bf16
__device__ __nv_bfloat16 g_Wtb[4*Dsz*Dsz];     // transposed bf16 weights (wq,wk,mpq,mpk)
__device__ float g_W[2*Dsz*Dsz];               // tf32-prerounded weights (wv, dense)
__device__ __nv_bfloat16 g_Qbf[Bsz*Lsz*Dsz];   // projected q, bf16
__device__ __nv_bfloat16 g_Kbf[Bsz*Lsz*Dsz];   // projected k, bf16
__device__ __nv_bfloat16 g_QPb[Bsz*Lsz*Dsz];   // mask-perturb q proj, bf16
__device__ __nv_bfloat16 g_KPb[Bsz*Lsz*Dsz];   // mask-perturb k proj, bf16
__device__ float g_V[Bsz*Lsz*Dsz];             // tf32-prerounded
__device__ __nv_bfloat16 g_Vtb[Bsz*Hsz*DKsz*Lsz];  // V transposed [b,h,d,k], bf16
__device__ float g_CS[Bsz*Hsz*DKsz];           // colsum of V, fp32
__device__ __nv_bfloat16 g_EMb[Bsz*Lsz*Lsz];   // exp(1-m), bf16
__device__ float g_G[Bsz*Lsz];
__device__ __nv_bfloat16 g_Sb[(size_t)Bsz*Hsz*Lsz*Lsz];   // exp(scores), bf16
__device__ float g_Z[Bsz*Hsz*Lsz];
__device__ float g_CTX[Bsz*Lsz*Dsz];           // tf32-prerounded

// ---------------- helpers ----------------
__device__ __forceinline__ unsigned f2tf(float f) {
    unsigned u;
    asm("cvt.rna.tf32.f32 %0, %1;" : "=r"(u) : "f"(f));
    return u;
}
__device__ __forceinline__ float tf32r(float f) { return __uint_as_float(f2tf(f)); }

__device__ __forceinline__ unsigned packbf2(float lo, float hi) {
    unsigned r;
    asm("cvt.rn.bf16x2.f32 %0, %1, %2;" : "=r"(r) : "f"(hi), "f"(lo));
    return r;
}
__device__ __forceinline__ float2 unpackbf2(unsigned u) {
    __nv_bfloat162 v = *reinterpret_cast<__nv_bfloat162*>(&u);
    return __bfloat1622float2(v);
}

__device__ __forceinline__ void mma_tf32(float c[4], const unsigned a[4], const unsigned b[2]) {
    asm volatile(
        "mma.sync.aligned.m16n8k8.row.col.f32.tf32.tf32.f32 "
        "{%0,%1,%2,%3}, {%4,%5,%6,%7}, {%8,%9}, {%0,%1,%2,%3};"
        : "+f"(c[0]), "+f"(c[1]), "+f"(c[2]), "+f"(c[3])
        : "r"(a[0]), "r"(a[1]), "r"(a[2]), "r"(a[3]), "r"(b[0]), "r"(b[1]));
}

__device__ __forceinline__ void mma_bf16(float c[4], const unsigned a[4], const unsigned b[2]) {
    asm volatile(
        "mma.sync.aligned.m16n8k16.row.col.f32.bf16.bf16.f32 "
        "{%0,%1,%2,%3}, {%4,%5,%6,%7}, {%8,%9}, {%0,%1,%2,%3};"
        : "+f"(c[0]), "+f"(c[1]), "+f"(c[2]), "+f"(c[3])
        : "r"(a[0]), "r"(a[1]), "r"(a[2]), "r"(a[3]), "r"(b[0]), "r"(b[1]));
}

__device__ __forceinline__ void cp_async16(void* smem, const void* gmem) {
    unsigned saddr = (unsigned)__cvta_generic_to_shared(smem);
    asm volatile("cp.async.cg.shared.global [%0], [%1], 16;" :: "r"(saddr), "l"(gmem));
}
__device__ __forceinline__ void cp_commit() { asm volatile("cp.async.commit_group;"); }
template<int N>
__device__ __forceinline__ void cp_wait() { asm volatile("cp.async.wait_group %0;" :: "n"(N)); }

// ---------------- tf32 GEMM core, 4-stage pipeline (V proj + dense) ----------------
template<int BM, int BN, bool BT, int MT, int NT, bool ACVT, bool BCVT>
__device__ __forceinline__ void gemm_core(
    const float* __restrict__ A, int lda,
    const float* __restrict__ B, int ldb,
    int K, float (&acc)[MT][NT][4])
{
    constexpr int BK = 16;
    constexpr int APITCH = BK + 4;
    constexpr int BPITCH = BT ? (BK + 4) : (BN + 8);
    constexpr int BROWS  = BT ? BN : BK;

    extern __shared__ float dynsm[];
    float* As = dynsm;
    float* Bs = dynsm + 4 * BM * APITCH;

    const int tid = threadIdx.x;
    const int lane = tid & 31;
    const int wid = tid >> 5;
    const int wm0 = (wid & 3) * (BM / 4);
    const int wn0 = (wid >> 2) * (BN / 2);

    constexpr int ALD = (BM * BK / 4) / 256;
    constexpr int BLD = (BT ? (BN * BK / 4) : (BK * BN / 4)) / 256;

    auto prefetch = [&](int k0, int s) {
        float* Asl = As + s * BM * APITCH;
        float* Bsl = Bs + s * BROWS * BPITCH;
        #pragma unroll
        for (int i = 0; i < ALD; i++) {
            int idx = tid + i * 256;
            int row = idx >> 2, kq = idx & 3;
            cp_async16(&Asl[row * APITCH + kq * 4], A + (size_t)row * lda + k0 + kq * 4);
        }
        #pragma unroll
        for (int i = 0; i < BLD; i++) {
            int idx = tid + i * 256;
            if constexpr (BT) {
                int row = idx >> 2, kq = idx & 3;
                cp_async16(&Bsl[row * BPITCH + kq * 4], B + (size_t)row * ldb + k0 + kq * 4);
            } else {
                int k = idx / (BN / 4), nq = idx % (BN / 4);
                cp_async16(&Bsl[k * BPITCH + nq * 4], B + (size_t)(k0 + k) * ldb + nq * 4);
            }
        }
        cp_commit();
    };

    const int nIter = K / BK;
    prefetch(0, 0);
    if (nIter > 1) prefetch(BK, 1);

    for (int it = 0; it < nIter; it++) {
        if (it + 2 < nIter) { prefetch((it + 2) * BK, (it + 2) & 3); cp_wait<2>(); }
        else if (it + 1 < nIter) { cp_wait<1>(); }
        else { cp_wait<0>(); }
        __syncthreads();

        const int cur = it & 3;
        const float* Asl = As + cur * BM * APITCH;
        const float* Bsl = Bs + cur * BROWS * BPITCH;
        const unsigned* Aslu = (const unsigned*)Asl;
        const unsigned* Bslu = (const unsigned*)Bsl;

        #pragma unroll
        for (int ks = 0; ks < 2; ks++) {
            unsigned af[MT][4];
            unsigned bf[NT][2];
            const int kk = ks * 8 + (lane & 3);
            #pragma unroll
            for (int mt = 0; mt < MT; mt++) {
                int row = wm0 + mt * 16 + (lane >> 2);
                if constexpr (ACVT) {
                    af[mt][0] = f2tf(Asl[row * APITCH + kk]);
                    af[mt][1] = f2tf(Asl[(row + 8) * APITCH + kk]);
                    af[mt][2] = f2tf(Asl[row * APITCH + kk + 4]);
                    af[mt][3] = f2tf(Asl[(row + 8) * APITCH + kk + 4]);
                } else {
                    af[mt][0] = Aslu[row * APITCH + kk];
                    af[mt][1] = Aslu[(row + 8) * APITCH + kk];
                    af[mt][2] = Aslu[row * APITCH + kk + 4];
                    af[mt][3] = Aslu[(row + 8) * APITCH + kk + 4];
                }
            }
            #pragma unroll
            for (int nt = 0; nt < NT; nt++) {
                int n = wn0 + nt * 8 + (lane >> 2);
                if constexpr (BT) {
                    if constexpr (BCVT) {
                        bf[nt][0] = f2tf(Bsl[n * BPITCH + kk]);
                        bf[nt][1] = f2tf(Bsl[n * BPITCH + kk + 4]);
                    } else {
                        bf[nt][0] = Bslu[n * BPITCH + kk];
                        bf[nt][1] = Bslu[n * BPITCH + kk + 4];
                    }
                } else {
                    if constexpr (BCVT) {
                        bf[nt][0] = f2tf(Bsl[kk * BPITCH + n]);
                        bf[nt][1] = f2tf(Bsl[(kk + 4) * BPITCH + n]);
                    } else {
                        bf[nt][0] = Bslu[kk * BPITCH + n];
                        bf[nt][1] = Bslu[(kk + 4) * BPITCH + n];
                    }
                }
            }
            #pragma unroll
            for (int mt = 0; mt < MT; mt++)
                #pragma unroll
                for (int nt = 0; nt < NT; nt++)
                    mma_tf32(acc[mt][nt], af[mt], bf[nt]);
        }
    }
}

// smem byte sizes
#define PROJ_SMEM  ((4*128*20 + 4*16*136) * 4)   // 75776 (tf32 path)
#define NTG_SMEM   (4*128*40*2 * 2)              // 81920 (bf16 4-stage NT)
#define CTX_S_BYTES   (4 * 128 * 24 * 2)
#define CTX_E_BYTES   (4 * 128 * 24 * 2)
#define CTX_V_BYTES   (4 * 64 * 24 * 2)
#define CTXF_SMEM  (CTX_S_BYTES + CTX_E_BYTES + CTX_V_BYTES)  // 61440

// ---------------- unified prep: preround(2) + wtrans(4) + incvt(2) in one launch ----------------
// 1-D grid of 5632 blocks: [0,512) preround, [512,1536) wtrans, [1536,5632) incvt.
struct PrepArgs {
    const float* pr[2];    // wv_w, dense_w
    const float* wt[4];    // wq_w, wk_w, mp_wq_w, mp_wk_w
    const float* q;
    const float* k;
};

__global__ void __launch_bounds__(256) prep_kernel(PrepArgs a)
{
    __shared__ float tile[32][33];
    const int bid = blockIdx.x;
    const int tid = threadIdx.x;

    if (bid < 512) {
        // preround: z = bid>>8, idx covers 65536 float4 per matrix
        const int z = bid >> 8;
        const int idx = (bid & 255) * 256 + tid;
        float4 v = ((const float4*)a.pr[z])[idx];
        ((float4*)(g_W + z * Dsz * Dsz))[idx] =
            make_float4(tf32r(v.x), tf32r(v.y), tf32r(v.z), tf32r(v.w));
    } else if (bid < 1536) {
        // wtrans: 256 blocks per matrix, 32x32 tiles
        const int t = bid - 512;
        const int z = t >> 8;
        const int c0 = (t & 15) * 32, r0 = ((t >> 4) & 15) * 32;
        const float* W = a.wt[z];
        const int tx = tid & 31, ty = tid >> 5;
        #pragma unroll
        for (int i = 0; i < 4; i++)
            tile[ty + i * 8][tx] = W[(size_t)(r0 + ty + i * 8) * Dsz + c0 + tx];
        __syncthreads();
        __nv_bfloat16* Wt = g_Wtb + (size_t)z * Dsz * Dsz;
        #pragma unroll
        for (int i = 0; i < 4; i++)
            Wt[(size_t)(c0 + ty + i * 8) * Dsz + r0 + tx] =
                __float2bfloat16(tile[tx][ty + i * 8]);
    } else {
        // incvt: 2048 blocks per tensor
        const int t = bid - 1536;
        const int y = t >> 11;
        const float* src = y ? a.k : a.q;
        __nv_bfloat16* dst = y ? g_Kin : g_Qin;
        const int idx = (t & 2047) * 256 + tid;
        float4 v = ((const float4*)src)[idx];
        ((uint2*)dst)[idx] = make_uint2(packbf2(v.x, v.y), packbf2(v.z, v.w));
    }
}

// ---------------- combined projections: 4x bf16 NT + 1x tf32 NN (V) + gate (z=5) ----------------
struct ProjAll {
    const __nv_bfloat16* A[4];
    const __nv_bfloat16* Wt[4];
    const float* bias[4];
    __nv_bfloat16* C[4];
    const float* vA; const float* vW; const float* vbias; float* vC;
    const float* q; const float* gw; const float* gb;   // gate
};

__global__ void __launch_bounds__(256, 2) projall_kernel(ProjAll a)
{
    const int zz = blockIdx.z;
    const int tid = threadIdx.x;
    const int lane = tid & 31, wid = tid >> 5;
    const int fcol = lane & 3;
    extern __shared__ float dynsm[];

    if (zz < 4) {
        // bf16 NT pipelined: C = A @ Wt^T + bias, K=512, BK=32, 4-stage
        const __nv_bfloat16* Ab = a.A[zz] + ((size_t)blockIdx.y * 128) * Dsz;
        const __nv_bfloat16* Bb = a.Wt[zz] + ((size_t)blockIdx.x * 128) * Dsz;

        __nv_bfloat16* As = (__nv_bfloat16*)dynsm;     // 4 x 128 x 40
        __nv_bfloat16* Bs = As + 4 * 128 * 40;

        auto pre = [&](int it, int s) {
            const int k0 = it * 32;
            __nv_bfloat16* Al = As + s * 128 * 40;
            __nv_bfloat16* Bl = Bs + s * 128 * 40;
            #pragma unroll
            for (int i = 0; i < 2; i++) {
                int idx = tid + i * 256;
                int row = idx >> 2, ch = idx & 3;
                cp_async16(&Al[row * 40 + ch * 8], Ab + (size_t)row * Dsz + k0 + ch * 8);
                cp_async16(&Bl[row * 40 + ch * 8], Bb + (size_t)row * Dsz + k0 + ch * 8);
            }
            cp_commit();
        };

        const int wm0 = (wid & 3) * 32;
        const int wn0 = (wid >> 2) * 64;
        const int frow = lane >> 2;
        float acc[2][8][4] = {};

        const int nIter = Dsz / 32;   // 16
        pre(0, 0);
        pre(1, 1);

        for (int it = 0; it < nIter; it++) {
            if (it + 2 < nIter) { pre(it + 2, (it + 2) & 3); cp_wait<2>(); }
            else if (it + 1 < nIter) { cp_wait<1>(); }
            else { cp_wait<0>(); }
            __syncthreads();

            const int cur = it & 3;
            const unsigned* Aw = (const unsigned*)(As + cur * 128 * 40);
            const unsigned* Bw = (const unsigned*)(Bs + cur * 128 * 40);

            #pragma unroll
            for (int ks = 0; ks < 2; ks++) {
                const int kw = ks * 8 + fcol;
                unsigned af[2][4];
                #pragma unroll
                for (int mt = 0; mt < 2; mt++) {
                    int row = wm0 + mt * 16 + frow;
                    af[mt][0] = Aw[row * 20 + kw];
                    af[mt][1] = Aw[(row + 8) * 20 + kw];
                    af[mt][2] = Aw[row * 20 + kw + 4];
                    af[mt][3] = Aw[(row + 8) * 20 + kw + 4];
                }
                #pragma unroll
                for (int nt = 0; nt < 8; nt++) {
                    int n = wn0 + nt * 8 + frow;
                    unsigned bf[2] = { Bw[n * 20 + kw], Bw[n * 20 + kw + 4] };
                    #pragma unroll
                    for (int mt = 0; mt < 2; mt++)
                        mma_bf16(acc[mt][nt], af[mt], bf);
                }
            }
        }

        const float* bias = a.bias[zz];
        __nv_bfloat16* C = a.C[zz];
        int rowBase = blockIdx.y * 128 + wm0 + frow;
        int colBase = blockIdx.x * 128 + wn0 + 2 * fcol;
        #pragma unroll
        for (int mt = 0; mt < 2; mt++)
            #pragma unroll
            for (int nt = 0; nt < 8; nt++) {
                int row = rowBase + mt * 16;
                int col = colBase + nt * 8;
                float b0 = bias[col], b1 = bias[col + 1];
                *(__nv_bfloat162*)&C[(size_t)row * Dsz + col] =
                    __float22bfloat162_rn(make_float2(acc[mt][nt][0] + b0, acc[mt][nt][1] + b1));
                *(__nv_bfloat162*)&C[(size_t)(row + 8) * Dsz + col] =
                    __float22bfloat162_rn(make_float2(acc[mt][nt][2] + b0, acc[mt][nt][3] + b1));
            }
    } else if (zz == 4) {
        // V projection: tf32 NN, output tf32-rounded fp32
        float acc[2][8][4] = {};
        const float* Ab = a.vA + (size_t)blockIdx.y * 128 * Dsz;
        const float* Bb = a.vW + blockIdx.x * 128;
        gemm_core<128, 128, false, 2, 8, true, false>(Ab, Dsz, Bb, Dsz, Dsz, acc);

        const float* bias = a.vbias;
        float* C = a.vC;
        int rowBase = blockIdx.y * 128 + (wid & 3) * 32 + (lane >> 2);
        int colBase = blockIdx.x * 128 + (wid >> 2) * 64 + 2 * fcol;
        #pragma unroll
        for (int mt = 0; mt < 2; mt++)
            #pragma unroll
            for (int nt = 0; nt < 8; nt++) {
                int row = rowBase + mt * 16;
                int col = colBase + nt * 8;
                float b0 = bias[col], b1 = bias[col + 1];
                *(float2*)&C[(size_t)row * Dsz + col] =
                    make_float2(tf32r(acc[mt][nt][0] + b0), tf32r(acc[mt][nt][1] + b1));
                *(float2*)&C[(size_t)(row + 8) * Dsz + col] =
                    make_float2(tf32r(acc[mt][nt][2] + b0), tf32r(acc[mt][nt][3] + b1));
            }
    } else {
        // gate + zero g_Z/g_CS (consumed by ms/ctx which launch later)
        const int bid = blockIdx.y * 4 + blockIdx.x;   // 0..127
        const int gidx = bid * 256 + tid;              // 0..32767 == extent of g_Z
        g_Z[gidx] = 0.f;
        if (gidx < Bsz * Hsz * DKsz) g_CS[gidx] = 0.f;

        const float4* gw4 = (const float4*)a.gw;
        #pragma unroll
        for (int p = 0; p < 4; p++) {
            const int row = bid * 32 + p * 8 + wid;
            const float4* r4 = (const float4*)(a.q + (size_t)row * Dsz);
            float s = 0.f;
            #pragma unroll
            for (int i = 0; i < 4; i++) {
                float4 v = r4[lane + i * 32];
                float4 w = gw4[lane + i * 32];
                s += v.x * w.x + v.y * w.y + v.z * w.z + v.w * w.w;
            }
            #pragma unroll
            for (int o = 16; o; o >>= 1) s += __shfl_xor_sync(0xffffffffu, s, o);
            if (lane == 0)
                g_G[row] = 1.0f / (1.0f + __expf(-(s + a.gb[0])));
        }
    }
}

// ---------------- dense: tf32 NN, plain fp32 out ----------------
__global__ void __launch_bounds__(256, 2) dense_gemm_kernel(
    const float* __restrict__ A, const float* __restrict__ W,
    const float* __restrict__ bias, float* __restrict__ C)
{
    float acc[2][8][4] = {};
    const float* Ab = A + (size_t)blockIdx.y * 128 * Dsz;
    const float* Bb = W + blockIdx.x * 128;
    gemm_core<128, 128, false, 2, 8, false, false>(Ab, Dsz, Bb, Dsz, Dsz, acc);

    int lane = threadIdx.x & 31, wid = threadIdx.x >> 5;
    int rowBase = blockIdx.y * 128 + (wid & 3) * 32 + (lane >> 2);
    int colBase = blockIdx.x * 128 + (wid >> 2) * 64 + 2 * (lane & 3);
    #pragma unroll
    for (int mt = 0; mt < 2; mt++)
        #pragma unroll
        for (int nt = 0; nt < 8; nt++) {
            int row = rowBase + mt * 16;
            int col = colBase + nt * 8;
            float b0 = bias[col], b1 = bias[col + 1];
            *(float2*)&C[(size_t)row * Dsz + col] =
                make_float2(acc[mt][nt][0] + b0, acc[mt][nt][1] + b1);
            *(float2*)&C[(size_t)(row + 8) * Dsz + col] =
                make_float2(acc[mt][nt][2] + b0, acc[mt][nt][3] + b1);
        }
}

// ---------------- merged m + score + vprep launch ----------------
__global__ void __launch_bounds__(256, 2) ms_gemm_kernel(float* __restrict__ m_out)
{
    const int zz = blockIdx.z;
    const int tid = threadIdx.x;
    int lane = tid & 31, wid = tid >> 5;
    int fcol = lane & 3;
    extern __shared__ float dynsm[];

    if (zz < Bsz) {
        const float SCALE = 0.04419417382415922f; // 1/sqrt(512)
        const int zb = zz;
        const __nv_bfloat16* Ab = g_QPb + ((size_t)zb * Lsz + blockIdx.y * 128) * Dsz;
        const __nv_bfloat16* Bb = g_KPb + ((size_t)zb * Lsz + blockIdx.x * 128) * Dsz;

        __nv_bfloat16* As = (__nv_bfloat16*)dynsm;
        __nv_bfloat16* Bs = As + 4 * 128 * 40;

        auto pre = [&](int it, int s) {
            const int k0 = it * 32;
            __nv_bfloat16* Al = As + s * 128 * 40;
            __nv_bfloat16* Bl = Bs + s * 128 * 40;
            #pragma unroll
            for (int i = 0; i < 2; i++) {
                int idx = tid + i * 256;
                int row = idx >> 2, ch = idx & 3;
                cp_async16(&Al[row * 40 + ch * 8], Ab + (size_t)row * Dsz + k0 + ch * 8);
                cp_async16(&Bl[row * 40 + ch * 8], Bb + (size_t)row * Dsz + k0 + ch * 8);
            }
            cp_commit();
        };

        const int wm0 = (wid & 3) * 32;
        const int wn0 = (wid >> 2) * 64;
        const int frow = lane >> 2;
        float acc[2][8][4] = {};

        const int nIter = Dsz / 32;
        pre(0, 0);
        pre(1, 1);

        for (int it = 0; it < nIter; it++) {
            if (it + 2 < nIter) { pre(it + 2, (it + 2) & 3); cp_wait<2>(); }
            else if (it + 1 < nIter) { cp_wait<1>(); }
            else { cp_wait<0>(); }
            __syncthreads();

            const int cur = it & 3;
            const unsigned* Aw = (const unsigned*)(As + cur * 128 * 40);
            const unsigned* Bw = (const unsigned*)(Bs + cur * 128 * 40);

            #pragma unroll
            for (int ks = 0; ks < 2; ks++) {
                const int kw = ks * 8 + fcol;
                unsigned af[2][4];
                #pragma unroll
                for (int mt = 0; mt < 2; mt++) {
                    int row = wm0 + mt * 16 + frow;
                    af[mt][0] = Aw[row * 20 + kw];
                    af[mt][1] = Aw[(row + 8) * 20 + kw];
                    af[mt][2] = Aw[row * 20 + kw + 4];
                    af[mt][3] = Aw[(row + 8) * 20 + kw + 4];
                }
                #pragma unroll
                for (int nt = 0; nt < 8; nt++) {
                    int n = wn0 + nt * 8 + frow;
                    unsigned bf[2] = { Bw[n * 20 + kw], Bw[n * 20 + kw + 4] };
                    #pragma unroll
                    for (int mt = 0; mt < 2; mt++)
                        mma_bf16(acc[mt][nt], af[mt], bf);
                }
            }
        }

        float* Mo = m_out + (size_t)zb * Lsz * Lsz;
        __nv_bfloat16* Eo = g_EMb + (size_t)zb * Lsz * Lsz;
        int rowBase = blockIdx.y * 128 + wm0 + frow;
        int colBase = blockIdx.x * 128 + wn0 + 2 * fcol;
        #pragma unroll
        for (int mt = 0; mt < 2; mt++)
            #pragma unroll
            for (int nt = 0; nt < 8; nt++) {
                int row = rowBase + mt * 16;
                int col = colBase + nt * 8;
                #pragma unroll
                for (int h = 0; h < 2; h++) {
                    int r = row + h * 8;
                    float s0 = 1.0f / (1.0f + __expf(-acc[mt][nt][2*h] * SCALE));
                    float s1 = 1.0f / (1.0f + __expf(-acc[mt][nt][2*h+1] * SCALE));
                    *(float2*)&Mo[(size_t)r * Lsz + col] = make_float2(s0, s1);
                    *(__nv_bfloat162*)&Eo[(size_t)r * Lsz + col] =
                        __float22bfloat162_rn(make_float2(__expf(1.0f - s0), __expf(1.0f - s1)));
                }
            }
    } else if (zz < Bsz + Bsz * Hsz) {
        const float SCALE = 0.125f;
        const int z = zz - Bsz;
        const int b = z >> 3, h = z & 7;
        const __nv_bfloat16* Ab = g_Qbf + ((size_t)b * Lsz + blockIdx.y * 128) * Dsz + h * DKsz;
        const __nv_bfloat16* Bb = g_Kbf + ((size_t)b * Lsz + blockIdx.x * 128) * Dsz + h * DKsz;

        __nv_bfloat16* Qs = (__nv_bfloat16*)dynsm;
        __nv_bfloat16* Ks = Qs + 128 * 88;
        const unsigned* Qw = (const unsigned*)Qs;
        const unsigned* Kw = (const unsigned*)Ks;

        #pragma unroll
        for (int i = 0; i < 4; i++) {
            int idx = tid + i * 256;
            int row = idx >> 3, ch = idx & 7;
            cp_async16(&Qs[row * 88 + ch * 8], Ab + (size_t)row * Dsz + ch * 8);
        }
        #pragma unroll
        for (int i = 0; i < 4; i++) {
            int idx = tid + i * 256;
            int row = idx >> 3, ch = idx & 7;
            cp_async16(&Ks[row * 88 + ch * 8], Bb + (size_t)row * Dsz + ch * 8);
        }
        cp_commit();
        cp_wait<0>();
        __syncthreads();

        const int wm0 = (wid & 3) * 32;
        const int wn0 = (wid >> 2) * 64;
        const int frow = lane >> 2;
        float acc[2][8][4] = {};

        #pragma unroll
        for (int ks = 0; ks < 4; ks++) {
            const int kw = ks * 8 + fcol;
            unsigned af[2][4];
            #pragma unroll
            for (int mt = 0; mt < 2; mt++) {
                int row = wm0 + mt * 16 + frow;
                af[mt][0] = Qw[row * 44 + kw];
                af[mt][1] = Qw[(row + 8) * 44 + kw];
                af[mt][2] = Qw[row * 44 + kw + 4];
                af[mt][3] = Qw[(row + 8) * 44 + kw + 4];
            }
            #pragma unroll
            for (int nt = 0; nt < 8; nt++) {
                int n = wn0 + nt * 8 + frow;
                unsigned bf[2] = { Kw[n * 44 + kw], Kw[n * 44 + kw + 4] };
                #pragma unroll
                for (int mt = 0; mt < 2; mt++)
                    mma_bf16(acc[mt][nt], af[mt], bf);
            }
        }

        __nv_bfloat16* Cp = g_Sb + (size_t)z * Lsz * Lsz;
        int rowBase = blockIdx.y * 128 + wm0 + frow;
        int colBase = blockIdx.x * 128 + wn0 + 2 * fcol;

        float rs[2][2] = {};
        #pragma unroll
        for (int mt = 0; mt < 2; mt++)
            #pragma unroll
            for (int nt = 0; nt < 8; nt++) {
                int row = rowBase + mt * 16;
                int col = colBase + nt * 8;
                float p0 = __expf(acc[mt][nt][0] * SCALE);
                float p1 = __expf(acc[mt][nt][1] * SCALE);
                float p2 = __expf(acc[mt][nt][2] * SCALE);
                float p3 = __expf(acc[mt][nt][3] * SCALE);
                *(__nv_bfloat162*)&Cp[(size_t)row * Lsz + col] =
                    __float22bfloat162_rn(make_float2(p0, p1));
                *(__nv_bfloat162*)&Cp[(size_t)(row + 8) * Lsz + col] =
                    __float22bfloat162_rn(make_float2(p2, p3));
                rs[mt][0] += p0 + p1;
                rs[mt][1] += p2 + p3;
            }

        #pragma unroll
        for (int mt = 0; mt < 2; mt++)
            #pragma unroll
            for (int hh = 0; hh < 2; hh++) {
                float v = rs[mt][hh];
                v += __shfl_xor_sync(0xffffffffu, v, 1);
                v += __shfl_xor_sync(0xffffffffu, v, 2);
                if (fcol == 0)
                    atomicAdd(&g_Z[(size_t)z * Lsz + rowBase + mt * 16 + hh * 8], v);
            }
    } else {
        __nv_bfloat16 (*sm)[72] = (__nv_bfloat16(*)[72])dynsm;
        const int b = zz - (Bsz + Bsz * Hsz);
        const int h = blockIdx.y, kt = blockIdx.x;
        const int k0 = kt * 128;

        const int d = tid & 63, rg = tid >> 6;
        float psum = 0.f;
        #pragma unroll
        for (int j = 0; j < 32; j++) {
            int row = rg + 4 * j;
            float v = g_V[((size_t)(b * Lsz + k0 + row)) * Dsz + h * DKsz + d];
            psum += v;
            sm[row][d] = __float2bfloat16(v);
        }
        atomicAdd(&g_CS[(b * Hsz + h) * DKsz + d], psum);
        __syncthreads();

        const int d2 = tid >> 2, c = tid & 3;
        __nv_bfloat16* dst = g_Vtb + ((size_t)((b * Hsz + h) * DKsz + d2)) * Lsz + k0 + c * 32;
        #pragma unroll
        for (int q = 0; q < 4; q++) {
            __nv_bfloat16 tmp[8];
            #pragma unroll
            for (int e = 0; e < 8; e++) tmp[e] = sm[c * 32 + q * 8 + e][d2];
            *(uint4*)(dst + q * 8) = *(uint4*)tmp;
        }
    }
}

// ---------------- fused calibrate + ctx GEMM (Σ-decomposition) ----------------
__global__ void __launch_bounds__(256, 2) ctx_fused_kernel()
{
    extern __shared__ char smc[];
    __nv_bfloat16* Ss = (__nv_bfloat16*)smc;
    __nv_bfloat16* Es = (__nv_bfloat16*)(smc + CTX_S_BYTES);
    __nv_bfloat16* Vs = (__nv_bfloat16*)(smc + CTX_S_BYTES + CTX_E_BYTES);

    const int tid = threadIdx.x;
    const int lane = tid & 31;
    const int wid = tid >> 5;
    const int z = blockIdx.z;
    const int b = z >> 3, h = z & 7;
    const int q0 = blockIdx.y * 128;

    const __nv_bfloat16* Sg = g_Sb + (size_t)z * Lsz * Lsz + (size_t)q0 * Lsz;
    const __nv_bfloat16* Eg = g_EMb + (size_t)b * Lsz * Lsz + (size_t)q0 * Lsz;
    const __nv_bfloat16* Vtg = g_Vtb + (size_t)z * DKsz * Lsz;

    const int wm = wid * 16;
    const int frow = lane >> 2, fcol = lane & 3;
    const int r0 = wm + frow, r1 = r0 + 8;

    const float g0 = g_G[b * Lsz + q0 + r0];
    const float g1 = g_G[b * Lsz + q0 + r1];
    const float iz0 = 1.0f / g_Z[(size_t)z * Lsz + q0 + r0];
    const float iz1 = 1.0f / g_Z[(size_t)z * Lsz + q0 + r1];
    const float ga0 = g0 * iz0, gc0 = (1.0f - g0) * iz0;
    const float ga1 = g1 * iz1, gc1 = (1.0f - g1) * iz1;
    float z2a = 0.f, z2b = 0.f;

    auto prefetch = [&](int it, int s) {
        const int k0 = it * 16;
        __nv_bfloat16* Sl = Ss + s * 128 * 24;
        __nv_bfloat16* El = Es + s * 128 * 24;
        __nv_bfloat16* Vl = Vs + s * 64 * 24;
        {
            int row = tid >> 1, ch = tid & 1;
            cp_async16(&Sl[row * 24 + ch * 8], Sg + (size_t)row * Lsz + k0 + ch * 8);
            cp_async16(&El[row * 24 + ch * 8], Eg + (size_t)row * Lsz + k0 + ch * 8);
        }
        if (tid < 128) {
            int d = tid >> 1, half = tid & 1;
            cp_async16(&Vl[d * 24 + half * 8], Vtg + (size_t)d * Lsz + k0 + half * 8);
        }
        cp_commit();
    };

    float acc[8][4] = {};
    const int nIter = Lsz / 16;
    prefetch(0, 0);
    prefetch(1, 1);

    for (int it = 0; it < nIter; it++) {
        if (it + 2 < nIter) { prefetch(it + 2, (it + 2) & 3); cp_wait<2>(); }
        else if (it + 1 < nIter) { cp_wait<1>(); }
        else { cp_wait<0>(); }
        __syncthreads();

        const int cur = it & 3;
        const unsigned* Sw = (const unsigned*)(Ss + cur * 128 * 24);
        const unsigned* Ew = (const unsigned*)(Es + cur * 128 * 24);
        const unsigned* Vw = (const unsigned*)(Vs + cur * 64 * 24);

        float2 p00 = unpackbf2(Sw[r0 * 12 + fcol]);
        float2 p01 = unpackbf2(Sw[r0 * 12 + fcol + 4]);
        float2 p10 = unpackbf2(Sw[r1 * 12 + fcol]);
        float2 p11 = unpackbf2(Sw[r1 * 12 + fcol + 4]);
        float2 e00 = unpackbf2(Ew[r0 * 12 + fcol]);
        float2 e01 = unpackbf2(Ew[r0 * 12 + fcol + 4]);
        float2 e10 = unpackbf2(Ew[r1 * 12 + fcol]);
        float2 e11 = unpackbf2(Ew[r1 * 12 + fcol + 4]);

        float x0 = p00.x * fmaf(gc0, e00.x, ga0);
        float x1 = p00.y * fmaf(gc0, e00.y, ga0);
        float x2 = p01.x * fmaf(gc0, e01.x, ga0);
        float x3 = p01.y * fmaf(gc0, e01.y, ga0);
        float x4 = p10.x * fmaf(gc1, e10.x, ga1);
        float x5 = p10.y * fmaf(gc1, e10.y, ga1);
        float x6 = p11.x * fmaf(gc1, e11.x, ga1);
        float x7 = p11.y * fmaf(gc1, e11.y, ga1);

        float y0 = x0 * fmaf(x0, 0.5f, 1.0f);
        float y1 = x1 * fmaf(x1, 0.5f, 1.0f);
        float y2 = x2 * fmaf(x2, 0.5f, 1.0f);
        float y3 = x3 * fmaf(x3, 0.5f, 1.0f);
        float y4 = x4 * fmaf(x4, 0.5f, 1.0f);
        float y5 = x5 * fmaf(x5, 0.5f, 1.0f);
        float y6 = x6 * fmaf(x6, 0.5f, 1.0f);
        float y7 = x7 * fmaf(x7, 0.5f, 1.0f);

        z2a += (y0 + y1) + (y2 + y3);
        z2b += (y4 + y5) + (y6 + y7);

        unsigned af[4];
        af[0] = packbf2(y0, y1);
        af[1] = packbf2(y4, y5);
        af[2] = packbf2(y2, y3);
        af[3] = packbf2(y6, y7);

        #pragma unroll
        for (int nt = 0; nt < 8; nt++) {
            const int n = nt * 8 + frow;
            unsigned bf[2] = { Vw[n * 12 + fcol], Vw[n * 12 + fcol + 4] };
            mma_bf16(acc[nt], af, bf);
        }
    }

    z2a += __shfl_xor_sync(0xffffffffu, z2a, 1);
    z2a += __shfl_xor_sync(0xffffffffu, z2a, 2);
    z2b += __shfl_xor_sync(0xffffffffu, z2b, 1);
    z2b += __shfl_xor_sync(0xffffffffu, z2b, 2);
    const float iza = 1.0f / (1024.0f + z2a);
    const float izb = 1.0f / (1024.0f + z2b);

    float* Cp = g_CTX + (size_t)b * Lsz * Dsz + (size_t)q0 * Dsz + h * DKsz;
    const float* CSp = g_CS + z * DKsz;
    #pragma unroll
    for (int nt = 0; nt < 8; nt++) {
        const int col = nt * 8 + 2 * fcol;
        float cs0 = CSp[col], cs1 = CSp[col + 1];
        *(float2*)&Cp[(size_t)r0 * Dsz + col] =
            make_float2(tf32r((cs0 + acc[nt][0]) * iza), tf32r((cs1 + acc[nt][1]) * iza));
        *(float2*)&Cp[(size_t)r1 * Dsz + col] =
            make_float2(tf32r((cs0 + acc[nt][2]) * izb), tf32r((cs1 + acc[nt][3]) * izb));
    }
}

// ---------------- launch ----------------
extern "C" void kernel_launch(void* const* d_in, const int* in_sizes, int n_in,
                              void* d_out, int out_size)
{
    const float* query   = (const float*)d_in[0];
    const float* key     = (const float*)d_in[1];
    const float* value   = (const float*)d_in[2];
    const float* wq_w    = (const float*)d_in[3];
    const float* wq_b    = (const float*)d_in[4];
    const float* wk_w    = (const float*)d_in[5];
    const float* wk_b    = (const float*)d_in[6];
    const float* wv_w    = (const float*)d_in[7];
    const float* wv_b    = (const float*)d_in[8];
    const float* dense_w = (const float*)d_in[9];
    const float* dense_b = (const float*)d_in[10];
    const float* gate_w  = (const float*)d_in[11];
    const float* gate_b  = (const float*)d_in[12];
    const float* mp_wq_w = (const float*)d_in[13];
    const float* mp_wq_b = (const float*)d_in[14];
    const float* mp_wk_w = (const float*)d_in[15];
    const float* mp_wk_b = (const float*)d_in[16];

    float* out   = (float*)d_out;
    float* m_out = out + (size_t)Bsz * Lsz * Dsz;

    void *pQin, *pKin, *pWtb, *pQbf, *pKbf, *pQPb, *pKPb;
    float *pV, *pCTX, *pW;
    cudaGetSymbolAddress(&pQin, g_Qin);
    cudaGetSymbolAddress(&pKin, g_Kin);
    cudaGetSymbolAddress(&pWtb, g_Wtb);
    cudaGetSymbolAddress(&pQbf, g_Qbf);
    cudaGetSymbolAddress(&pKbf, g_Kbf);
    cudaGetSymbolAddress(&pQPb, g_QPb);
    cudaGetSymbolAddress(&pKPb, g_KPb);
    cudaGetSymbolAddress((void**)&pV,   g_V);
    cudaGetSymbolAddress((void**)&pCTX, g_CTX);
    cudaGetSymbolAddress((void**)&pW,   g_W);

    static int attr_set = 0;
    if (!attr_set) {
        cudaFuncSetAttribute(projall_kernel,
                             cudaFuncAttributeMaxDynamicSharedMemorySize, NTG_SMEM);
        cudaFuncSetAttribute(dense_gemm_kernel,
                             cudaFuncAttributeMaxDynamicSharedMemorySize, PROJ_SMEM);
        cudaFuncSetAttribute(ms_gemm_kernel,
                             cudaFuncAttributeMaxDynamicSharedMemorySize, NTG_SMEM);
        cudaFuncSetAttribute(ctx_fused_kernel,
                             cudaFuncAttributeMaxDynamicSharedMemorySize, CTXF_SMEM);
        attr_set = 1;
    }

    dim3 t256(256);

    // unified prologue: preround + wtrans + incvt (one launch, 5632 blocks)
    PrepArgs prep;
    prep.pr[0] = wv_w; prep.pr[1] = dense_w;
    prep.wt[0] = wq_w; prep.wt[1] = wk_w; prep.wt[2] = mp_wq_w; prep.wt[3] = mp_wk_w;
    prep.q = query; prep.k = key;
    prep_kernel<<<5632, t256>>>(prep);

    // projections (4x bf16 + V tf32) + gate/zeroing as z=5
    ProjAll pa;
    pa.A[0] = (const __nv_bfloat16*)pQin; pa.Wt[0] = (const __nv_bfloat16*)pWtb + 0*Dsz*Dsz;
    pa.bias[0] = wq_b;    pa.C[0] = (__nv_bfloat16*)pQbf;
    pa.A[1] = (const __nv_bfloat16*)pKin; pa.Wt[1] = (const __nv_bfloat16*)pWtb + 1*Dsz*Dsz;
    pa.bias[1] = wk_b;    pa.C[1] = (__nv_bfloat16*)pKbf;
    pa.A[2] = (const __nv_bfloat16*)pQin; pa.Wt[2] = (const __nv_bfloat16*)pWtb + 2*Dsz*Dsz;
    pa.bias[2] = mp_wq_b; pa.C[2] = (__nv_bfloat16*)pQPb;
    pa.A[3] = (const __nv_bfloat16*)pKin; pa.Wt[3] = (const __nv_bfloat16*)pWtb + 3*Dsz*Dsz;
    pa.bias[3] = mp_wk_b; pa.C[3] = (__nv_bfloat16*)pKPb;
    pa.vA = value; pa.vW = pW + 0*Dsz*Dsz; pa.vbias = wv_b; pa.vC = pV;
    pa.q = query; pa.gw = gate_w; pa.gb = gate_b;
    projall_kernel<<<dim3(4, 32, 6), t256, NTG_SMEM>>>(pa);

    ms_gemm_kernel<<<dim3(8, 8, Bsz + Bsz * Hsz + Bsz), t256, NTG_SMEM>>>(m_out);

    ctx_fused_kernel<<<dim3(1, 8, Bsz * Hsz), t256, CTXF_SMEM>>>();

    dense_gemm_kernel<<<dim3(4, 32), t256, PROJ_SMEM>>>(pCTX, pW + 1*Dsz*Dsz, dense_b, out);
}